// round 3
// baseline (speedup 1.0000x reference)
#include <cuda_runtime.h>
#include <math.h>

// Problem constants (fixed shapes)
#define NN   30000
#define EE   240000
#define E2   (EE + NN)      // 270000 edges incl self-loops
#define BB   64
#define FF   64
#define HH   4
#define CC   256            // H*F
#define GCOLS 832           // F*(1+H*T) = 64*13
#define BOTN 256

#define NEG_INF __int_as_float(0xff800000)

// ---------------- device scratch (no allocations allowed) ----------------
__device__ float g_x0[NN * FF];          // layer-0 input features
__device__ float g_xcur[NN * CC];        // current layer input (layers 1,2)
__device__ float g_xs[NN * CC];          // transformed features xs = x @ W
__device__ float g_out[NN * CC];         // message accumulation (bias-initialized)
__device__ float g_asrc[NN * HH];
__device__ float g_adst[NN * HH];
__device__ float g_segmax[NN * HH];
__device__ float g_segsum[NN * HH];
__device__ float g_ex[E2 * HH];          // logits, then exp values
__device__ float g_g[BB * GCOLS];        // pooled embedding

// ---------------- helpers ----------------
__device__ __forceinline__ void atomicMaxFloat(float* addr, float v) {
    // mixed-sign float max via int/uint monotonic mapping
    if (v >= 0.0f) atomicMax((int*)addr, __float_as_int(v));
    else           atomicMin((unsigned int*)addr, __float_as_uint(v));
}

__device__ __forceinline__ void edge_endpoints(const int* __restrict__ ei,
                                               int e, int& src, int& dst) {
    if (e < EE) { src = ei[e]; dst = ei[EE + e]; }
    else        { src = dst = e - EE; }
}

// ---------------- kernels ----------------

__global__ void k_zero_g() {
    int i = blockIdx.x * blockDim.x + threadIdx.x;
    if (i < BB * GCOLS) g_g[i] = 0.0f;
}

// x0 = relu(sf @ bbox_w + bbox_b); fused g0 = segment_max(x0, batch)
// block: 64 threads (one per output col), covers 32 consecutive nodes
__global__ void k_input(const float* __restrict__ sf,
                        const float* __restrict__ bw,
                        const float* __restrict__ bb,
                        const int* __restrict__ batch) {
    int c = threadIdx.x;                 // 0..63
    int base = blockIdx.x * 32;
    if (base >= NN) return;
    float w0 = bw[0 * FF + c], w1 = bw[1 * FF + c], w2 = bw[2 * FF + c],
          w3 = bw[3 * FF + c], w4 = bw[4 * FF + c];
    float bias = bb[c];
    int curb = batch[base];
    float mx = 0.0f;
    int lim = min(32, NN - base);
    for (int i = 0; i < lim; i++) {
        int n = base + i;
        int b = batch[n];
        if (b != curb) {
            atomicMax((int*)&g_g[curb * GCOLS + c], __float_as_int(mx));
            curb = b; mx = 0.0f;
        }
        const float* s = &sf[n * 5];
        float v = bias + s[0]*w0 + s[1]*w1 + s[2]*w2 + s[3]*w3 + s[4]*w4;
        v = fmaxf(v, 0.0f);
        g_x0[n * FF + c] = v;
        mx = fmaxf(mx, v);
    }
    atomicMax((int*)&g_g[curb * GCOLS + c], __float_as_int(mx));
}

// xs = A @ W;  A = g_x0 (layer 0, K=64) or g_xcur (K=256); W: [K, 256]
// tile 64x64, BK=16, 256 threads, 4x4 per thread
__global__ void k_gemm(int layer, int K, const float* __restrict__ W) {
    const float* A = (layer == 0) ? g_x0 : g_xcur;
    __shared__ float As[16][64];
    __shared__ float Bs[16][64];
    int bm = blockIdx.y * 64;
    int bn = blockIdx.x * 64;
    int tid = threadIdx.x;
    int ty = tid >> 4, tx = tid & 15;
    float acc[4][4];
#pragma unroll
    for (int i = 0; i < 4; i++)
#pragma unroll
        for (int j = 0; j < 4; j++) acc[i][j] = 0.0f;

    for (int k0 = 0; k0 < K; k0 += 16) {
        {   // A tile: 64 rows x 16 k, float4 per thread
            int row = tid >> 2;
            int kk = (tid & 3) * 4;
            float4 v = make_float4(0.f, 0.f, 0.f, 0.f);
            int gr = bm + row;
            if (gr < NN) v = *(const float4*)&A[(size_t)gr * K + k0 + kk];
            As[kk + 0][row] = v.x; As[kk + 1][row] = v.y;
            As[kk + 2][row] = v.z; As[kk + 3][row] = v.w;
        }
        {   // B tile: 16 k x 64 cols
            int kk = tid >> 4;
            int cc2 = (tid & 15) * 4;
            float4 v = *(const float4*)&W[(size_t)(k0 + kk) * CC + bn + cc2];
            *(float4*)&Bs[kk][cc2] = v;
        }
        __syncthreads();
#pragma unroll
        for (int k = 0; k < 16; k++) {
            float a[4], b[4];
            *(float4*)a = *(float4*)&As[k][ty * 4];
            *(float4*)b = *(float4*)&Bs[k][tx * 4];
#pragma unroll
            for (int i = 0; i < 4; i++)
#pragma unroll
                for (int j = 0; j < 4; j++) acc[i][j] += a[i] * b[j];
        }
        __syncthreads();
    }
#pragma unroll
    for (int i = 0; i < 4; i++) {
        int gr = bm + ty * 4 + i;
        if (gr < NN) {
            float4 v = make_float4(acc[i][0], acc[i][1], acc[i][2], acc[i][3]);
            *(float4*)&g_xs[(size_t)gr * CC + bn + tx * 4] = v;
        }
    }
}

// per node: a_src[n,h], a_dst[n,h]; also init segmax=-inf, segsum=0
// one warp per node; 8 nodes per 256-thread block.
__global__ void k_att(const float* __restrict__ att_src,
                      const float* __restrict__ att_dst) {
    __shared__ float s_src[CC], s_dst[CC];
    int tid = threadIdx.x;
    s_src[tid] = att_src[tid];
    s_dst[tid] = att_dst[tid];
    __syncthreads();
    int warp = tid >> 5, lane = tid & 31;
    int n = blockIdx.x * 8 + warp;
    if (n >= NN) return;
    const float* row = &g_xs[(size_t)n * CC];
#pragma unroll
    for (int h = 0; h < HH; h++) {
        float x0 = row[h * 64 + lane];
        float x1 = row[h * 64 + 32 + lane];
        float s = x0 * s_src[h * 64 + lane] + x1 * s_src[h * 64 + 32 + lane];
        float d = x0 * s_dst[h * 64 + lane] + x1 * s_dst[h * 64 + 32 + lane];
#pragma unroll
        for (int o = 16; o > 0; o >>= 1) {
            s += __shfl_down_sync(0xffffffff, s, o);
            d += __shfl_down_sync(0xffffffff, d, o);
        }
        if (lane == 0) {
            g_asrc[n * HH + h] = s;
            g_adst[n * HH + h] = d;
        }
    }
    if (lane < HH) {
        g_segmax[n * HH + lane] = NEG_INF;
        g_segsum[n * HH + lane] = 0.0f;
    }
}

// logits + segment max over dst
__global__ void k_logits(const int* __restrict__ ei) {
    int idx = blockIdx.x * blockDim.x + threadIdx.x;
    if (idx >= E2 * HH) return;
    int e = idx >> 2, h = idx & 3;
    int src, dst;
    edge_endpoints(ei, e, src, dst);
    float v = g_asrc[src * HH + h] + g_adst[dst * HH + h];
    v = (v >= 0.0f) ? v : 0.2f * v;       // leaky_relu(0.2)
    g_ex[idx] = v;
    atomicMaxFloat(&g_segmax[dst * HH + h], v);
}

// exp(logit - max) + segment sum
__global__ void k_exp(const int* __restrict__ ei) {
    int idx = blockIdx.x * blockDim.x + threadIdx.x;
    if (idx >= E2 * HH) return;
    int e = idx >> 2, h = idx & 3;
    int src, dst;
    edge_endpoints(ei, e, src, dst);
    (void)src;
    float t = expf(g_ex[idx] - g_segmax[dst * HH + h]);
    g_ex[idx] = t;
    atomicAdd(&g_segsum[dst * HH + h], t);
}

// out[n,c] = bias[c]
__global__ void k_fillbias(const float* __restrict__ bias) {
    int idx = blockIdx.x * blockDim.x + threadIdx.x;
    if (idx < NN * CC) g_out[idx] = bias[idx & (CC - 1)];
}

// message accumulation: out[dst] += alpha * xs[src]
// 64 threads per edge, 4 consecutive channels each (float4 gather, 4 atomics)
__global__ void k_msg(const int* __restrict__ ei) {
    long long gtid = (long long)blockIdx.x * blockDim.x + threadIdx.x;
    if (gtid >= (long long)E2 * 64) return;
    int e = (int)(gtid >> 6);
    int lane = (int)(gtid & 63);
    int c = lane * 4;
    int h = c >> 6;
    int src, dst;
    edge_endpoints(ei, e, src, dst);
    float alpha = g_ex[e * HH + h] / (g_segsum[dst * HH + h] + 1e-16f);
    float4 v = *(const float4*)&g_xs[(size_t)src * CC + c];
    float* o = &g_out[(size_t)dst * CC + c];
    atomicAdd(o + 0, alpha * v.x);
    atomicAdd(o + 1, alpha * v.y);
    atomicAdd(o + 2, alpha * v.z);
    atomicAdd(o + 3, alpha * v.w);
}

// relu(out) -> xcur ; fused segment_max into g at column offset goff
// block: 256 threads (one per col), covers 32 consecutive (batch-sorted) nodes
__global__ void k_post(const int* __restrict__ batch, int goff) {
    int c = threadIdx.x;
    int base = blockIdx.x * 32;
    if (base >= NN) return;
    int curb = batch[base];
    float mx = 0.0f;
    int lim = min(32, NN - base);
    for (int i = 0; i < lim; i++) {
        int n = base + i;
        int b = batch[n];
        if (b != curb) {
            atomicMax((int*)&g_g[curb * GCOLS + goff + c], __float_as_int(mx));
            curb = b; mx = 0.0f;
        }
        float v = fmaxf(g_out[(size_t)n * CC + c], 0.0f);
        g_xcur[(size_t)n * CC + c] = v;
        mx = fmaxf(mx, v);
    }
    atomicMax((int*)&g_g[curb * GCOLS + goff + c], __float_as_int(mx));
}

// final: out[b, j] = g[b,:] @ agg_w[:, j] + agg_b[j]
__global__ void k_final(const float* __restrict__ agg_w,
                        const float* __restrict__ agg_b,
                        float* __restrict__ out) {
    __shared__ float sg[GCOLS];
    int b = blockIdx.x;
    int tid = threadIdx.x;
    for (int k = tid; k < GCOLS; k += 256) sg[k] = g_g[b * GCOLS + k];
    __syncthreads();
    float acc = agg_b[tid];
    for (int k = 0; k < GCOLS; k++) acc += sg[k] * agg_w[(size_t)k * BOTN + tid];
    out[b * BOTN + tid] = acc;
}

// ---------------- host ----------------
extern "C" void kernel_launch(void* const* d_in, const int* in_sizes, int n_in,
                              void* d_out, int out_size) {
    const float* sf    = (const float*)d_in[0];
    const int*   ei    = (const int*)d_in[1];    // int32 (JAX x64 disabled)
    const int*   batch = (const int*)d_in[2];    // int32
    const float* bw    = (const float*)d_in[3];
    const float* bb    = (const float*)d_in[4];
    const float* lin_w[3]   = {(const float*)d_in[5],  (const float*)d_in[9],  (const float*)d_in[13]};
    const float* att_src[3] = {(const float*)d_in[6],  (const float*)d_in[10], (const float*)d_in[14]};
    const float* att_dst[3] = {(const float*)d_in[7],  (const float*)d_in[11], (const float*)d_in[15]};
    const float* bias[3]    = {(const float*)d_in[8],  (const float*)d_in[12], (const float*)d_in[16]};
    const float* agg_w = (const float*)d_in[17];
    const float* agg_b = (const float*)d_in[18];
    float* out = (float*)d_out;

    k_zero_g<<<(BB * GCOLS + 255) / 256, 256>>>();
    k_input<<<(NN + 31) / 32, 64>>>(sf, bw, bb, batch);

    for (int L = 0; L < 3; L++) {
        int K = (L == 0) ? FF : CC;
        dim3 gg(CC / 64, (NN + 63) / 64);
        k_gemm<<<gg, 256>>>(L, K, lin_w[L]);
        k_att<<<(NN + 7) / 8, 256>>>(att_src[L], att_dst[L]);
        int ne = E2 * HH;
        k_logits<<<(ne + 255) / 256, 256>>>(ei);
        k_exp<<<(ne + 255) / 256, 256>>>(ei);
        k_fillbias<<<(NN * CC + 255) / 256, 256>>>(bias[L]);
        long long nm = (long long)E2 * 64;
        k_msg<<<(unsigned)((nm + 255) / 256), 256>>>(ei);
        k_post<<<(NN + 31) / 32, 256>>>(batch, FF + L * CC);
    }

    k_final<<<BB, BOTN>>>(agg_w, agg_b, out);
}

// round 6
// speedup vs baseline: 1.0124x; 1.0124x over previous
#include <cuda_runtime.h>
#include <cuda_bf16.h>
#include <math.h>
#include <stdint.h>

// Problem constants (fixed shapes)
#define NN   30000
#define EE   240000
#define E2   (EE + NN)      // 270000 edges incl self-loops
#define BB   64
#define FF   64
#define HH   4
#define CC   256            // H*F
#define GCOLS 832           // F*(1+H*T)
#define BOTN 256

#define NEG_INF __int_as_float(0xff800000)

// ---------------- device scratch (no allocations allowed) ----------------
__device__ float g_x0[NN * FF];
__device__ float g_xcur[NN * CC];
__device__ float g_xs[NN * CC];
__device__ float g_out[NN * CC];
__device__ float g_asrc[NN * HH];
__device__ float g_adst[NN * HH];
__device__ float g_segmax[NN * HH];
__device__ float g_segsum[NN * HH];
__device__ float g_ex[E2 * HH];
__device__ float g_g[BB * GCOLS];

// ---------------- helpers ----------------
__device__ __forceinline__ void atomicMaxFloat(float* addr, float v) {
    if (v >= 0.0f) atomicMax((int*)addr, __float_as_int(v));
    else           atomicMin((unsigned int*)addr, __float_as_uint(v));
}

__device__ __forceinline__ void edge_endpoints(const int* __restrict__ ei,
                                               int e, int& src, int& dst) {
    if (e < EE) { src = ei[e]; dst = ei[EE + e]; }
    else        { src = dst = e - EE; }
}

__device__ __forceinline__ uint32_t pk2(float a, float b) {
    __nv_bfloat162 h = __floats2bfloat162_rn(a, b);
    return *(uint32_t*)&h;
}
__device__ __forceinline__ __nv_bfloat16 bf_hi(float a) { return __float2bfloat16_rn(a); }
__device__ __forceinline__ __nv_bfloat16 bf_lo(float a) {
    return __float2bfloat16_rn(a - __bfloat162float(__float2bfloat16_rn(a)));
}

// m16n8k16 bf16 MMA, fp32 accumulate (standard sm_80+ PTX; base sm_103 OK)
__device__ __forceinline__ void mma16816(float* c, const uint32_t* a,
                                         uint32_t b0, uint32_t b1) {
    asm volatile(
        "mma.sync.aligned.m16n8k16.row.col.f32.bf16.bf16.f32 "
        "{%0,%1,%2,%3}, {%4,%5,%6,%7}, {%8,%9}, {%0,%1,%2,%3};"
        : "+f"(c[0]), "+f"(c[1]), "+f"(c[2]), "+f"(c[3])
        : "r"(a[0]), "r"(a[1]), "r"(a[2]), "r"(a[3]), "r"(b0), "r"(b1));
}

// ---------------- kernels ----------------

__global__ void k_zero_g() {
    int i = blockIdx.x * blockDim.x + threadIdx.x;
    if (i < BB * GCOLS) g_g[i] = 0.0f;
}

// x0 = relu(sf @ bbox_w + bbox_b); fused g0 = segment_max(x0, batch)
__global__ void k_input(const float* __restrict__ sf,
                        const float* __restrict__ bw,
                        const float* __restrict__ bb,
                        const int* __restrict__ batch) {
    int c = threadIdx.x;
    int base = blockIdx.x * 32;
    if (base >= NN) return;
    float w0 = bw[0 * FF + c], w1 = bw[1 * FF + c], w2 = bw[2 * FF + c],
          w3 = bw[3 * FF + c], w4 = bw[4 * FF + c];
    float bias = bb[c];
    int curb = batch[base];
    float mx = 0.0f;
    int lim = min(32, NN - base);
    for (int i = 0; i < lim; i++) {
        int n = base + i;
        int b = batch[n];
        if (b != curb) {
            atomicMax((int*)&g_g[curb * GCOLS + c], __float_as_int(mx));
            curb = b; mx = 0.0f;
        }
        const float* s = &sf[n * 5];
        float v = bias + s[0]*w0 + s[1]*w1 + s[2]*w2 + s[3]*w3 + s[4]*w4;
        v = fmaxf(v, 0.0f);
        g_x0[n * FF + c] = v;
        mx = fmaxf(mx, v);
    }
    atomicMax((int*)&g_g[curb * GCOLS + c], __float_as_int(mx));
}

// ---- split-bf16 tensor-core GEMM: g_xs[m, :] = A[m, :K] @ W[:K, :256]
// CTA 128x128, 8 warps = 4(M) x 2(N), warp tile 32x64.
// smem rows padded to 40 bf16 -> conflict-free fragment loads.
#define APAD 40

__global__ void __launch_bounds__(256, 2)
k_gemm_mma(int layer, int K, const float* __restrict__ W) {
    const float* A = (layer == 0) ? g_x0 : g_xcur;
    __shared__ __nv_bfloat16 Ah[128 * APAD], Al[128 * APAD];
    __shared__ __nv_bfloat16 Bh[128 * APAD], Bl[128 * APAD];

    int tid = threadIdx.x;
    int warp = tid >> 5, lane = tid & 31;
    int wm = warp & 3;        // M warp: rows wm*32
    int wn = warp >> 2;       // N warp: cols wn*64
    int g = lane >> 2, t = lane & 3;
    int bm = blockIdx.y * 128;
    int bn = blockIdx.x * 128;

    float acc[2][8][4];
#pragma unroll
    for (int i = 0; i < 2; i++)
#pragma unroll
        for (int j = 0; j < 8; j++)
#pragma unroll
            for (int q = 0; q < 4; q++) acc[i][j][q] = 0.0f;

    for (int k0 = 0; k0 < K; k0 += 32) {
        __syncthreads();   // previous iteration's fragment reads done
        // --- A chunk: 128 rows x 32 k, fp32 -> bf16 hi/lo
        {
#pragma unroll
            for (int i = tid; i < 1024; i += 256) {
                int r = i >> 3;            // 8 float4 per row
                int kq = (i & 7) << 2;
                float4 v = make_float4(0.f, 0.f, 0.f, 0.f);
                int gr = bm + r;
                if (gr < NN) v = *(const float4*)&A[(size_t)gr * K + k0 + kq];
                uint32_t* ph = (uint32_t*)&Ah[r * APAD + kq];
                uint32_t* pl = (uint32_t*)&Al[r * APAD + kq];
                ph[0] = pk2(v.x, v.y); ph[1] = pk2(v.z, v.w);
                pl[0] = pk2(__bfloat162float(bf_lo(v.x)), __bfloat162float(bf_lo(v.y)));
                pl[1] = pk2(__bfloat162float(bf_lo(v.z)), __bfloat162float(bf_lo(v.w)));
            }
        }
        // --- B chunk transposed: Bs[n][k] = W[k0+k][bn+n], 128 n x 32 k
        {
#pragma unroll
            for (int i = tid; i < 1024; i += 256) {
                int k = i >> 5;            // 32 float4 per k-row
                int nq = (i & 31) << 2;
                float4 v = *(const float4*)&W[(size_t)(k0 + k) * CC + bn + nq];
                float f[4] = {v.x, v.y, v.z, v.w};
#pragma unroll
                for (int j = 0; j < 4; j++) {
                    Bh[(nq + j) * APAD + k] = bf_hi(f[j]);
                    Bl[(nq + j) * APAD + k] = bf_lo(f[j]);
                }
            }
        }
        __syncthreads();

#pragma unroll
        for (int ks = 0; ks < 32; ks += 16) {
            uint32_t ah[2][4], al[2][4];
#pragma unroll
            for (int mt = 0; mt < 2; mt++) {
                int r = wm * 32 + mt * 16;
                ah[mt][0] = *(uint32_t*)&Ah[(r + g) * APAD + ks + 2 * t];
                ah[mt][1] = *(uint32_t*)&Ah[(r + g + 8) * APAD + ks + 2 * t];
                ah[mt][2] = *(uint32_t*)&Ah[(r + g) * APAD + ks + 8 + 2 * t];
                ah[mt][3] = *(uint32_t*)&Ah[(r + g + 8) * APAD + ks + 8 + 2 * t];
                al[mt][0] = *(uint32_t*)&Al[(r + g) * APAD + ks + 2 * t];
                al[mt][1] = *(uint32_t*)&Al[(r + g + 8) * APAD + ks + 2 * t];
                al[mt][2] = *(uint32_t*)&Al[(r + g) * APAD + ks + 8 + 2 * t];
                al[mt][3] = *(uint32_t*)&Al[(r + g + 8) * APAD + ks + 8 + 2 * t];
            }
#pragma unroll
            for (int nt = 0; nt < 8; nt++) {
                int c = wn * 64 + nt * 8 + g;
                uint32_t bh0 = *(uint32_t*)&Bh[c * APAD + ks + 2 * t];
                uint32_t bh1 = *(uint32_t*)&Bh[c * APAD + ks + 8 + 2 * t];
                uint32_t bl0 = *(uint32_t*)&Bl[c * APAD + ks + 2 * t];
                uint32_t bl1 = *(uint32_t*)&Bl[c * APAD + ks + 8 + 2 * t];
#pragma unroll
                for (int mt = 0; mt < 2; mt++) {
                    mma16816(acc[mt][nt], ah[mt], bh0, bh1);
                    mma16816(acc[mt][nt], ah[mt], bl0, bl1);
                    mma16816(acc[mt][nt], al[mt], bh0, bh1);
                }
            }
        }
    }

    // --- store C
#pragma unroll
    for (int mt = 0; mt < 2; mt++) {
        int r0 = bm + wm * 32 + mt * 16 + g;
#pragma unroll
        for (int nt = 0; nt < 8; nt++) {
            int c = bn + wn * 64 + nt * 8 + 2 * t;
            if (r0 < NN)
                *(float2*)&g_xs[(size_t)r0 * CC + c] =
                    make_float2(acc[mt][nt][0], acc[mt][nt][1]);
            if (r0 + 8 < NN)
                *(float2*)&g_xs[(size_t)(r0 + 8) * CC + c] =
                    make_float2(acc[mt][nt][2], acc[mt][nt][3]);
        }
    }
}

// per node: a_src[n,h], a_dst[n,h]; init segmax/segsum
__global__ void k_att(const float* __restrict__ att_src,
                      const float* __restrict__ att_dst) {
    __shared__ float s_src[CC], s_dst[CC];
    int tid = threadIdx.x;
    s_src[tid] = att_src[tid];
    s_dst[tid] = att_dst[tid];
    __syncthreads();
    int warp = tid >> 5, lane = tid & 31;
    int n = blockIdx.x * 8 + warp;
    if (n >= NN) return;
    const float* row = &g_xs[(size_t)n * CC];
#pragma unroll
    for (int h = 0; h < HH; h++) {
        float x0 = row[h * 64 + lane];
        float x1 = row[h * 64 + 32 + lane];
        float s = x0 * s_src[h * 64 + lane] + x1 * s_src[h * 64 + 32 + lane];
        float d = x0 * s_dst[h * 64 + lane] + x1 * s_dst[h * 64 + 32 + lane];
#pragma unroll
        for (int o = 16; o > 0; o >>= 1) {
            s += __shfl_down_sync(0xffffffff, s, o);
            d += __shfl_down_sync(0xffffffff, d, o);
        }
        if (lane == 0) {
            g_asrc[n * HH + h] = s;
            g_adst[n * HH + h] = d;
        }
    }
    if (lane < HH) {
        g_segmax[n * HH + lane] = NEG_INF;
        g_segsum[n * HH + lane] = 0.0f;
    }
}

__global__ void k_logits(const int* __restrict__ ei) {
    int idx = blockIdx.x * blockDim.x + threadIdx.x;
    if (idx >= E2 * HH) return;
    int e = idx >> 2, h = idx & 3;
    int src, dst;
    edge_endpoints(ei, e, src, dst);
    float v = g_asrc[src * HH + h] + g_adst[dst * HH + h];
    v = (v >= 0.0f) ? v : 0.2f * v;
    g_ex[idx] = v;
    atomicMaxFloat(&g_segmax[dst * HH + h], v);
}

__global__ void k_exp(const int* __restrict__ ei) {
    int idx = blockIdx.x * blockDim.x + threadIdx.x;
    if (idx >= E2 * HH) return;
    int e = idx >> 2, h = idx & 3;
    int src, dst;
    edge_endpoints(ei, e, src, dst);
    (void)src;
    float t = expf(g_ex[idx] - g_segmax[dst * HH + h]);
    g_ex[idx] = t;
    atomicAdd(&g_segsum[dst * HH + h], t);
}

__global__ void k_fillbias(const float* __restrict__ bias) {
    int idx = blockIdx.x * blockDim.x + threadIdx.x;
    if (idx < NN * CC) g_out[idx] = bias[idx & (CC - 1)];
}

__global__ void k_msg(const int* __restrict__ ei) {
    long long gtid = (long long)blockIdx.x * blockDim.x + threadIdx.x;
    if (gtid >= (long long)E2 * 64) return;
    int e = (int)(gtid >> 6);
    int lane = (int)(gtid & 63);
    int c = lane * 4;
    int h = c >> 6;
    int src, dst;
    edge_endpoints(ei, e, src, dst);
    float alpha = g_ex[e * HH + h] / (g_segsum[dst * HH + h] + 1e-16f);
    float4 v = *(const float4*)&g_xs[(size_t)src * CC + c];
    float* o = &g_out[(size_t)dst * CC + c];
    atomicAdd(o + 0, alpha * v.x);
    atomicAdd(o + 1, alpha * v.y);
    atomicAdd(o + 2, alpha * v.z);
    atomicAdd(o + 3, alpha * v.w);
}

__global__ void k_post(const int* __restrict__ batch, int goff) {
    int c = threadIdx.x;
    int base = blockIdx.x * 32;
    if (base >= NN) return;
    int curb = batch[base];
    float mx = 0.0f;
    int lim = min(32, NN - base);
    for (int i = 0; i < lim; i++) {
        int n = base + i;
        int b = batch[n];
        if (b != curb) {
            atomicMax((int*)&g_g[curb * GCOLS + goff + c], __float_as_int(mx));
            curb = b; mx = 0.0f;
        }
        float v = fmaxf(g_out[(size_t)n * CC + c], 0.0f);
        g_xcur[(size_t)n * CC + c] = v;
        mx = fmaxf(mx, v);
    }
    atomicMax((int*)&g_g[curb * GCOLS + goff + c], __float_as_int(mx));
}

__global__ void k_final(const float* __restrict__ agg_w,
                        const float* __restrict__ agg_b,
                        float* __restrict__ out) {
    __shared__ float sg[GCOLS];
    int b = blockIdx.x;
    int tid = threadIdx.x;
    for (int k = tid; k < GCOLS; k += 256) sg[k] = g_g[b * GCOLS + k];
    __syncthreads();
    float acc = agg_b[tid];
    for (int k = 0; k < GCOLS; k++) acc += sg[k] * agg_w[(size_t)k * BOTN + tid];
    out[b * BOTN + tid] = acc;
}

// ---------------- host ----------------
extern "C" void kernel_launch(void* const* d_in, const int* in_sizes, int n_in,
                              void* d_out, int out_size) {
    const float* sf    = (const float*)d_in[0];
    const int*   ei    = (const int*)d_in[1];
    const int*   batch = (const int*)d_in[2];
    const float* bw    = (const float*)d_in[3];
    const float* bb    = (const float*)d_in[4];
    const float* lin_w[3]   = {(const float*)d_in[5],  (const float*)d_in[9],  (const float*)d_in[13]};
    const float* att_src[3] = {(const float*)d_in[6],  (const float*)d_in[10], (const float*)d_in[14]};
    const float* att_dst[3] = {(const float*)d_in[7],  (const float*)d_in[11], (const float*)d_in[15]};
    const float* bias[3]    = {(const float*)d_in[8],  (const float*)d_in[12], (const float*)d_in[16]};
    const float* agg_w = (const float*)d_in[17];
    const float* agg_b = (const float*)d_in[18];
    float* out = (float*)d_out;

    k_zero_g<<<(BB * GCOLS + 255) / 256, 256>>>();
    k_input<<<(NN + 31) / 32, 64>>>(sf, bw, bb, batch);

    for (int L = 0; L < 3; L++) {
        int K = (L == 0) ? FF : CC;
        dim3 gg(2, (NN + 127) / 128);
        k_gemm_mma<<<gg, 256>>>(L, K, lin_w[L]);
        k_att<<<(NN + 7) / 8, 256>>>(att_src[L], att_dst[L]);
        int ne = E2 * HH;
        k_logits<<<(ne + 255) / 256, 256>>>(ei);
        k_exp<<<(ne + 255) / 256, 256>>>(ei);
        k_fillbias<<<(NN * CC + 255) / 256, 256>>>(bias[L]);
        long long nm = (long long)E2 * 64;
        k_msg<<<(unsigned)((nm + 255) / 256), 256>>>(ei);
        k_post<<<(NN + 31) / 32, 256>>>(batch, FF + L * CC);
    }

    k_final<<<BB, BOTN>>>(agg_w, agg_b, out);
}

// round 8
// speedup vs baseline: 1.1960x; 1.1814x over previous
#include <cuda_runtime.h>
#include <cuda_bf16.h>
#include <math.h>
#include <stdint.h>

// Problem constants (fixed shapes)
#define NN   30000
#define EE   240000
#define E2   (EE + NN)      // 270000 edges incl self-loops
#define BB   64
#define FF   64
#define HH   4
#define CC   256            // H*F
#define GCOLS 832           // F*(1+H*T)
#define BOTN 256

#define NEG_INF __int_as_float(0xff800000)

// ---------------- device scratch (no allocations allowed) ----------------
__device__ float g_x0[NN * FF];
__device__ float g_xcur[NN * CC];
__device__ float g_xs[NN * CC];
__device__ float g_out[NN * CC];
__device__ float g_asrc[NN * HH];
__device__ float g_adst[NN * HH];
__device__ float g_g[BB * GCOLS];
// CSR (built once per launch)
__device__ int g_deg[NN];
__device__ int g_cursor[NN];
__device__ int g_off[NN + 1];
__device__ int g_csr_src[E2];

// ---------------- helpers ----------------
__device__ __forceinline__ void edge_endpoints(const int* __restrict__ ei,
                                               int e, int& src, int& dst) {
    if (e < EE) { src = ei[e]; dst = ei[EE + e]; }
    else        { src = dst = e - EE; }
}

__device__ __forceinline__ uint32_t pk2(float a, float b) {
    __nv_bfloat162 h = __floats2bfloat162_rn(a, b);
    return *(uint32_t*)&h;
}
__device__ __forceinline__ __nv_bfloat16 bf_hi(float a) { return __float2bfloat16_rn(a); }
__device__ __forceinline__ __nv_bfloat16 bf_lo(float a) {
    return __float2bfloat16_rn(a - __bfloat162float(__float2bfloat16_rn(a)));
}

// m16n8k16 bf16 MMA, fp32 accumulate (standard sm_80+ PTX; base sm_103 OK)
__device__ __forceinline__ void mma16816(float* c, const uint32_t* a,
                                         uint32_t b0, uint32_t b1) {
    asm volatile(
        "mma.sync.aligned.m16n8k16.row.col.f32.bf16.bf16.f32 "
        "{%0,%1,%2,%3}, {%4,%5,%6,%7}, {%8,%9}, {%0,%1,%2,%3};"
        : "+f"(c[0]), "+f"(c[1]), "+f"(c[2]), "+f"(c[3])
        : "r"(a[0]), "r"(a[1]), "r"(a[2]), "r"(a[3]), "r"(b0), "r"(b1));
}

// ---------------- CSR build (once per launch) ----------------
__global__ void k_zero_counts() {
    int i = blockIdx.x * blockDim.x + threadIdx.x;
    if (i < NN) { g_deg[i] = 0; g_cursor[i] = 0; }
    if (i < BB * GCOLS) g_g[i] = 0.0f;
}

__global__ void k_hist(const int* __restrict__ ei) {
    int e = blockIdx.x * blockDim.x + threadIdx.x;
    if (e >= E2) return;
    int dst = (e < EE) ? ei[EE + e] : e - EE;
    atomicAdd(&g_deg[dst], 1);
}

// single block, 1024 threads: exclusive scan of g_deg -> g_off
__global__ void k_scan() {
    __shared__ int sp[1024];
    int tid = threadIdx.x;
    const int CHK = (NN + 1023) / 1024;   // 30
    int base = tid * CHK;
    int s = 0;
    for (int i = 0; i < CHK; i++) {
        int idx = base + i;
        if (idx < NN) s += g_deg[idx];
    }
    sp[tid] = s;
    __syncthreads();
    for (int o = 1; o < 1024; o <<= 1) {
        int u = (tid >= o) ? sp[tid - o] : 0;
        __syncthreads();
        sp[tid] += u;
        __syncthreads();
    }
    int run = sp[tid] - s;
    for (int i = 0; i < CHK; i++) {
        int idx = base + i;
        if (idx < NN) { g_off[idx] = run; run += g_deg[idx]; }
    }
    if (tid == 1023) g_off[NN] = sp[1023];
}

__global__ void k_scatter(const int* __restrict__ ei) {
    int e = blockIdx.x * blockDim.x + threadIdx.x;
    if (e >= E2) return;
    int src, dst;
    edge_endpoints(ei, e, src, dst);
    int pos = atomicAdd(&g_cursor[dst], 1);
    g_csr_src[g_off[dst] + pos] = src;
}

// ---------------- input layer ----------------
__global__ void k_input(const float* __restrict__ sf,
                        const float* __restrict__ bw,
                        const float* __restrict__ bb,
                        const int* __restrict__ batch) {
    int c = threadIdx.x;
    int base = blockIdx.x * 32;
    if (base >= NN) return;
    float w0 = bw[0 * FF + c], w1 = bw[1 * FF + c], w2 = bw[2 * FF + c],
          w3 = bw[3 * FF + c], w4 = bw[4 * FF + c];
    float bias = bb[c];
    int curb = batch[base];
    float mx = 0.0f;
    int lim = min(32, NN - base);
    for (int i = 0; i < lim; i++) {
        int n = base + i;
        int b = batch[n];
        if (b != curb) {
            atomicMax((int*)&g_g[curb * GCOLS + c], __float_as_int(mx));
            curb = b; mx = 0.0f;
        }
        const float* s = &sf[n * 5];
        float v = bias + s[0]*w0 + s[1]*w1 + s[2]*w2 + s[3]*w3 + s[4]*w4;
        v = fmaxf(v, 0.0f);
        g_x0[n * FF + c] = v;
        mx = fmaxf(mx, v);
    }
    atomicMax((int*)&g_g[curb * GCOLS + c], __float_as_int(mx));
}

// ---- split-bf16 tensor-core GEMM: g_xs[m, :] = A[m, :K] @ W[:K, :256]
#define APAD 40

__global__ void __launch_bounds__(256, 2)
k_gemm_mma(int layer, int K, const float* __restrict__ W) {
    const float* A = (layer == 0) ? g_x0 : g_xcur;
    __shared__ __nv_bfloat16 Ah[128 * APAD], Al[128 * APAD];
    __shared__ __nv_bfloat16 Bh[128 * APAD], Bl[128 * APAD];

    int tid = threadIdx.x;
    int warp = tid >> 5, lane = tid & 31;
    int wm = warp & 3;
    int wn = warp >> 2;
    int g = lane >> 2, t = lane & 3;
    int bm = blockIdx.y * 128;
    int bn = blockIdx.x * 128;

    float acc[2][8][4];
#pragma unroll
    for (int i = 0; i < 2; i++)
#pragma unroll
        for (int j = 0; j < 8; j++)
#pragma unroll
            for (int q = 0; q < 4; q++) acc[i][j][q] = 0.0f;

    for (int k0 = 0; k0 < K; k0 += 32) {
        __syncthreads();
        {
#pragma unroll
            for (int i = tid; i < 1024; i += 256) {
                int r = i >> 3;
                int kq = (i & 7) << 2;
                float4 v = make_float4(0.f, 0.f, 0.f, 0.f);
                int gr = bm + r;
                if (gr < NN) v = *(const float4*)&A[(size_t)gr * K + k0 + kq];
                uint32_t* ph = (uint32_t*)&Ah[r * APAD + kq];
                uint32_t* pl = (uint32_t*)&Al[r * APAD + kq];
                ph[0] = pk2(v.x, v.y); ph[1] = pk2(v.z, v.w);
                pl[0] = pk2(__bfloat162float(bf_lo(v.x)), __bfloat162float(bf_lo(v.y)));
                pl[1] = pk2(__bfloat162float(bf_lo(v.z)), __bfloat162float(bf_lo(v.w)));
            }
        }
        {
#pragma unroll
            for (int i = tid; i < 1024; i += 256) {
                int k = i >> 5;
                int nq = (i & 31) << 2;
                float4 v = *(const float4*)&W[(size_t)(k0 + k) * CC + bn + nq];
                float f[4] = {v.x, v.y, v.z, v.w};
#pragma unroll
                for (int j = 0; j < 4; j++) {
                    Bh[(nq + j) * APAD + k] = bf_hi(f[j]);
                    Bl[(nq + j) * APAD + k] = bf_lo(f[j]);
                }
            }
        }
        __syncthreads();

#pragma unroll
        for (int ks = 0; ks < 32; ks += 16) {
            uint32_t ah[2][4], al[2][4];
#pragma unroll
            for (int mt = 0; mt < 2; mt++) {
                int r = wm * 32 + mt * 16;
                ah[mt][0] = *(uint32_t*)&Ah[(r + g) * APAD + ks + 2 * t];
                ah[mt][1] = *(uint32_t*)&Ah[(r + g + 8) * APAD + ks + 2 * t];
                ah[mt][2] = *(uint32_t*)&Ah[(r + g) * APAD + ks + 8 + 2 * t];
                ah[mt][3] = *(uint32_t*)&Ah[(r + g + 8) * APAD + ks + 8 + 2 * t];
                al[mt][0] = *(uint32_t*)&Al[(r + g) * APAD + ks + 2 * t];
                al[mt][1] = *(uint32_t*)&Al[(r + g + 8) * APAD + ks + 2 * t];
                al[mt][2] = *(uint32_t*)&Al[(r + g) * APAD + ks + 8 + 2 * t];
                al[mt][3] = *(uint32_t*)&Al[(r + g + 8) * APAD + ks + 8 + 2 * t];
            }
#pragma unroll
            for (int nt = 0; nt < 8; nt++) {
                int c = wn * 64 + nt * 8 + g;
                uint32_t bh0 = *(uint32_t*)&Bh[c * APAD + ks + 2 * t];
                uint32_t bh1 = *(uint32_t*)&Bh[c * APAD + ks + 8 + 2 * t];
                uint32_t bl0 = *(uint32_t*)&Bl[c * APAD + ks + 2 * t];
                uint32_t bl1 = *(uint32_t*)&Bl[c * APAD + ks + 8 + 2 * t];
#pragma unroll
                for (int mt = 0; mt < 2; mt++) {
                    mma16816(acc[mt][nt], ah[mt], bh0, bh1);
                    mma16816(acc[mt][nt], ah[mt], bl0, bl1);
                    mma16816(acc[mt][nt], al[mt], bh0, bh1);
                }
            }
        }
    }

#pragma unroll
    for (int mt = 0; mt < 2; mt++) {
        int r0 = bm + wm * 32 + mt * 16 + g;
#pragma unroll
        for (int nt = 0; nt < 8; nt++) {
            int c = bn + wn * 64 + nt * 8 + 2 * t;
            if (r0 < NN)
                *(float2*)&g_xs[(size_t)r0 * CC + c] =
                    make_float2(acc[mt][nt][0], acc[mt][nt][1]);
            if (r0 + 8 < NN)
                *(float2*)&g_xs[(size_t)(r0 + 8) * CC + c] =
                    make_float2(acc[mt][nt][2], acc[mt][nt][3]);
        }
    }
}

// per node attention coefficients a_src[n,h], a_dst[n,h]
__global__ void k_att(const float* __restrict__ att_src,
                      const float* __restrict__ att_dst) {
    __shared__ float s_src[CC], s_dst[CC];
    int tid = threadIdx.x;
    s_src[tid] = att_src[tid];
    s_dst[tid] = att_dst[tid];
    __syncthreads();
    int warp = tid >> 5, lane = tid & 31;
    int n = blockIdx.x * 8 + warp;
    if (n >= NN) return;
    const float* row = &g_xs[(size_t)n * CC];
#pragma unroll
    for (int h = 0; h < HH; h++) {
        float x0 = row[h * 64 + lane];
        float x1 = row[h * 64 + 32 + lane];
        float s = x0 * s_src[h * 64 + lane] + x1 * s_src[h * 64 + 32 + lane];
        float d = x0 * s_dst[h * 64 + lane] + x1 * s_dst[h * 64 + 32 + lane];
#pragma unroll
        for (int o = 16; o > 0; o >>= 1) {
            s += __shfl_down_sync(0xffffffff, s, o);
            d += __shfl_down_sync(0xffffffff, d, o);
        }
        if (lane == 0) {
            g_asrc[n * HH + h] = s;
            g_adst[n * HH + h] = d;
        }
    }
}

// ---- fused GAT aggregation: one warp per dst node, no atomics.
// out[n] = (sum_e ex_e * xs[src_e]) / (sum_e ex_e + 1e-16) + bias
__global__ void __launch_bounds__(256)
k_gat(const float* __restrict__ bias) {
    __shared__ int   ssrc[8][32];
    __shared__ float sex[8][32][4];
    int tid = threadIdx.x;
    int warp = tid >> 5, lane = tid & 31;
    int n = blockIdx.x * 8 + warp;
    if (n >= NN) return;
    int beg = g_off[n], end = g_off[n + 1];
    float4 ad = *(const float4*)&g_adst[n * HH];

    // pass 1: max logit per head
    float4 mx = make_float4(NEG_INF, NEG_INF, NEG_INF, NEG_INF);
    for (int i = beg + lane; i < end; i += 32) {
        int s = g_csr_src[i];
        float4 as = *(const float4*)&g_asrc[s * HH];
        float lx = as.x + ad.x, ly = as.y + ad.y, lz = as.z + ad.z, lw = as.w + ad.w;
        lx = (lx >= 0.f) ? lx : 0.2f * lx;
        ly = (ly >= 0.f) ? ly : 0.2f * ly;
        lz = (lz >= 0.f) ? lz : 0.2f * lz;
        lw = (lw >= 0.f) ? lw : 0.2f * lw;
        mx.x = fmaxf(mx.x, lx); mx.y = fmaxf(mx.y, ly);
        mx.z = fmaxf(mx.z, lz); mx.w = fmaxf(mx.w, lw);
    }
#pragma unroll
    for (int o = 16; o > 0; o >>= 1) {
        mx.x = fmaxf(mx.x, __shfl_xor_sync(0xffffffff, mx.x, o));
        mx.y = fmaxf(mx.y, __shfl_xor_sync(0xffffffff, mx.y, o));
        mx.z = fmaxf(mx.z, __shfl_xor_sync(0xffffffff, mx.z, o));
        mx.w = fmaxf(mx.w, __shfl_xor_sync(0xffffffff, mx.w, o));
    }

    // pass 2: chunks of 32 edges
    float acc[8];
#pragma unroll
    for (int q = 0; q < 8; q++) acc[q] = 0.0f;
    float4 den = make_float4(0.f, 0.f, 0.f, 0.f);
    int myc = lane * 8;          // this lane's channel base; head = lane>>3
    for (int cb = beg; cb < end; cb += 32) {
        int i = cb + lane;
        int s = 0;
        float4 ex = make_float4(0.f, 0.f, 0.f, 0.f);
        if (i < end) {
            s = g_csr_src[i];
            float4 as = *(const float4*)&g_asrc[s * HH];
            float lx = as.x + ad.x, ly = as.y + ad.y, lz = as.z + ad.z, lw = as.w + ad.w;
            lx = (lx >= 0.f) ? lx : 0.2f * lx;
            ly = (ly >= 0.f) ? ly : 0.2f * ly;
            lz = (lz >= 0.f) ? lz : 0.2f * lz;
            lw = (lw >= 0.f) ? lw : 0.2f * lw;
            ex = make_float4(__expf(lx - mx.x), __expf(ly - mx.y),
                             __expf(lz - mx.z), __expf(lw - mx.w));
            den.x += ex.x; den.y += ex.y; den.z += ex.z; den.w += ex.w;
        }
        ssrc[warp][lane] = s;
        *(float4*)&sex[warp][lane][0] = ex;
        __syncwarp();
        int cnt = min(32, end - cb);
        for (int j = 0; j < cnt; j++) {
            int s2 = ssrc[warp][j];
            float exv = sex[warp][j][lane >> 3];
            const float4* p = (const float4*)&g_xs[(size_t)s2 * CC + myc];
            float4 v1 = p[0];
            float4 v2 = p[1];
            acc[0] += exv * v1.x; acc[1] += exv * v1.y;
            acc[2] += exv * v1.z; acc[3] += exv * v1.w;
            acc[4] += exv * v2.x; acc[5] += exv * v2.y;
            acc[6] += exv * v2.z; acc[7] += exv * v2.w;
        }
        __syncwarp();
    }

    // reduce denom across lanes
#pragma unroll
    for (int o = 16; o > 0; o >>= 1) {
        den.x += __shfl_xor_sync(0xffffffff, den.x, o);
        den.y += __shfl_xor_sync(0xffffffff, den.y, o);
        den.z += __shfl_xor_sync(0xffffffff, den.z, o);
        den.w += __shfl_xor_sync(0xffffffff, den.w, o);
    }
    float dh[4] = {den.x, den.y, den.z, den.w};
    float rinv = 1.0f / (dh[lane >> 3] + 1e-16f);

    float4 o1, o2;
    const float4* bp = (const float4*)&bias[myc];
    float4 b1 = bp[0], b2 = bp[1];
    o1.x = acc[0] * rinv + b1.x; o1.y = acc[1] * rinv + b1.y;
    o1.z = acc[2] * rinv + b1.z; o1.w = acc[3] * rinv + b1.w;
    o2.x = acc[4] * rinv + b2.x; o2.y = acc[5] * rinv + b2.y;
    o2.z = acc[6] * rinv + b2.z; o2.w = acc[7] * rinv + b2.w;
    float4* op = (float4*)&g_out[(size_t)n * CC + myc];
    op[0] = o1;
    op[1] = o2;
}

// relu(out) -> xcur ; fused segment_max into g at column offset goff
__global__ void k_post(const int* __restrict__ batch, int goff) {
    int c = threadIdx.x;
    int base = blockIdx.x * 32;
    if (base >= NN) return;
    int curb = batch[base];
    float mx = 0.0f;
    int lim = min(32, NN - base);
    for (int i = 0; i < lim; i++) {
        int n = base + i;
        int b = batch[n];
        if (b != curb) {
            atomicMax((int*)&g_g[curb * GCOLS + goff + c], __float_as_int(mx));
            curb = b; mx = 0.0f;
        }
        float v = fmaxf(g_out[(size_t)n * CC + c], 0.0f);
        g_xcur[(size_t)n * CC + c] = v;
        mx = fmaxf(mx, v);
    }
    atomicMax((int*)&g_g[curb * GCOLS + goff + c], __float_as_int(mx));
}

__global__ void k_final(const float* __restrict__ agg_w,
                        const float* __restrict__ agg_b,
                        float* __restrict__ out) {
    __shared__ float sg[GCOLS];
    int b = blockIdx.x;
    int tid = threadIdx.x;
    for (int k = tid; k < GCOLS; k += 256) sg[k] = g_g[b * GCOLS + k];
    __syncthreads();
    float acc = agg_b[tid];
    for (int k = 0; k < GCOLS; k++) acc += sg[k] * agg_w[(size_t)k * BOTN + tid];
    out[b * BOTN + tid] = acc;
}

// ---------------- host ----------------
extern "C" void kernel_launch(void* const* d_in, const int* in_sizes, int n_in,
                              void* d_out, int out_size) {
    const float* sf    = (const float*)d_in[0];
    const int*   ei    = (const int*)d_in[1];
    const int*   batch = (const int*)d_in[2];
    const float* bw    = (const float*)d_in[3];
    const float* bb    = (const float*)d_in[4];
    const float* lin_w[3]   = {(const float*)d_in[5],  (const float*)d_in[9],  (const float*)d_in[13]};
    const float* att_src[3] = {(const float*)d_in[6],  (const float*)d_in[10], (const float*)d_in[14]};
    const float* att_dst[3] = {(const float*)d_in[7],  (const float*)d_in[11], (const float*)d_in[15]};
    const float* bias[3]    = {(const float*)d_in[8],  (const float*)d_in[12], (const float*)d_in[16]};
    const float* agg_w = (const float*)d_in[17];
    const float* agg_b = (const float*)d_in[18];
    float* out = (float*)d_out;

    // CSR build (graph is layer-invariant)
    k_zero_counts<<<(BB * GCOLS + 255) / 256, 256>>>();
    k_hist<<<(E2 + 255) / 256, 256>>>(ei);
    k_scan<<<1, 1024>>>();
    k_scatter<<<(E2 + 255) / 256, 256>>>(ei);

    k_input<<<(NN + 31) / 32, 64>>>(sf, bw, bb, batch);

    for (int L = 0; L < 3; L++) {
        int K = (L == 0) ? FF : CC;
        dim3 gg(2, (NN + 127) / 128);
        k_gemm_mma<<<gg, 256>>>(L, K, lin_w[L]);
        k_att<<<(NN + 7) / 8, 256>>>(att_src[L], att_dst[L]);
        k_gat<<<(NN + 7) / 8, 256>>>(bias[L]);
        k_post<<<(NN + 31) / 32, 256>>>(batch, FF + L * CC);
    }

    k_final<<<BB, BOTN>>>(agg_w, agg_b, out);
}

// round 10
// speedup vs baseline: 2.4733x; 2.0680x over previous
#include <cuda_runtime.h>
#include <cuda_bf16.h>
#include <math.h>
#include <stdint.h>

// Problem constants (fixed shapes)
#define NN   30000
#define EE   240000
#define E2   (EE + NN)      // 270000 edges incl self-loops
#define BB   64
#define FF   64
#define HH   4
#define CC   256            // H*F
#define GCOLS 832           // F*(1+H*T)
#define BOTN 256

// ---------------- device scratch (no allocations allowed) ----------------
__device__ float g_xs[NN * CC];          // xs = x @ W (fp32, read by gat)
__device__ float g_out[NN * CC];         // gat output
__device__ float g_asrc[NN * HH];
__device__ float g_adst[NN * HH];
__device__ float g_g[BB * GCOLS];
// bf16 hi/lo activation + weight buffers (GEMM operands)
__device__ __align__(16) __nv_bfloat16 g_x0hi[NN * FF];
__device__ __align__(16) __nv_bfloat16 g_x0lo[NN * FF];
__device__ __align__(16) __nv_bfloat16 g_xhi[NN * CC];
__device__ __align__(16) __nv_bfloat16 g_xlo[NN * CC];
__device__ __align__(16) __nv_bfloat16 g_wthi[CC * CC];   // transposed [n][k]
__device__ __align__(16) __nv_bfloat16 g_wtlo[CC * CC];
// CSR (built once per launch)
__device__ int g_deg[NN];
__device__ int g_cursor[NN];
__device__ int g_off[NN + 1];
__device__ int g_csr_src[E2];

// ---------------- helpers ----------------
__device__ __forceinline__ void edge_endpoints(const int* __restrict__ ei,
                                               int e, int& src, int& dst) {
    if (e < EE) { src = ei[e]; dst = ei[EE + e]; }
    else        { src = dst = e - EE; }
}

__device__ __forceinline__ __nv_bfloat16 bf_hi(float a) { return __float2bfloat16_rn(a); }
__device__ __forceinline__ __nv_bfloat16 bf_lo(float a) {
    return __float2bfloat16_rn(a - __bfloat162float(__float2bfloat16_rn(a)));
}

// m16n8k16 bf16 MMA, fp32 accumulate
__device__ __forceinline__ void mma16816(float* c, const uint32_t* a,
                                         uint32_t b0, uint32_t b1) {
    asm volatile(
        "mma.sync.aligned.m16n8k16.row.col.f32.bf16.bf16.f32 "
        "{%0,%1,%2,%3}, {%4,%5,%6,%7}, {%8,%9}, {%0,%1,%2,%3};"
        : "+f"(c[0]), "+f"(c[1]), "+f"(c[2]), "+f"(c[3])
        : "r"(a[0]), "r"(a[1]), "r"(a[2]), "r"(a[3]), "r"(b0), "r"(b1));
}

// ---------------- CSR build (once per launch) ----------------
__global__ void k_zero_counts() {
    int i = blockIdx.x * blockDim.x + threadIdx.x;
    if (i < NN) { g_deg[i] = 0; g_cursor[i] = 0; }
    if (i < BB * GCOLS) g_g[i] = 0.0f;
}

__global__ void k_hist(const int* __restrict__ ei) {
    int e = blockIdx.x * blockDim.x + threadIdx.x;
    if (e >= E2) return;
    int dst = (e < EE) ? ei[EE + e] : e - EE;
    atomicAdd(&g_deg[dst], 1);
}

__global__ void k_scan() {
    __shared__ int sp[1024];
    int tid = threadIdx.x;
    const int CHK = (NN + 1023) / 1024;
    int base = tid * CHK;
    int s = 0;
    for (int i = 0; i < CHK; i++) {
        int idx = base + i;
        if (idx < NN) s += g_deg[idx];
    }
    sp[tid] = s;
    __syncthreads();
    for (int o = 1; o < 1024; o <<= 1) {
        int u = (tid >= o) ? sp[tid - o] : 0;
        __syncthreads();
        sp[tid] += u;
        __syncthreads();
    }
    int run = sp[tid] - s;
    for (int i = 0; i < CHK; i++) {
        int idx = base + i;
        if (idx < NN) { g_off[idx] = run; run += g_deg[idx]; }
    }
    if (tid == 1023) g_off[NN] = sp[1023];
}

__global__ void k_scatter(const int* __restrict__ ei) {
    int e = blockIdx.x * blockDim.x + threadIdx.x;
    if (e >= E2) return;
    int src, dst;
    edge_endpoints(ei, e, src, dst);
    int pos = atomicAdd(&g_cursor[dst], 1);
    g_csr_src[g_off[dst] + pos] = src;
}

// ---------------- weight transpose + bf16 split (per layer) ----------------
__global__ void k_wconv(int K, const float* __restrict__ W) {
    int idx = blockIdx.x * blockDim.x + threadIdx.x;
    if (idx >= K * CC) return;
    int k = idx >> 8, n = idx & 255;
    float v = W[(size_t)k * CC + n];
    g_wthi[n * K + k] = bf_hi(v);
    g_wtlo[n * K + k] = bf_lo(v);
}

// ---------------- input layer ----------------
__global__ void k_input(const float* __restrict__ sf,
                        const float* __restrict__ bw,
                        const float* __restrict__ bb,
                        const int* __restrict__ batch) {
    int c = threadIdx.x;
    int base = blockIdx.x * 32;
    if (base >= NN) return;
    float w0 = bw[0 * FF + c], w1 = bw[1 * FF + c], w2 = bw[2 * FF + c],
          w3 = bw[3 * FF + c], w4 = bw[4 * FF + c];
    float bias = bb[c];
    int curb = batch[base];
    float mx = 0.0f;
    int lim = min(32, NN - base);
    for (int i = 0; i < lim; i++) {
        int n = base + i;
        int b = batch[n];
        if (b != curb) {
            atomicMax((int*)&g_g[curb * GCOLS + c], __float_as_int(mx));
            curb = b; mx = 0.0f;
        }
        const float* s = &sf[n * 5];
        float v = bias + s[0]*w0 + s[1]*w1 + s[2]*w2 + s[3]*w3 + s[4]*w4;
        v = fmaxf(v, 0.0f);
        g_x0hi[n * FF + c] = bf_hi(v);
        g_x0lo[n * FF + c] = bf_lo(v);
        mx = fmaxf(mx, v);
    }
    atomicMax((int*)&g_g[curb * GCOLS + c], __float_as_int(mx));
}

// ---- split-bf16 tensor-core GEMM + fused attention coefficients.
// g_xs[m,:] = A[m,:K] @ W[:K,:256]; a_src/a_dst from epilogue accumulators.
#define APAD 40

__global__ void __launch_bounds__(256, 2)
k_gemm_mma(int layer, int K,
           const float* __restrict__ att_src, const float* __restrict__ att_dst) {
    const __nv_bfloat16* Ahg = (layer == 0) ? g_x0hi : g_xhi;
    const __nv_bfloat16* Alg = (layer == 0) ? g_x0lo : g_xlo;
    __shared__ __nv_bfloat16 Ah[128 * APAD], Al[128 * APAD];
    __shared__ __nv_bfloat16 Bh[128 * APAD], Bl[128 * APAD];

    int tid = threadIdx.x;
    int warp = tid >> 5, lane = tid & 31;
    int wm = warp & 3;
    int wn = warp >> 2;
    int g = lane >> 2, t = lane & 3;
    int bm = blockIdx.y * 128;
    int bn = blockIdx.x * 128;

    float acc[2][8][4];
#pragma unroll
    for (int i = 0; i < 2; i++)
#pragma unroll
        for (int j = 0; j < 8; j++)
#pragma unroll
            for (int q = 0; q < 4; q++) acc[i][j][q] = 0.0f;

    for (int k0 = 0; k0 < K; k0 += 32) {
        __syncthreads();
        // A chunk: 128 rows x 32 k, uint4 = 8 bf16 per load
        {
#pragma unroll
            for (int i = tid; i < 512; i += 256) {
                int r = i >> 2;            // 4 uint4 per row
                int kq = (i & 3) << 3;
                int gr = bm + r;
                uint4 vh = make_uint4(0, 0, 0, 0), vl = make_uint4(0, 0, 0, 0);
                if (gr < NN) {
                    size_t o = (size_t)gr * K + k0 + kq;
                    vh = *(const uint4*)&Ahg[o];
                    vl = *(const uint4*)&Alg[o];
                }
                *(uint4*)&Ah[r * APAD + kq] = vh;
                *(uint4*)&Al[r * APAD + kq] = vl;
            }
        }
        // B chunk: 128 n x 32 k from transposed bf16 weights
        {
#pragma unroll
            for (int i = tid; i < 512; i += 256) {
                int n = i >> 2;
                int kq = (i & 3) << 3;
                size_t o = (size_t)(bn + n) * K + k0 + kq;
                *(uint4*)&Bh[n * APAD + kq] = *(const uint4*)&g_wthi[o];
                *(uint4*)&Bl[n * APAD + kq] = *(const uint4*)&g_wtlo[o];
            }
        }
        __syncthreads();

#pragma unroll
        for (int ks = 0; ks < 32; ks += 16) {
            uint32_t ah[2][4], al[2][4];
#pragma unroll
            for (int mt = 0; mt < 2; mt++) {
                int r = wm * 32 + mt * 16;
                ah[mt][0] = *(uint32_t*)&Ah[(r + g) * APAD + ks + 2 * t];
                ah[mt][1] = *(uint32_t*)&Ah[(r + g + 8) * APAD + ks + 2 * t];
                ah[mt][2] = *(uint32_t*)&Ah[(r + g) * APAD + ks + 8 + 2 * t];
                ah[mt][3] = *(uint32_t*)&Ah[(r + g + 8) * APAD + ks + 8 + 2 * t];
                al[mt][0] = *(uint32_t*)&Al[(r + g) * APAD + ks + 2 * t];
                al[mt][1] = *(uint32_t*)&Al[(r + g + 8) * APAD + ks + 2 * t];
                al[mt][2] = *(uint32_t*)&Al[(r + g) * APAD + ks + 8 + 2 * t];
                al[mt][3] = *(uint32_t*)&Al[(r + g + 8) * APAD + ks + 8 + 2 * t];
            }
#pragma unroll
            for (int nt = 0; nt < 8; nt++) {
                int c = wn * 64 + nt * 8 + g;
                uint32_t bh0 = *(uint32_t*)&Bh[c * APAD + ks + 2 * t];
                uint32_t bh1 = *(uint32_t*)&Bh[c * APAD + ks + 8 + 2 * t];
                uint32_t bl0 = *(uint32_t*)&Bl[c * APAD + ks + 2 * t];
                uint32_t bl1 = *(uint32_t*)&Bl[c * APAD + ks + 8 + 2 * t];
#pragma unroll
                for (int mt = 0; mt < 2; mt++) {
                    mma16816(acc[mt][nt], ah[mt], bh0, bh1);
                    mma16816(acc[mt][nt], ah[mt], bl0, bl1);
                    mma16816(acc[mt][nt], al[mt], bh0, bh1);
                }
            }
        }
    }

    // store C + fused attention dots
    int h = (bn >> 6) + wn;   // this warp's head (2 heads per CTA col block)
#pragma unroll
    for (int mt = 0; mt < 2; mt++) {
        int r0 = bm + wm * 32 + mt * 16 + g;
        float sA = 0.f, dA = 0.f, sB = 0.f, dB = 0.f;
#pragma unroll
        for (int nt = 0; nt < 8; nt++) {
            int c = bn + wn * 64 + nt * 8 + 2 * t;
            float w0s = att_src[c], w1s = att_src[c + 1];
            float w0d = att_dst[c], w1d = att_dst[c + 1];
            sA += acc[mt][nt][0] * w0s + acc[mt][nt][1] * w1s;
            dA += acc[mt][nt][0] * w0d + acc[mt][nt][1] * w1d;
            sB += acc[mt][nt][2] * w0s + acc[mt][nt][3] * w1s;
            dB += acc[mt][nt][2] * w0d + acc[mt][nt][3] * w1d;
            if (r0 < NN)
                *(float2*)&g_xs[(size_t)r0 * CC + c] =
                    make_float2(acc[mt][nt][0], acc[mt][nt][1]);
            if (r0 + 8 < NN)
                *(float2*)&g_xs[(size_t)(r0 + 8) * CC + c] =
                    make_float2(acc[mt][nt][2], acc[mt][nt][3]);
        }
        // reduce over the 4-lane quad (t = lane&3)
#pragma unroll
        for (int o = 1; o < 4; o <<= 1) {
            sA += __shfl_xor_sync(0xffffffff, sA, o);
            dA += __shfl_xor_sync(0xffffffff, dA, o);
            sB += __shfl_xor_sync(0xffffffff, sB, o);
            dB += __shfl_xor_sync(0xffffffff, dB, o);
        }
        if (t == 0) {
            if (r0 < NN)     { g_asrc[r0 * HH + h] = sA; g_adst[r0 * HH + h] = dA; }
            if (r0 + 8 < NN) { g_asrc[(r0 + 8) * HH + h] = sB; g_adst[(r0 + 8) * HH + h] = dB; }
        }
    }
}

// ---- fused GAT aggregation: one warp per dst node, no atomics, no max pass.
__global__ void __launch_bounds__(256)
k_gat(const float* __restrict__ bias) {
    __shared__ int   ssrc[8][32];
    __shared__ float sex[8][32][4];
    int tid = threadIdx.x;
    int warp = tid >> 5, lane = tid & 31;
    int n = blockIdx.x * 8 + warp;
    if (n >= NN) return;
    int beg = g_off[n], end = g_off[n + 1];
    float4 ad = *(const float4*)&g_adst[n * HH];

    float acc[8];
#pragma unroll
    for (int q = 0; q < 8; q++) acc[q] = 0.0f;
    float4 den = make_float4(0.f, 0.f, 0.f, 0.f);
    int myc = lane * 8;
    int hme = lane >> 3;
    for (int cb = beg; cb < end; cb += 32) {
        int i = cb + lane;
        int s = 0;
        float4 ex = make_float4(0.f, 0.f, 0.f, 0.f);
        if (i < end) {
            s = g_csr_src[i];
            float4 as = *(const float4*)&g_asrc[s * HH];
            float lx = as.x + ad.x, ly = as.y + ad.y, lz = as.z + ad.z, lw = as.w + ad.w;
            lx = (lx >= 0.f) ? lx : 0.2f * lx;
            ly = (ly >= 0.f) ? ly : 0.2f * ly;
            lz = (lz >= 0.f) ? lz : 0.2f * lz;
            lw = (lw >= 0.f) ? lw : 0.2f * lw;
            ex = make_float4(__expf(lx), __expf(ly), __expf(lz), __expf(lw));
            den.x += ex.x; den.y += ex.y; den.z += ex.z; den.w += ex.w;
        }
        ssrc[warp][lane] = s;
        *(float4*)&sex[warp][lane][0] = ex;
        __syncwarp();
        int cnt = min(32, end - cb);
        // pipelined gather: depth-1 load-ahead
        int s0 = ssrc[warp][0];
        float e0 = sex[warp][0][hme];
        const float4* p = (const float4*)&g_xs[(size_t)s0 * CC + myc];
        float4 a1 = p[0], a2 = p[1];
        for (int j = 0; j < cnt; j++) {
            float4 b1 = a1, b2 = a2;
            float ev = e0;
            if (j + 1 < cnt) {
                int sn = ssrc[warp][j + 1];
                e0 = sex[warp][j + 1][hme];
                const float4* q = (const float4*)&g_xs[(size_t)sn * CC + myc];
                a1 = q[0]; a2 = q[1];
            }
            acc[0] += ev * b1.x; acc[1] += ev * b1.y;
            acc[2] += ev * b1.z; acc[3] += ev * b1.w;
            acc[4] += ev * b2.x; acc[5] += ev * b2.y;
            acc[6] += ev * b2.z; acc[7] += ev * b2.w;
        }
        __syncwarp();
    }

#pragma unroll
    for (int o = 16; o > 0; o >>= 1) {
        den.x += __shfl_xor_sync(0xffffffff, den.x, o);
        den.y += __shfl_xor_sync(0xffffffff, den.y, o);
        den.z += __shfl_xor_sync(0xffffffff, den.z, o);
        den.w += __shfl_xor_sync(0xffffffff, den.w, o);
    }
    float dh[4] = {den.x, den.y, den.z, den.w};
    float rinv = 1.0f / (dh[hme] + 1e-16f);

    const float4* bp = (const float4*)&bias[myc];
    float4 b1 = bp[0], b2 = bp[1];
    float4 o1, o2;
    o1.x = acc[0] * rinv + b1.x; o1.y = acc[1] * rinv + b1.y;
    o1.z = acc[2] * rinv + b1.z; o1.w = acc[3] * rinv + b1.w;
    o2.x = acc[4] * rinv + b2.x; o2.y = acc[5] * rinv + b2.y;
    o2.z = acc[6] * rinv + b2.z; o2.w = acc[7] * rinv + b2.w;
    float4* op = (float4*)&g_out[(size_t)n * CC + myc];
    op[0] = o1;
    op[1] = o2;
}

// relu(out) -> bf16 hi/lo for next GEMM ; fused segment_max into g
__global__ void k_post(const int* __restrict__ batch, int goff) {
    int c = threadIdx.x;
    int base = blockIdx.x * 32;
    if (base >= NN) return;
    int curb = batch[base];
    float mx = 0.0f;
    int lim = min(32, NN - base);
    for (int i = 0; i < lim; i++) {
        int n = base + i;
        int b = batch[n];
        if (b != curb) {
            atomicMax((int*)&g_g[curb * GCOLS + goff + c], __float_as_int(mx));
            curb = b; mx = 0.0f;
        }
        float v = fmaxf(g_out[(size_t)n * CC + c], 0.0f);
        g_xhi[(size_t)n * CC + c] = bf_hi(v);
        g_xlo[(size_t)n * CC + c] = bf_lo(v);
        mx = fmaxf(mx, v);
    }
    atomicMax((int*)&g_g[curb * GCOLS + goff + c], __float_as_int(mx));
}

__global__ void k_final(const float* __restrict__ agg_w,
                        const float* __restrict__ agg_b,
                        float* __restrict__ out) {
    __shared__ float sg[GCOLS];
    int b = blockIdx.x;
    int tid = threadIdx.x;
    for (int k = tid; k < GCOLS; k += 256) sg[k] = g_g[b * GCOLS + k];
    __syncthreads();
    float acc = agg_b[tid];
    for (int k = 0; k < GCOLS; k++) acc += sg[k] * agg_w[(size_t)k * BOTN + tid];
    out[b * BOTN + tid] = acc;
}

// ---------------- host ----------------
extern "C" void kernel_launch(void* const* d_in, const int* in_sizes, int n_in,
                              void* d_out, int out_size) {
    const float* sf    = (const float*)d_in[0];
    const int*   ei    = (const int*)d_in[1];
    const int*   batch = (const int*)d_in[2];
    const float* bw    = (const float*)d_in[3];
    const float* bb    = (const float*)d_in[4];
    const float* lin_w[3]   = {(const float*)d_in[5],  (const float*)d_in[9],  (const float*)d_in[13]};
    const float* att_src[3] = {(const float*)d_in[6],  (const float*)d_in[10], (const float*)d_in[14]};
    const float* att_dst[3] = {(const float*)d_in[7],  (const float*)d_in[11], (const float*)d_in[15]};
    const float* bias[3]    = {(const float*)d_in[8],  (const float*)d_in[12], (const float*)d_in[16]};
    const float* agg_w = (const float*)d_in[17];
    const float* agg_b = (const float*)d_in[18];
    float* out = (float*)d_out;

    // CSR build (graph is layer-invariant)
    k_zero_counts<<<(BB * GCOLS + 255) / 256, 256>>>();
    k_hist<<<(E2 + 255) / 256, 256>>>(ei);
    k_scan<<<1, 1024>>>();
    k_scatter<<<(E2 + 255) / 256, 256>>>(ei);

    k_input<<<(NN + 31) / 32, 64>>>(sf, bw, bb, batch);

    for (int L = 0; L < 3; L++) {
        int K = (L == 0) ? FF : CC;
        k_wconv<<<(K * CC + 255) / 256, 256>>>(K, lin_w[L]);
        dim3 gg(2, (NN + 127) / 128);
        k_gemm_mma<<<gg, 256>>>(L, K, att_src[L], att_dst[L]);
        k_gat<<<(NN + 7) / 8, 256>>>(bias[L]);
        k_post<<<(NN + 31) / 32, 256>>>(batch, FF + L * CC);
    }

    k_final<<<BB, BOTN>>>(agg_w, agg_b, out);
}

// round 11
// speedup vs baseline: 2.6872x; 1.0865x over previous
#include <cuda_runtime.h>
#include <cuda_bf16.h>
#include <math.h>
#include <stdint.h>

// Problem constants (fixed shapes)
#define NN   30000
#define EE   240000
#define E2   (EE + NN)      // 270000 edges incl self-loops
#define BB   64
#define FF   64
#define HH   4
#define CC   256            // H*F
#define GCOLS 832           // F*(1+H*T)
#define BOTN 256

// ---------------- device scratch (no allocations allowed) ----------------
__device__ float g_xs[NN * CC];          // xs = x @ W (fp32, read by gat)
__device__ float g_asrc[NN * HH];
__device__ float g_adst[NN * HH];
__device__ float g_g[BB * GCOLS];
// bf16 hi/lo activation + weight buffers (GEMM operands)
__device__ __align__(16) __nv_bfloat16 g_x0hi[NN * FF];
__device__ __align__(16) __nv_bfloat16 g_x0lo[NN * FF];
__device__ __align__(16) __nv_bfloat16 g_xhi[NN * CC];
__device__ __align__(16) __nv_bfloat16 g_xlo[NN * CC];
__device__ __align__(16) __nv_bfloat16 g_wthi[CC * CC];   // transposed [n][k]
__device__ __align__(16) __nv_bfloat16 g_wtlo[CC * CC];
// CSR (built once per launch)
__device__ int g_deg[NN];
__device__ int g_cursor[NN];
__device__ int g_off[NN + 1];
__device__ int g_csr_src[E2];

// ---------------- helpers ----------------
__device__ __forceinline__ void edge_endpoints(const int* __restrict__ ei,
                                               int e, int& src, int& dst) {
    if (e < EE) { src = ei[e]; dst = ei[EE + e]; }
    else        { src = dst = e - EE; }
}

__device__ __forceinline__ __nv_bfloat16 bf_hi(float a) { return __float2bfloat16_rn(a); }
__device__ __forceinline__ __nv_bfloat16 bf_lo(float a) {
    return __float2bfloat16_rn(a - __bfloat162float(__float2bfloat16_rn(a)));
}
__device__ __forceinline__ uint32_t pk2(float a, float b) {
    __nv_bfloat162 h = __floats2bfloat162_rn(a, b);
    return *(uint32_t*)&h;
}

// m16n8k16 bf16 MMA, fp32 accumulate
__device__ __forceinline__ void mma16816(float* c, const uint32_t* a,
                                         uint32_t b0, uint32_t b1) {
    asm volatile(
        "mma.sync.aligned.m16n8k16.row.col.f32.bf16.bf16.f32 "
        "{%0,%1,%2,%3}, {%4,%5,%6,%7}, {%8,%9}, {%0,%1,%2,%3};"
        : "+f"(c[0]), "+f"(c[1]), "+f"(c[2]), "+f"(c[3])
        : "r"(a[0]), "r"(a[1]), "r"(a[2]), "r"(a[3]), "r"(b0), "r"(b1));
}

__device__ __forceinline__ void cpa16(uint32_t dst, const void* src, bool pred) {
    asm volatile("cp.async.cg.shared.global [%0], [%1], 16, %2;"
                 :: "r"(dst), "l"(src), "r"(pred ? 16 : 0));
}
#define CPA_COMMIT() asm volatile("cp.async.commit_group;" ::: "memory")
#define CPA_WAIT1()  asm volatile("cp.async.wait_group 1;" ::: "memory")
#define CPA_WAIT0()  asm volatile("cp.async.wait_group 0;" ::: "memory")

// ---------------- CSR build (once per launch) ----------------
__global__ void k_zero_counts() {
    int i = blockIdx.x * blockDim.x + threadIdx.x;
    if (i < NN) { g_deg[i] = 0; g_cursor[i] = 0; }
    if (i < BB * GCOLS) g_g[i] = 0.0f;
}

__global__ void k_hist(const int* __restrict__ ei) {
    int e = blockIdx.x * blockDim.x + threadIdx.x;
    if (e >= E2) return;
    int dst = (e < EE) ? ei[EE + e] : e - EE;
    atomicAdd(&g_deg[dst], 1);
}

__global__ void k_scan() {
    __shared__ int sp[1024];
    int tid = threadIdx.x;
    const int CHK = (NN + 1023) / 1024;
    int base = tid * CHK;
    int s = 0;
    for (int i = 0; i < CHK; i++) {
        int idx = base + i;
        if (idx < NN) s += g_deg[idx];
    }
    sp[tid] = s;
    __syncthreads();
    for (int o = 1; o < 1024; o <<= 1) {
        int u = (tid >= o) ? sp[tid - o] : 0;
        __syncthreads();
        sp[tid] += u;
        __syncthreads();
    }
    int run = sp[tid] - s;
    for (int i = 0; i < CHK; i++) {
        int idx = base + i;
        if (idx < NN) { g_off[idx] = run; run += g_deg[idx]; }
    }
    if (tid == 1023) g_off[NN] = sp[1023];
}

__global__ void k_scatter(const int* __restrict__ ei) {
    int e = blockIdx.x * blockDim.x + threadIdx.x;
    if (e >= E2) return;
    int src, dst;
    edge_endpoints(ei, e, src, dst);
    int pos = atomicAdd(&g_cursor[dst], 1);
    g_csr_src[g_off[dst] + pos] = src;
}

// ---------------- weight transpose + bf16 split (per layer) ----------------
__global__ void k_wconv(int K, const float* __restrict__ W) {
    int idx = blockIdx.x * blockDim.x + threadIdx.x;
    if (idx >= K * CC) return;
    int k = idx >> 8, n = idx & 255;
    float v = W[(size_t)k * CC + n];
    g_wthi[n * K + k] = bf_hi(v);
    g_wtlo[n * K + k] = bf_lo(v);
}

// ---------------- input layer ----------------
__global__ void k_input(const float* __restrict__ sf,
                        const float* __restrict__ bw,
                        const float* __restrict__ bb,
                        const int* __restrict__ batch) {
    int c = threadIdx.x;
    int base = blockIdx.x * 32;
    if (base >= NN) return;
    float w0 = bw[0 * FF + c], w1 = bw[1 * FF + c], w2 = bw[2 * FF + c],
          w3 = bw[3 * FF + c], w4 = bw[4 * FF + c];
    float bias = bb[c];
    int curb = batch[base];
    float mx = 0.0f;
    int lim = min(32, NN - base);
    for (int i = 0; i < lim; i++) {
        int n = base + i;
        int b = batch[n];
        if (b != curb) {
            atomicMax((int*)&g_g[curb * GCOLS + c], __float_as_int(mx));
            curb = b; mx = 0.0f;
        }
        const float* s = &sf[n * 5];
        float v = bias + s[0]*w0 + s[1]*w1 + s[2]*w2 + s[3]*w3 + s[4]*w4;
        v = fmaxf(v, 0.0f);
        g_x0hi[n * FF + c] = bf_hi(v);
        g_x0lo[n * FF + c] = bf_lo(v);
        mx = fmaxf(mx, v);
    }
    atomicMax((int*)&g_g[curb * GCOLS + c], __float_as_int(mx));
}

// ---- split-bf16 tensor-core GEMM + fused attention coefficients.
// Double-buffered via cp.async. g_xs[m,:] = A[m,:K] @ W[:K,:256]
#define APAD 40
#define ARR_B (128 * APAD * 2)      // bytes per operand array (10240)
#define STG_B (4 * ARR_B)           // bytes per stage (40960)
#define GEMM_SMEM (2 * STG_B)       // 81920

__global__ void __launch_bounds__(256, 2)
k_gemm_mma(int layer, int K,
           const float* __restrict__ att_src, const float* __restrict__ att_dst) {
    const __nv_bfloat16* Ahg = (layer == 0) ? g_x0hi : g_xhi;
    const __nv_bfloat16* Alg = (layer == 0) ? g_x0lo : g_xlo;
    extern __shared__ char smem[];

    int tid = threadIdx.x;
    int warp = tid >> 5, lane = tid & 31;
    int wm = warp & 3;
    int wn = warp >> 2;
    int g = lane >> 2, t = lane & 3;
    int bm = blockIdx.y * 128;
    int bn = blockIdx.x * 128;

    uint32_t sbase = (uint32_t)__cvta_generic_to_shared(smem);

    // fill stage s with chunk starting at k0 (4 cp.async x 4 arrays / thread)
    auto fill = [&](int s, int k0) {
        uint32_t st = sbase + s * STG_B;
#pragma unroll
        for (int i = tid; i < 512; i += 256) {
            int r = i >> 2;
            int kq = (i & 3) << 3;
            int gr = bm + r;
            bool p = gr < NN;
            size_t oa = (size_t)(p ? gr : 0) * K + k0 + kq;
            uint32_t d = (r * APAD + kq) * 2;
            cpa16(st + 0 * ARR_B + d, &Ahg[oa], p);
            cpa16(st + 1 * ARR_B + d, &Alg[oa], p);
            size_t ob = (size_t)(bn + r) * K + k0 + kq;
            cpa16(st + 2 * ARR_B + d, &g_wthi[ob], true);
            cpa16(st + 3 * ARR_B + d, &g_wtlo[ob], true);
        }
        CPA_COMMIT();
    };

    float acc[2][8][4];
#pragma unroll
    for (int i = 0; i < 2; i++)
#pragma unroll
        for (int j = 0; j < 8; j++)
#pragma unroll
            for (int q = 0; q < 4; q++) acc[i][j][q] = 0.0f;

    int nch = K >> 5;
    fill(0, 0);
    for (int ch = 0; ch < nch; ch++) {
        if (ch + 1 < nch) { fill((ch + 1) & 1, (ch + 1) << 5); CPA_WAIT1(); }
        else              { CPA_WAIT0(); }
        __syncthreads();

        const __nv_bfloat16* Ah = (const __nv_bfloat16*)(smem + (ch & 1) * STG_B);
        const __nv_bfloat16* Al = (const __nv_bfloat16*)(smem + (ch & 1) * STG_B + ARR_B);
        const __nv_bfloat16* Bh = (const __nv_bfloat16*)(smem + (ch & 1) * STG_B + 2 * ARR_B);
        const __nv_bfloat16* Bl = (const __nv_bfloat16*)(smem + (ch & 1) * STG_B + 3 * ARR_B);

#pragma unroll
        for (int ks = 0; ks < 32; ks += 16) {
            uint32_t ah[2][4], al[2][4];
#pragma unroll
            for (int mt = 0; mt < 2; mt++) {
                int r = wm * 32 + mt * 16;
                ah[mt][0] = *(uint32_t*)&Ah[(r + g) * APAD + ks + 2 * t];
                ah[mt][1] = *(uint32_t*)&Ah[(r + g + 8) * APAD + ks + 2 * t];
                ah[mt][2] = *(uint32_t*)&Ah[(r + g) * APAD + ks + 8 + 2 * t];
                ah[mt][3] = *(uint32_t*)&Ah[(r + g + 8) * APAD + ks + 8 + 2 * t];
                al[mt][0] = *(uint32_t*)&Al[(r + g) * APAD + ks + 2 * t];
                al[mt][1] = *(uint32_t*)&Al[(r + g + 8) * APAD + ks + 2 * t];
                al[mt][2] = *(uint32_t*)&Al[(r + g) * APAD + ks + 8 + 2 * t];
                al[mt][3] = *(uint32_t*)&Al[(r + g + 8) * APAD + ks + 8 + 2 * t];
            }
#pragma unroll
            for (int nt = 0; nt < 8; nt++) {
                int c = wn * 64 + nt * 8 + g;
                uint32_t bh0 = *(uint32_t*)&Bh[c * APAD + ks + 2 * t];
                uint32_t bh1 = *(uint32_t*)&Bh[c * APAD + ks + 8 + 2 * t];
                uint32_t bl0 = *(uint32_t*)&Bl[c * APAD + ks + 2 * t];
                uint32_t bl1 = *(uint32_t*)&Bl[c * APAD + ks + 8 + 2 * t];
#pragma unroll
                for (int mt = 0; mt < 2; mt++) {
                    mma16816(acc[mt][nt], ah[mt], bh0, bh1);
                    mma16816(acc[mt][nt], ah[mt], bl0, bl1);
                    mma16816(acc[mt][nt], al[mt], bh0, bh1);
                }
            }
        }
        __syncthreads();
    }

    // store C + fused attention dots
    int h = (bn >> 6) + wn;
#pragma unroll
    for (int mt = 0; mt < 2; mt++) {
        int r0 = bm + wm * 32 + mt * 16 + g;
        float sA = 0.f, dA = 0.f, sB = 0.f, dB = 0.f;
#pragma unroll
        for (int nt = 0; nt < 8; nt++) {
            int c = bn + wn * 64 + nt * 8 + 2 * t;
            float w0s = att_src[c], w1s = att_src[c + 1];
            float w0d = att_dst[c], w1d = att_dst[c + 1];
            sA += acc[mt][nt][0] * w0s + acc[mt][nt][1] * w1s;
            dA += acc[mt][nt][0] * w0d + acc[mt][nt][1] * w1d;
            sB += acc[mt][nt][2] * w0s + acc[mt][nt][3] * w1s;
            dB += acc[mt][nt][2] * w0d + acc[mt][nt][3] * w1d;
            if (r0 < NN)
                *(float2*)&g_xs[(size_t)r0 * CC + c] =
                    make_float2(acc[mt][nt][0], acc[mt][nt][1]);
            if (r0 + 8 < NN)
                *(float2*)&g_xs[(size_t)(r0 + 8) * CC + c] =
                    make_float2(acc[mt][nt][2], acc[mt][nt][3]);
        }
#pragma unroll
        for (int o = 1; o < 4; o <<= 1) {
            sA += __shfl_xor_sync(0xffffffff, sA, o);
            dA += __shfl_xor_sync(0xffffffff, dA, o);
            sB += __shfl_xor_sync(0xffffffff, sB, o);
            dB += __shfl_xor_sync(0xffffffff, dB, o);
        }
        if (t == 0) {
            if (r0 < NN)     { g_asrc[r0 * HH + h] = sA; g_adst[r0 * HH + h] = dA; }
            if (r0 + 8 < NN) { g_asrc[(r0 + 8) * HH + h] = sB; g_adst[(r0 + 8) * HH + h] = dB; }
        }
    }
}

// ---- fused GAT aggregation + relu + bf16 split (writes next-layer GEMM input)
__global__ void __launch_bounds__(256)
k_gat(const float* __restrict__ bias) {
    __shared__ int   ssrc[8][32];
    __shared__ float sex[8][32][4];
    int tid = threadIdx.x;
    int warp = tid >> 5, lane = tid & 31;
    int n = blockIdx.x * 8 + warp;
    if (n >= NN) return;
    int beg = g_off[n], end = g_off[n + 1];
    float4 ad = *(const float4*)&g_adst[n * HH];

    float acc[8];
#pragma unroll
    for (int q = 0; q < 8; q++) acc[q] = 0.0f;
    float4 den = make_float4(0.f, 0.f, 0.f, 0.f);
    int myc = lane * 8;
    int hme = lane >> 3;
    for (int cb = beg; cb < end; cb += 32) {
        int i = cb + lane;
        int s = 0;
        float4 ex = make_float4(0.f, 0.f, 0.f, 0.f);
        if (i < end) {
            s = g_csr_src[i];
            float4 as = *(const float4*)&g_asrc[s * HH];
            float lx = as.x + ad.x, ly = as.y + ad.y, lz = as.z + ad.z, lw = as.w + ad.w;
            lx = (lx >= 0.f) ? lx : 0.2f * lx;
            ly = (ly >= 0.f) ? ly : 0.2f * ly;
            lz = (lz >= 0.f) ? lz : 0.2f * lz;
            lw = (lw >= 0.f) ? lw : 0.2f * lw;
            ex = make_float4(__expf(lx), __expf(ly), __expf(lz), __expf(lw));
            den.x += ex.x; den.y += ex.y; den.z += ex.z; den.w += ex.w;
        }
        ssrc[warp][lane] = s;
        *(float4*)&sex[warp][lane][0] = ex;
        __syncwarp();
        int cnt = min(32, end - cb);
        int s0 = ssrc[warp][0];
        float e0 = sex[warp][0][hme];
        const float4* p = (const float4*)&g_xs[(size_t)s0 * CC + myc];
        float4 a1 = p[0], a2 = p[1];
        for (int j = 0; j < cnt; j++) {
            float4 b1 = a1, b2 = a2;
            float ev = e0;
            if (j + 1 < cnt) {
                int sn = ssrc[warp][j + 1];
                e0 = sex[warp][j + 1][hme];
                const float4* q = (const float4*)&g_xs[(size_t)sn * CC + myc];
                a1 = q[0]; a2 = q[1];
            }
            acc[0] += ev * b1.x; acc[1] += ev * b1.y;
            acc[2] += ev * b1.z; acc[3] += ev * b1.w;
            acc[4] += ev * b2.x; acc[5] += ev * b2.y;
            acc[6] += ev * b2.z; acc[7] += ev * b2.w;
        }
        __syncwarp();
    }

#pragma unroll
    for (int o = 16; o > 0; o >>= 1) {
        den.x += __shfl_xor_sync(0xffffffff, den.x, o);
        den.y += __shfl_xor_sync(0xffffffff, den.y, o);
        den.z += __shfl_xor_sync(0xffffffff, den.z, o);
        den.w += __shfl_xor_sync(0xffffffff, den.w, o);
    }
    float dh[4] = {den.x, den.y, den.z, den.w};
    float rinv = 1.0f / (dh[hme] + 1e-16f);

    const float4* bp = (const float4*)&bias[myc];
    float4 b1 = bp[0], b2 = bp[1];
    float v[8];
    v[0] = fmaxf(acc[0] * rinv + b1.x, 0.f);
    v[1] = fmaxf(acc[1] * rinv + b1.y, 0.f);
    v[2] = fmaxf(acc[2] * rinv + b1.z, 0.f);
    v[3] = fmaxf(acc[3] * rinv + b1.w, 0.f);
    v[4] = fmaxf(acc[4] * rinv + b2.x, 0.f);
    v[5] = fmaxf(acc[5] * rinv + b2.y, 0.f);
    v[6] = fmaxf(acc[6] * rinv + b2.z, 0.f);
    v[7] = fmaxf(acc[7] * rinv + b2.w, 0.f);
    // bf16 hi/lo split, one uint4 store each
    uint4 uh, ul;
    uh.x = pk2(v[0], v[1]); uh.y = pk2(v[2], v[3]);
    uh.z = pk2(v[4], v[5]); uh.w = pk2(v[6], v[7]);
    float l[8];
#pragma unroll
    for (int q = 0; q < 8; q++) {
        __nv_bfloat16 hbits = __float2bfloat16_rn(v[q]);
        l[q] = v[q] - __bfloat162float(hbits);
    }
    ul.x = pk2(l[0], l[1]); ul.y = pk2(l[2], l[3]);
    ul.z = pk2(l[4], l[5]); ul.w = pk2(l[6], l[7]);
    *(uint4*)&g_xhi[(size_t)n * CC + myc] = uh;
    *(uint4*)&g_xlo[(size_t)n * CC + myc] = ul;
}

// pooling only: read hi+lo, fused segment_max into g at column offset goff
__global__ void k_post(const int* __restrict__ batch, int goff) {
    int c = threadIdx.x;
    int base = blockIdx.x * 32;
    if (base >= NN) return;
    int curb = batch[base];
    float mx = 0.0f;
    int lim = min(32, NN - base);
    for (int i = 0; i < lim; i++) {
        int n = base + i;
        int b = batch[n];
        if (b != curb) {
            atomicMax((int*)&g_g[curb * GCOLS + goff + c], __float_as_int(mx));
            curb = b; mx = 0.0f;
        }
        size_t idx = (size_t)n * CC + c;
        float v = __bfloat162float(g_xhi[idx]) + __bfloat162float(g_xlo[idx]);
        mx = fmaxf(mx, v);
    }
    atomicMax((int*)&g_g[curb * GCOLS + goff + c], __float_as_int(mx));
}

__global__ void k_final(const float* __restrict__ agg_w,
                        const float* __restrict__ agg_b,
                        float* __restrict__ out) {
    __shared__ float sg[GCOLS];
    int b = blockIdx.x;
    int tid = threadIdx.x;
    for (int k = tid; k < GCOLS; k += 256) sg[k] = g_g[b * GCOLS + k];
    __syncthreads();
    float acc = agg_b[tid];
    for (int k = 0; k < GCOLS; k++) acc += sg[k] * agg_w[(size_t)k * BOTN + tid];
    out[b * BOTN + tid] = acc;
}

// ---------------- host ----------------
extern "C" void kernel_launch(void* const* d_in, const int* in_sizes, int n_in,
                              void* d_out, int out_size) {
    const float* sf    = (const float*)d_in[0];
    const int*   ei    = (const int*)d_in[1];
    const int*   batch = (const int*)d_in[2];
    const float* bw    = (const float*)d_in[3];
    const float* bb    = (const float*)d_in[4];
    const float* lin_w[3]   = {(const float*)d_in[5],  (const float*)d_in[9],  (const float*)d_in[13]};
    const float* att_src[3] = {(const float*)d_in[6],  (const float*)d_in[10], (const float*)d_in[14]};
    const float* att_dst[3] = {(const float*)d_in[7],  (const float*)d_in[11], (const float*)d_in[15]};
    const float* bias[3]    = {(const float*)d_in[8],  (const float*)d_in[12], (const float*)d_in[16]};
    const float* agg_w = (const float*)d_in[17];
    const float* agg_b = (const float*)d_in[18];
    float* out = (float*)d_out;

    cudaFuncSetAttribute(k_gemm_mma, cudaFuncAttributeMaxDynamicSharedMemorySize, GEMM_SMEM);

    // CSR build (graph is layer-invariant)
    k_zero_counts<<<(BB * GCOLS + 255) / 256, 256>>>();
    k_hist<<<(E2 + 255) / 256, 256>>>(ei);
    k_scan<<<1, 1024>>>();
    k_scatter<<<(E2 + 255) / 256, 256>>>(ei);

    k_input<<<(NN + 31) / 32, 64>>>(sf, bw, bb, batch);

    for (int L = 0; L < 3; L++) {
        int K = (L == 0) ? FF : CC;
        k_wconv<<<(K * CC + 255) / 256, 256>>>(K, lin_w[L]);
        dim3 gg(2, (NN + 127) / 128);
        k_gemm_mma<<<gg, 256, GEMM_SMEM>>>(L, K, att_src[L], att_dst[L]);
        k_gat<<<(NN + 7) / 8, 256>>>(bias[L]);
        k_post<<<(NN + 31) / 32, 256>>>(batch, FF + L * CC);
    }

    k_final<<<BB, BOTN>>>(agg_w, agg_b, out);
}

// round 13
// speedup vs baseline: 3.0668x; 1.1413x over previous
#include <cuda_runtime.h>
#include <cuda_bf16.h>
#include <math.h>
#include <stdint.h>

// Problem constants (fixed shapes)
#define NN   30000
#define EE   240000
#define E2   (EE + NN)      // 270000 edges incl self-loops
#define BB   64
#define FF   64
#define HH   4
#define CC   256            // H*F
#define GCOLS 832           // F*(1+H*T)
#define BOTN 256

// ---------------- device scratch (no allocations allowed) ----------------
__device__ float g_xs[NN * CC];          // xs = x @ W (fp32, read by gat)
__device__ float g_asrc[NN * HH];
__device__ float g_adst[NN * HH];
__device__ float g_g[BB * GCOLS];
// bf16 hi/lo activation + weight buffers (GEMM operands)
__device__ __align__(16) __nv_bfloat16 g_x0hi[NN * FF];
__device__ __align__(16) __nv_bfloat16 g_x0lo[NN * FF];
__device__ __align__(16) __nv_bfloat16 g_xhi[NN * CC];
__device__ __align__(16) __nv_bfloat16 g_xlo[NN * CC];
__device__ __align__(16) __nv_bfloat16 g_wthi[3 * CC * CC];   // transposed [n][k], per layer
__device__ __align__(16) __nv_bfloat16 g_wtlo[3 * CC * CC];
// CSR (built once per launch)
__device__ int g_deg[NN];
__device__ int g_cursor[NN];
__device__ int g_off[NN + 1];
__device__ int g_csr_src[E2];

// ---------------- helpers ----------------
__device__ __forceinline__ void edge_endpoints(const int* __restrict__ ei,
                                               int e, int& src, int& dst) {
    if (e < EE) { src = ei[e]; dst = ei[EE + e]; }
    else        { src = dst = e - EE; }
}

__device__ __forceinline__ __nv_bfloat16 bf_hi(float a) { return __float2bfloat16_rn(a); }
__device__ __forceinline__ __nv_bfloat16 bf_lo(float a) {
    return __float2bfloat16_rn(a - __bfloat162float(__float2bfloat16_rn(a)));
}
__device__ __forceinline__ uint32_t pk2(float a, float b) {
    __nv_bfloat162 h = __floats2bfloat162_rn(a, b);
    return *(uint32_t*)&h;
}

// m16n8k16 bf16 MMA, fp32 accumulate
__device__ __forceinline__ void mma16816(float* c, const uint32_t* a,
                                         uint32_t b0, uint32_t b1) {
    asm volatile(
        "mma.sync.aligned.m16n8k16.row.col.f32.bf16.bf16.f32 "
        "{%0,%1,%2,%3}, {%4,%5,%6,%7}, {%8,%9}, {%0,%1,%2,%3};"
        : "+f"(c[0]), "+f"(c[1]), "+f"(c[2]), "+f"(c[3])
        : "r"(a[0]), "r"(a[1]), "r"(a[2]), "r"(a[3]), "r"(b0), "r"(b1));
}

__device__ __forceinline__ void cpa16(uint32_t dst, const void* src, bool pred) {
    asm volatile("cp.async.cg.shared.global [%0], [%1], 16, %2;"
                 :: "r"(dst), "l"(src), "r"(pred ? 16 : 0));
}
#define CPA_COMMIT() asm volatile("cp.async.commit_group;" ::: "memory")
#define CPA_WAIT1()  asm volatile("cp.async.wait_group 1;" ::: "memory")
#define CPA_WAIT0()  asm volatile("cp.async.wait_group 0;" ::: "memory")

// ---------------- CSR build (once per launch) ----------------
__global__ void k_zero_counts() {
    int i = blockIdx.x * blockDim.x + threadIdx.x;
    if (i < NN) { g_deg[i] = 0; g_cursor[i] = 0; }
    if (i < BB * GCOLS) g_g[i] = 0.0f;
}

__global__ void k_hist(const int* __restrict__ ei) {
    int e = blockIdx.x * blockDim.x + threadIdx.x;
    if (e >= E2) return;
    int dst = (e < EE) ? ei[EE + e] : e - EE;
    atomicAdd(&g_deg[dst], 1);
}

__global__ void k_scan() {
    __shared__ int sp[1024];
    int tid = threadIdx.x;
    const int CHK = (NN + 1023) / 1024;
    int base = tid * CHK;
    int s = 0;
    for (int i = 0; i < CHK; i++) {
        int idx = base + i;
        if (idx < NN) s += g_deg[idx];
    }
    sp[tid] = s;
    __syncthreads();
    for (int o = 1; o < 1024; o <<= 1) {
        int u = (tid >= o) ? sp[tid - o] : 0;
        __syncthreads();
        sp[tid] += u;
        __syncthreads();
    }
    int run = sp[tid] - s;
    for (int i = 0; i < CHK; i++) {
        int idx = base + i;
        if (idx < NN) { g_off[idx] = run; run += g_deg[idx]; }
    }
    if (tid == 1023) g_off[NN] = sp[1023];
}

__global__ void k_scatter(const int* __restrict__ ei) {
    int e = blockIdx.x * blockDim.x + threadIdx.x;
    if (e >= E2) return;
    int src, dst;
    edge_endpoints(ei, e, src, dst);
    int pos = atomicAdd(&g_cursor[dst], 1);
    g_csr_src[g_off[dst] + pos] = src;
}

// ---------------- weight transpose + bf16 split (all layers, once) ----------------
__global__ void k_wconv_all(const float* __restrict__ W0,
                            const float* __restrict__ W1,
                            const float* __restrict__ W2) {
    int idx = blockIdx.x * blockDim.x + threadIdx.x;
    if (idx >= 3 * CC * CC) return;
    int L = idx >> 16;
    int r = idx & 65535;
    int k = r >> 8, n = r & 255;
    int K = (L == 0) ? FF : CC;
    if (k >= K) return;
    const float* W = (L == 0) ? W0 : ((L == 1) ? W1 : W2);
    float v = W[(size_t)k * CC + n];
    g_wthi[L * CC * CC + n * K + k] = bf_hi(v);
    g_wtlo[L * CC * CC + n * K + k] = bf_lo(v);
}

// ---------------- input layer: 8 nodes per 64-thread block ----------------
__global__ void k_input(const float* __restrict__ sf,
                        const float* __restrict__ bw,
                        const float* __restrict__ bb,
                        const int* __restrict__ batch) {
    int c = threadIdx.x;            // 0..63
    int base = blockIdx.x * 8;
    float w0 = bw[0 * FF + c], w1 = bw[1 * FF + c], w2 = bw[2 * FF + c],
          w3 = bw[3 * FF + c], w4 = bw[4 * FF + c];
    float bias = bb[c];
    int curb = batch[base];
    float mx = 0.0f;
#pragma unroll
    for (int i = 0; i < 8; i++) {
        int n = base + i;
        int b = batch[n];
        if (b != curb) {
            atomicMax((int*)&g_g[curb * GCOLS + c], __float_as_int(mx));
            curb = b; mx = 0.0f;
        }
        const float* s = &sf[n * 5];
        float v = bias + s[0]*w0 + s[1]*w1 + s[2]*w2 + s[3]*w3 + s[4]*w4;
        v = fmaxf(v, 0.0f);
        g_x0hi[n * FF + c] = bf_hi(v);
        g_x0lo[n * FF + c] = bf_lo(v);
        mx = fmaxf(mx, v);
    }
    atomicMax((int*)&g_g[curb * GCOLS + c], __float_as_int(mx));
}

// ---- split-bf16 tensor-core GEMM + fused attention coefficients.
// Double-buffered via cp.async. g_xs[m,:] = A[m,:K] @ W[:K,:256]
#define APAD 40
#define ARR_B (128 * APAD * 2)      // bytes per operand array (10240)
#define STG_B (4 * ARR_B)           // bytes per stage (40960)
#define GEMM_SMEM (2 * STG_B)       // 81920

__global__ void __launch_bounds__(256, 2)
k_gemm_mma(int layer, int K,
           const float* __restrict__ att_src, const float* __restrict__ att_dst) {
    const __nv_bfloat16* Ahg = (layer == 0) ? g_x0hi : g_xhi;
    const __nv_bfloat16* Alg = (layer == 0) ? g_x0lo : g_xlo;
    const __nv_bfloat16* Whg = g_wthi + layer * CC * CC;
    const __nv_bfloat16* Wlg = g_wtlo + layer * CC * CC;
    extern __shared__ char smem[];

    int tid = threadIdx.x;
    int warp = tid >> 5, lane = tid & 31;
    int wm = warp & 3;
    int wn = warp >> 2;
    int g = lane >> 2, t = lane & 3;
    int bm = blockIdx.y * 128;
    int bn = blockIdx.x * 128;

    uint32_t sbase = (uint32_t)__cvta_generic_to_shared(smem);

    auto fill = [&](int s, int k0) {
        uint32_t st = sbase + s * STG_B;
#pragma unroll
        for (int i = tid; i < 512; i += 256) {
            int r = i >> 2;
            int kq = (i & 3) << 3;
            int gr = bm + r;
            bool p = gr < NN;
            size_t oa = (size_t)(p ? gr : 0) * K + k0 + kq;
            uint32_t d = (r * APAD + kq) * 2;
            cpa16(st + 0 * ARR_B + d, &Ahg[oa], p);
            cpa16(st + 1 * ARR_B + d, &Alg[oa], p);
            size_t ob = (size_t)(bn + r) * K + k0 + kq;
            cpa16(st + 2 * ARR_B + d, &Whg[ob], true);
            cpa16(st + 3 * ARR_B + d, &Wlg[ob], true);
        }
        CPA_COMMIT();
    };

    float acc[2][8][4];
#pragma unroll
    for (int i = 0; i < 2; i++)
#pragma unroll
        for (int j = 0; j < 8; j++)
#pragma unroll
            for (int q = 0; q < 4; q++) acc[i][j][q] = 0.0f;

    int nch = K >> 5;
    fill(0, 0);
    for (int ch = 0; ch < nch; ch++) {
        if (ch + 1 < nch) { fill((ch + 1) & 1, (ch + 1) << 5); CPA_WAIT1(); }
        else              { CPA_WAIT0(); }
        __syncthreads();

        const __nv_bfloat16* Ah = (const __nv_bfloat16*)(smem + (ch & 1) * STG_B);
        const __nv_bfloat16* Al = (const __nv_bfloat16*)(smem + (ch & 1) * STG_B + ARR_B);
        const __nv_bfloat16* Bh = (const __nv_bfloat16*)(smem + (ch & 1) * STG_B + 2 * ARR_B);
        const __nv_bfloat16* Bl = (const __nv_bfloat16*)(smem + (ch & 1) * STG_B + 3 * ARR_B);

#pragma unroll
        for (int ks = 0; ks < 32; ks += 16) {
            uint32_t ah[2][4], al[2][4];
#pragma unroll
            for (int mt = 0; mt < 2; mt++) {
                int r = wm * 32 + mt * 16;
                ah[mt][0] = *(uint32_t*)&Ah[(r + g) * APAD + ks + 2 * t];
                ah[mt][1] = *(uint32_t*)&Ah[(r + g + 8) * APAD + ks + 2 * t];
                ah[mt][2] = *(uint32_t*)&Ah[(r + g) * APAD + ks + 8 + 2 * t];
                ah[mt][3] = *(uint32_t*)&Ah[(r + g + 8) * APAD + ks + 8 + 2 * t];
                al[mt][0] = *(uint32_t*)&Al[(r + g) * APAD + ks + 2 * t];
                al[mt][1] = *(uint32_t*)&Al[(r + g + 8) * APAD + ks + 2 * t];
                al[mt][2] = *(uint32_t*)&Al[(r + g) * APAD + ks + 8 + 2 * t];
                al[mt][3] = *(uint32_t*)&Al[(r + g + 8) * APAD + ks + 8 + 2 * t];
            }
#pragma unroll
            for (int nt = 0; nt < 8; nt++) {
                int c = wn * 64 + nt * 8 + g;
                uint32_t bh0 = *(uint32_t*)&Bh[c * APAD + ks + 2 * t];
                uint32_t bh1 = *(uint32_t*)&Bh[c * APAD + ks + 8 + 2 * t];
                uint32_t bl0 = *(uint32_t*)&Bl[c * APAD + ks + 2 * t];
                uint32_t bl1 = *(uint32_t*)&Bl[c * APAD + ks + 8 + 2 * t];
#pragma unroll
                for (int mt = 0; mt < 2; mt++) {
                    mma16816(acc[mt][nt], ah[mt], bh0, bh1);
                    mma16816(acc[mt][nt], ah[mt], bl0, bl1);
                    mma16816(acc[mt][nt], al[mt], bh0, bh1);
                }
            }
        }
        __syncthreads();
    }

    // store C + fused attention dots
    int h = (bn >> 6) + wn;
#pragma unroll
    for (int mt = 0; mt < 2; mt++) {
        int r0 = bm + wm * 32 + mt * 16 + g;
        float sA = 0.f, dA = 0.f, sB = 0.f, dB = 0.f;
#pragma unroll
        for (int nt = 0; nt < 8; nt++) {
            int c = bn + wn * 64 + nt * 8 + 2 * t;
            float w0s = att_src[c], w1s = att_src[c + 1];
            float w0d = att_dst[c], w1d = att_dst[c + 1];
            sA += acc[mt][nt][0] * w0s + acc[mt][nt][1] * w1s;
            dA += acc[mt][nt][0] * w0d + acc[mt][nt][1] * w1d;
            sB += acc[mt][nt][2] * w0s + acc[mt][nt][3] * w1s;
            dB += acc[mt][nt][2] * w0d + acc[mt][nt][3] * w1d;
            if (r0 < NN)
                *(float2*)&g_xs[(size_t)r0 * CC + c] =
                    make_float2(acc[mt][nt][0], acc[mt][nt][1]);
            if (r0 + 8 < NN)
                *(float2*)&g_xs[(size_t)(r0 + 8) * CC + c] =
                    make_float2(acc[mt][nt][2], acc[mt][nt][3]);
        }
#pragma unroll
        for (int o = 1; o < 4; o <<= 1) {
            sA += __shfl_xor_sync(0xffffffff, sA, o);
            dA += __shfl_xor_sync(0xffffffff, dA, o);
            sB += __shfl_xor_sync(0xffffffff, sB, o);
            dB += __shfl_xor_sync(0xffffffff, dB, o);
        }
        if (t == 0) {
            if (r0 < NN)     { g_asrc[r0 * HH + h] = sA; g_adst[r0 * HH + h] = dA; }
            if (r0 + 8 < NN) { g_asrc[(r0 + 8) * HH + h] = sB; g_adst[(r0 + 8) * HH + h] = dB; }
        }
    }
}

// ---- fused GAT aggregation + relu + bf16 split + batch max-pool.
// Block = 8 consecutive nodes (one warp each); 3750 blocks exactly cover NN.
__global__ void __launch_bounds__(256)
k_gat(const float* __restrict__ bias, const int* __restrict__ batch, int goff) {
    __shared__ int   ssrc[8][32];
    __shared__ float sex[8][32][4];
    __shared__ float sv[8][CC];
    int tid = threadIdx.x;
    int warp = tid >> 5, lane = tid & 31;
    int n = blockIdx.x * 8 + warp;          // always < NN (3750*8 == NN)
    int beg = g_off[n], end = g_off[n + 1];
    float4 ad = *(const float4*)&g_adst[n * HH];

    float acc[8];
#pragma unroll
    for (int q = 0; q < 8; q++) acc[q] = 0.0f;
    float4 den = make_float4(0.f, 0.f, 0.f, 0.f);
    int myc = lane * 8;
    int hme = lane >> 3;
    for (int cb = beg; cb < end; cb += 32) {
        int i = cb + lane;
        int s = 0;
        float4 ex = make_float4(0.f, 0.f, 0.f, 0.f);
        if (i < end) {
            s = g_csr_src[i];
            float4 as = *(const float4*)&g_asrc[s * HH];
            float lx = as.x + ad.x, ly = as.y + ad.y, lz = as.z + ad.z, lw = as.w + ad.w;
            lx = (lx >= 0.f) ? lx : 0.2f * lx;
            ly = (ly >= 0.f) ? ly : 0.2f * ly;
            lz = (lz >= 0.f) ? lz : 0.2f * lz;
            lw = (lw >= 0.f) ? lw : 0.2f * lw;
            ex = make_float4(__expf(lx), __expf(ly), __expf(lz), __expf(lw));
            den.x += ex.x; den.y += ex.y; den.z += ex.z; den.w += ex.w;
        }
        ssrc[warp][lane] = s;
        *(float4*)&sex[warp][lane][0] = ex;
        __syncwarp();
        int cnt = min(32, end - cb);
        // depth-2 ping-pong prefetch
        float4 p1[2], p2[2];
        float pe[2];
#define LOADJ(slot, j) do {                                            \
            int _s = ssrc[warp][j];                                    \
            pe[slot] = sex[warp][j][hme];                              \
            const float4* _q = (const float4*)&g_xs[(size_t)_s * CC + myc]; \
            p1[slot] = _q[0]; p2[slot] = _q[1];                        \
        } while (0)
        LOADJ(0, 0);
        if (cnt > 1) LOADJ(1, 1);
        for (int j = 0; j < cnt; j++) {
            float4 b1 = p1[j & 1], b2 = p2[j & 1];
            float ev = pe[j & 1];
            if (j + 2 < cnt) LOADJ(j & 1, j + 2);
            acc[0] += ev * b1.x; acc[1] += ev * b1.y;
            acc[2] += ev * b1.z; acc[3] += ev * b1.w;
            acc[4] += ev * b2.x; acc[5] += ev * b2.y;
            acc[6] += ev * b2.z; acc[7] += ev * b2.w;
        }
#undef LOADJ
        __syncwarp();
    }

#pragma unroll
    for (int o = 16; o > 0; o >>= 1) {
        den.x += __shfl_xor_sync(0xffffffff, den.x, o);
        den.y += __shfl_xor_sync(0xffffffff, den.y, o);
        den.z += __shfl_xor_sync(0xffffffff, den.z, o);
        den.w += __shfl_xor_sync(0xffffffff, den.w, o);
    }
    float dh[4] = {den.x, den.y, den.z, den.w};
    float rinv = 1.0f / (dh[hme] + 1e-16f);

    const float4* bp = (const float4*)&bias[myc];
    float4 b1 = bp[0], b2 = bp[1];
    float v[8];
    v[0] = fmaxf(acc[0] * rinv + b1.x, 0.f);
    v[1] = fmaxf(acc[1] * rinv + b1.y, 0.f);
    v[2] = fmaxf(acc[2] * rinv + b1.z, 0.f);
    v[3] = fmaxf(acc[3] * rinv + b1.w, 0.f);
    v[4] = fmaxf(acc[4] * rinv + b2.x, 0.f);
    v[5] = fmaxf(acc[5] * rinv + b2.y, 0.f);
    v[6] = fmaxf(acc[6] * rinv + b2.z, 0.f);
    v[7] = fmaxf(acc[7] * rinv + b2.w, 0.f);
    // stash for pooling
    *(float4*)&sv[warp][myc] = make_float4(v[0], v[1], v[2], v[3]);
    *(float4*)&sv[warp][myc + 4] = make_float4(v[4], v[5], v[6], v[7]);
    // bf16 hi/lo split for next GEMM
    uint4 uh, ul;
    uh.x = pk2(v[0], v[1]); uh.y = pk2(v[2], v[3]);
    uh.z = pk2(v[4], v[5]); uh.w = pk2(v[6], v[7]);
    float l[8];
#pragma unroll
    for (int q = 0; q < 8; q++) {
        __nv_bfloat16 hbits = __float2bfloat16_rn(v[q]);
        l[q] = v[q] - __bfloat162float(hbits);
    }
    ul.x = pk2(l[0], l[1]); ul.y = pk2(l[2], l[3]);
    ul.z = pk2(l[4], l[5]); ul.w = pk2(l[6], l[7]);
    *(uint4*)&g_xhi[(size_t)n * CC + myc] = uh;
    *(uint4*)&g_xlo[(size_t)n * CC + myc] = ul;

    // fused batch max-pool: thread tid owns channel tid across block's 8 nodes
    __syncthreads();
    int c = tid;
    int nbase = blockIdx.x * 8;
    int curb = batch[nbase];
    float mx = sv[0][c];
#pragma unroll
    for (int w = 1; w < 8; w++) {
        int b = batch[nbase + w];
        if (b != curb) {
            atomicMax((int*)&g_g[curb * GCOLS + goff + c], __float_as_int(mx));
            curb = b; mx = 0.0f;
        }
        mx = fmaxf(mx, sv[w][c]);
    }
    atomicMax((int*)&g_g[curb * GCOLS + goff + c], __float_as_int(mx));
}

__global__ void k_final(const float* __restrict__ agg_w,
                        const float* __restrict__ agg_b,
                        float* __restrict__ out) {
    __shared__ float sg[GCOLS];
    int b = blockIdx.x;
    int tid = threadIdx.x;
    for (int k = tid; k < GCOLS; k += 256) sg[k] = g_g[b * GCOLS + k];
    __syncthreads();
    float acc = agg_b[tid];
    for (int k = 0; k < GCOLS; k++) acc += sg[k] * agg_w[(size_t)k * BOTN + tid];
    out[b * BOTN + tid] = acc;
}

// ---------------- host ----------------
extern "C" void kernel_launch(void* const* d_in, const int* in_sizes, int n_in,
                              void* d_out, int out_size) {
    const float* sf    = (const float*)d_in[0];
    const int*   ei    = (const int*)d_in[1];
    const int*   batch = (const int*)d_in[2];
    const float* bw    = (const float*)d_in[3];
    const float* bb    = (const float*)d_in[4];
    const float* lin_w[3]   = {(const float*)d_in[5],  (const float*)d_in[9],  (const float*)d_in[13]};
    const float* att_src[3] = {(const float*)d_in[6],  (const float*)d_in[10], (const float*)d_in[14]};
    const float* att_dst[3] = {(const float*)d_in[7],  (const float*)d_in[11], (const float*)d_in[15]};
    const float* bias[3]    = {(const float*)d_in[8],  (const float*)d_in[12], (const float*)d_in[16]};
    const float* agg_w = (const float*)d_in[17];
    const float* agg_b = (const float*)d_in[18];
    float* out = (float*)d_out;

    cudaFuncSetAttribute(k_gemm_mma, cudaFuncAttributeMaxDynamicSharedMemorySize, GEMM_SMEM);

    // CSR build (graph is layer-invariant)
    k_zero_counts<<<(BB * GCOLS + 255) / 256, 256>>>();
    k_hist<<<(E2 + 255) / 256, 256>>>(ei);
    k_scan<<<1, 1024>>>();
    k_scatter<<<(E2 + 255) / 256, 256>>>(ei);

    k_wconv_all<<<(3 * CC * CC + 255) / 256, 256>>>(lin_w[0], lin_w[1], lin_w[2]);
    k_input<<<NN / 8, 64>>>(sf, bw, bb, batch);

    for (int L = 0; L < 3; L++) {
        int K = (L == 0) ? FF : CC;
        dim3 gg(2, (NN + 127) / 128);
        k_gemm_mma<<<gg, 256, GEMM_SMEM>>>(L, K, att_src[L], att_dst[L]);
        k_gat<<<NN / 8, 256>>>(bias[L], batch, FF + L * CC);
    }

    k_final<<<BB, BOTN>>>(agg_w, agg_b, out);
}

// round 14
// speedup vs baseline: 3.2906x; 1.0730x over previous
#include <cuda_runtime.h>
#include <cuda_fp16.h>
#include <math.h>
#include <stdint.h>

// Problem constants (fixed shapes)
#define NN   30000
#define EE   240000
#define E2   (EE + NN)      // 270000 edges incl self-loops
#define BB   64
#define FF   64
#define HH   4
#define CC   256            // H*F
#define GCOLS 832           // F*(1+H*T)
#define BOTN 256

// ---------------- device scratch (no allocations allowed) ----------------
__device__ float g_xs[NN * CC];          // xs = x @ W (fp32, read by gat)
__device__ float g_asrc[NN * HH];
__device__ float g_adst[NN * HH];
__device__ float g_g[BB * GCOLS];
// fp16 hi/lo activation buffers + fp16 weights (GEMM operands)
__device__ __align__(16) __half g_x0hi[NN * FF];
__device__ __align__(16) __half g_x0lo[NN * FF];
__device__ __align__(16) __half g_xhi[NN * CC];
__device__ __align__(16) __half g_xlo[NN * CC];
__device__ __align__(16) __half g_wt[3 * CC * CC];   // transposed [n][k], per layer
// CSR (built once per launch)
__device__ int g_deg[NN];
__device__ int g_cursor[NN];
__device__ int g_off[NN + 1];
__device__ int g_csr_src[E2];

// ---------------- helpers ----------------
__device__ __forceinline__ void edge_endpoints(const int* __restrict__ ei,
                                               int e, int& src, int& dst) {
    if (e < EE) { src = ei[e]; dst = ei[EE + e]; }
    else        { src = dst = e - EE; }
}

__device__ __forceinline__ uint32_t pk2h(float a, float b) {
    __half2 h = __floats2half2_rn(a, b);
    return *(uint32_t*)&h;
}

// m16n8k16 fp16 MMA, fp32 accumulate
__device__ __forceinline__ void mma16816(float* c, const uint32_t* a,
                                         uint32_t b0, uint32_t b1) {
    asm volatile(
        "mma.sync.aligned.m16n8k16.row.col.f32.f16.f16.f32 "
        "{%0,%1,%2,%3}, {%4,%5,%6,%7}, {%8,%9}, {%0,%1,%2,%3};"
        : "+f"(c[0]), "+f"(c[1]), "+f"(c[2]), "+f"(c[3])
        : "r"(a[0]), "r"(a[1]), "r"(a[2]), "r"(a[3]), "r"(b0), "r"(b1));
}

__device__ __forceinline__ void cpa16(uint32_t dst, const void* src, bool pred) {
    asm volatile("cp.async.cg.shared.global [%0], [%1], 16, %2;"
                 :: "r"(dst), "l"(src), "r"(pred ? 16 : 0));
}
#define CPA_COMMIT() asm volatile("cp.async.commit_group;" ::: "memory")
#define CPA_WAIT2()  asm volatile("cp.async.wait_group 2;" ::: "memory")
#define CPA_WAIT1()  asm volatile("cp.async.wait_group 1;" ::: "memory")
#define CPA_WAIT0()  asm volatile("cp.async.wait_group 0;" ::: "memory")

// ---------------- CSR build (once per launch) ----------------
__global__ void k_zero_counts() {
    int i = blockIdx.x * blockDim.x + threadIdx.x;
    if (i < NN) { g_deg[i] = 0; g_cursor[i] = 0; }
    if (i < BB * GCOLS) g_g[i] = 0.0f;
}

__global__ void k_hist(const int* __restrict__ ei) {
    int e = blockIdx.x * blockDim.x + threadIdx.x;
    if (e >= E2) return;
    int dst = (e < EE) ? ei[EE + e] : e - EE;
    atomicAdd(&g_deg[dst], 1);
}

__global__ void k_scan() {
    __shared__ int sp[1024];
    int tid = threadIdx.x;
    const int CHK = (NN + 1023) / 1024;
    int base = tid * CHK;
    int s = 0;
    for (int i = 0; i < CHK; i++) {
        int idx = base + i;
        if (idx < NN) s += g_deg[idx];
    }
    sp[tid] = s;
    __syncthreads();
    for (int o = 1; o < 1024; o <<= 1) {
        int u = (tid >= o) ? sp[tid - o] : 0;
        __syncthreads();
        sp[tid] += u;
        __syncthreads();
    }
    int run = sp[tid] - s;
    for (int i = 0; i < CHK; i++) {
        int idx = base + i;
        if (idx < NN) { g_off[idx] = run; run += g_deg[idx]; }
    }
    if (tid == 1023) g_off[NN] = sp[1023];
}

__global__ void k_scatter(const int* __restrict__ ei) {
    int e = blockIdx.x * blockDim.x + threadIdx.x;
    if (e >= E2) return;
    int src, dst;
    edge_endpoints(ei, e, src, dst);
    int pos = atomicAdd(&g_cursor[dst], 1);
    g_csr_src[g_off[dst] + pos] = src;
}

// ---------------- weight transpose + fp16 (all layers, once) ----------------
__global__ void k_wconv_all(const float* __restrict__ W0,
                            const float* __restrict__ W1,
                            const float* __restrict__ W2) {
    int idx = blockIdx.x * blockDim.x + threadIdx.x;
    if (idx >= 3 * CC * CC) return;
    int L = idx >> 16;
    int r = idx & 65535;
    int k = r >> 8, n = r & 255;
    int K = (L == 0) ? FF : CC;
    if (k >= K) return;
    const float* W = (L == 0) ? W0 : ((L == 1) ? W1 : W2);
    g_wt[L * CC * CC + n * K + k] = __float2half_rn(W[(size_t)k * CC + n]);
}

// ---------------- input layer: 8 nodes per 64-thread block ----------------
__global__ void k_input(const float* __restrict__ sf,
                        const float* __restrict__ bw,
                        const float* __restrict__ bb,
                        const int* __restrict__ batch) {
    int c = threadIdx.x;            // 0..63
    int base = blockIdx.x * 8;
    float w0 = bw[0 * FF + c], w1 = bw[1 * FF + c], w2 = bw[2 * FF + c],
          w3 = bw[3 * FF + c], w4 = bw[4 * FF + c];
    float bias = bb[c];
    int curb = batch[base];
    float mx = 0.0f;
#pragma unroll
    for (int i = 0; i < 8; i++) {
        int n = base + i;
        int b = batch[n];
        if (b != curb) {
            atomicMax((int*)&g_g[curb * GCOLS + c], __float_as_int(mx));
            curb = b; mx = 0.0f;
        }
        const float* s = &sf[n * 5];
        float v = bias + s[0]*w0 + s[1]*w1 + s[2]*w2 + s[3]*w3 + s[4]*w4;
        v = fmaxf(v, 0.0f);
        __half h = __float2half_rn(v);
        g_x0hi[n * FF + c] = h;
        g_x0lo[n * FF + c] = __float2half_rn(v - __half2float(h));
        mx = fmaxf(mx, v);
    }
    atomicMax((int*)&g_g[curb * GCOLS + c], __float_as_int(mx));
}

// ---- fp16 2-product tensor-core GEMM + fused attention coefficients.
// 3-stage cp.async pipeline. g_xs[m,:] = A[m,:K] @ W[:K,:256]
#define APAD 40
#define ARR_B (128 * APAD * 2)      // bytes per operand array (10240)
#define STG_B (3 * ARR_B)           // bytes per stage (30720)
#define NSTG  3
#define GEMM_SMEM (NSTG * STG_B)    // 92160

__global__ void __launch_bounds__(256, 2)
k_gemm_mma(int layer, int K,
           const float* __restrict__ att_src, const float* __restrict__ att_dst) {
    const __half* Ahg = (layer == 0) ? g_x0hi : g_xhi;
    const __half* Alg = (layer == 0) ? g_x0lo : g_xlo;
    const __half* Whg = g_wt + layer * CC * CC;
    extern __shared__ char smem[];

    int tid = threadIdx.x;
    int warp = tid >> 5, lane = tid & 31;
    int wm = warp & 3;
    int wn = warp >> 2;
    int g = lane >> 2, t = lane & 3;
    int bm = blockIdx.y * 128;
    int bn = blockIdx.x * 128;

    uint32_t sbase = (uint32_t)__cvta_generic_to_shared(smem);

    auto fill = [&](int s, int k0) {
        uint32_t st = sbase + s * STG_B;
#pragma unroll
        for (int i = tid; i < 512; i += 256) {
            int r = i >> 2;
            int kq = (i & 3) << 3;
            int gr = bm + r;
            bool p = gr < NN;
            size_t oa = (size_t)(p ? gr : 0) * K + k0 + kq;
            uint32_t d = (r * APAD + kq) * 2;
            cpa16(st + 0 * ARR_B + d, &Ahg[oa], p);
            cpa16(st + 1 * ARR_B + d, &Alg[oa], p);
            size_t ob = (size_t)(bn + r) * K + k0 + kq;
            cpa16(st + 2 * ARR_B + d, &Whg[ob], true);
        }
        CPA_COMMIT();
    };

    float acc[2][8][4];
#pragma unroll
    for (int i = 0; i < 2; i++)
#pragma unroll
        for (int j = 0; j < 8; j++)
#pragma unroll
            for (int q = 0; q < 4; q++) acc[i][j][q] = 0.0f;

    int nch = K >> 5;
    fill(0, 0);
    if (nch > 1) fill(1, 32);
    for (int ch = 0; ch < nch; ch++) {
        if (ch + 2 < nch) { fill((ch + 2) % NSTG, (ch + 2) << 5); CPA_WAIT2(); }
        else if (ch + 1 < nch) { CPA_WAIT1(); }
        else { CPA_WAIT0(); }
        __syncthreads();

        int st = ch % NSTG;
        const __half* Ah = (const __half*)(smem + st * STG_B);
        const __half* Al = (const __half*)(smem + st * STG_B + ARR_B);
        const __half* Bh = (const __half*)(smem + st * STG_B + 2 * ARR_B);

#pragma unroll
        for (int ks = 0; ks < 32; ks += 16) {
            uint32_t ah[2][4], al[2][4];
#pragma unroll
            for (int mt = 0; mt < 2; mt++) {
                int r = wm * 32 + mt * 16;
                ah[mt][0] = *(uint32_t*)&Ah[(r + g) * APAD + ks + 2 * t];
                ah[mt][1] = *(uint32_t*)&Ah[(r + g + 8) * APAD + ks + 2 * t];
                ah[mt][2] = *(uint32_t*)&Ah[(r + g) * APAD + ks + 8 + 2 * t];
                ah[mt][3] = *(uint32_t*)&Ah[(r + g + 8) * APAD + ks + 8 + 2 * t];
                al[mt][0] = *(uint32_t*)&Al[(r + g) * APAD + ks + 2 * t];
                al[mt][1] = *(uint32_t*)&Al[(r + g + 8) * APAD + ks + 2 * t];
                al[mt][2] = *(uint32_t*)&Al[(r + g) * APAD + ks + 8 + 2 * t];
                al[mt][3] = *(uint32_t*)&Al[(r + g + 8) * APAD + ks + 8 + 2 * t];
            }
#pragma unroll
            for (int nt = 0; nt < 8; nt++) {
                int c = wn * 64 + nt * 8 + g;
                uint32_t b0 = *(uint32_t*)&Bh[c * APAD + ks + 2 * t];
                uint32_t b1 = *(uint32_t*)&Bh[c * APAD + ks + 8 + 2 * t];
#pragma unroll
                for (int mt = 0; mt < 2; mt++) {
                    mma16816(acc[mt][nt], ah[mt], b0, b1);
                    mma16816(acc[mt][nt], al[mt], b0, b1);
                }
            }
        }
        __syncthreads();
    }

    // store C + fused attention dots
    int h = (bn >> 6) + wn;
#pragma unroll
    for (int mt = 0; mt < 2; mt++) {
        int r0 = bm + wm * 32 + mt * 16 + g;
        float sA = 0.f, dA = 0.f, sB = 0.f, dB = 0.f;
#pragma unroll
        for (int nt = 0; nt < 8; nt++) {
            int c = bn + wn * 64 + nt * 8 + 2 * t;
            float w0s = att_src[c], w1s = att_src[c + 1];
            float w0d = att_dst[c], w1d = att_dst[c + 1];
            sA += acc[mt][nt][0] * w0s + acc[mt][nt][1] * w1s;
            dA += acc[mt][nt][0] * w0d + acc[mt][nt][1] * w1d;
            sB += acc[mt][nt][2] * w0s + acc[mt][nt][3] * w1s;
            dB += acc[mt][nt][2] * w0d + acc[mt][nt][3] * w1d;
            if (r0 < NN)
                *(float2*)&g_xs[(size_t)r0 * CC + c] =
                    make_float2(acc[mt][nt][0], acc[mt][nt][1]);
            if (r0 + 8 < NN)
                *(float2*)&g_xs[(size_t)(r0 + 8) * CC + c] =
                    make_float2(acc[mt][nt][2], acc[mt][nt][3]);
        }
#pragma unroll
        for (int o = 1; o < 4; o <<= 1) {
            sA += __shfl_xor_sync(0xffffffff, sA, o);
            dA += __shfl_xor_sync(0xffffffff, dA, o);
            sB += __shfl_xor_sync(0xffffffff, sB, o);
            dB += __shfl_xor_sync(0xffffffff, dB, o);
        }
        if (t == 0) {
            if (r0 < NN)     { g_asrc[r0 * HH + h] = sA; g_adst[r0 * HH + h] = dA; }
            if (r0 + 8 < NN) { g_asrc[(r0 + 8) * HH + h] = sB; g_adst[(r0 + 8) * HH + h] = dB; }
        }
    }
}

// ---- fused GAT aggregation + relu + fp16 split + batch max-pool.
// Block = 8 consecutive nodes (one warp each); 3750 blocks exactly cover NN.
__global__ void __launch_bounds__(256)
k_gat(const float* __restrict__ bias, const int* __restrict__ batch, int goff) {
    __shared__ int   ssrc[8][32];
    __shared__ float sex[8][32][4];
    __shared__ float sv[8][CC];
    int tid = threadIdx.x;
    int warp = tid >> 5, lane = tid & 31;
    int n = blockIdx.x * 8 + warp;          // always < NN (3750*8 == NN)
    int beg = g_off[n], end = g_off[n + 1];
    float4 ad = *(const float4*)&g_adst[n * HH];

    float acc[8];
#pragma unroll
    for (int q = 0; q < 8; q++) acc[q] = 0.0f;
    float4 den = make_float4(0.f, 0.f, 0.f, 0.f);
    int myc = lane * 8;
    int hme = lane >> 3;
    for (int cb = beg; cb < end; cb += 32) {
        int i = cb + lane;
        int s = 0;
        float4 ex = make_float4(0.f, 0.f, 0.f, 0.f);
        if (i < end) {
            s = g_csr_src[i];
            float4 as = *(const float4*)&g_asrc[s * HH];
            float lx = as.x + ad.x, ly = as.y + ad.y, lz = as.z + ad.z, lw = as.w + ad.w;
            lx = (lx >= 0.f) ? lx : 0.2f * lx;
            ly = (ly >= 0.f) ? ly : 0.2f * ly;
            lz = (lz >= 0.f) ? lz : 0.2f * lz;
            lw = (lw >= 0.f) ? lw : 0.2f * lw;
            ex = make_float4(__expf(lx), __expf(ly), __expf(lz), __expf(lw));
            den.x += ex.x; den.y += ex.y; den.z += ex.z; den.w += ex.w;
        }
        ssrc[warp][lane] = s;
        *(float4*)&sex[warp][lane][0] = ex;
        __syncwarp();
        int cnt = min(32, end - cb);
        // depth-2 ping-pong prefetch
        float4 p1[2], p2[2];
        float pe[2];
#define LOADJ(slot, j) do {                                            \
            int _s = ssrc[warp][j];                                    \
            pe[slot] = sex[warp][j][hme];                              \
            const float4* _q = (const float4*)&g_xs[(size_t)_s * CC + myc]; \
            p1[slot] = _q[0]; p2[slot] = _q[1];                        \
        } while (0)
        LOADJ(0, 0);
        if (cnt > 1) LOADJ(1, 1);
        for (int j = 0; j < cnt; j++) {
            float4 b1 = p1[j & 1], b2 = p2[j & 1];
            float ev = pe[j & 1];
            if (j + 2 < cnt) LOADJ(j & 1, j + 2);
            acc[0] += ev * b1.x; acc[1] += ev * b1.y;
            acc[2] += ev * b1.z; acc[3] += ev * b1.w;
            acc[4] += ev * b2.x; acc[5] += ev * b2.y;
            acc[6] += ev * b2.z; acc[7] += ev * b2.w;
        }
#undef LOADJ
        __syncwarp();
    }

#pragma unroll
    for (int o = 16; o > 0; o >>= 1) {
        den.x += __shfl_xor_sync(0xffffffff, den.x, o);
        den.y += __shfl_xor_sync(0xffffffff, den.y, o);
        den.z += __shfl_xor_sync(0xffffffff, den.z, o);
        den.w += __shfl_xor_sync(0xffffffff, den.w, o);
    }
    float dh[4] = {den.x, den.y, den.z, den.w};
    float rinv = 1.0f / (dh[hme] + 1e-16f);

    const float4* bp = (const float4*)&bias[myc];
    float4 b1 = bp[0], b2 = bp[1];
    float v[8];
    v[0] = fmaxf(acc[0] * rinv + b1.x, 0.f);
    v[1] = fmaxf(acc[1] * rinv + b1.y, 0.f);
    v[2] = fmaxf(acc[2] * rinv + b1.z, 0.f);
    v[3] = fmaxf(acc[3] * rinv + b1.w, 0.f);
    v[4] = fmaxf(acc[4] * rinv + b2.x, 0.f);
    v[5] = fmaxf(acc[5] * rinv + b2.y, 0.f);
    v[6] = fmaxf(acc[6] * rinv + b2.z, 0.f);
    v[7] = fmaxf(acc[7] * rinv + b2.w, 0.f);
    // stash for pooling
    *(float4*)&sv[warp][myc] = make_float4(v[0], v[1], v[2], v[3]);
    *(float4*)&sv[warp][myc + 4] = make_float4(v[4], v[5], v[6], v[7]);
    // fp16 hi/lo split for next GEMM
    uint4 uh, ul;
    float l[8];
#pragma unroll
    for (int q = 0; q < 8; q++) {
        __half hbits = __float2half_rn(v[q]);
        l[q] = v[q] - __half2float(hbits);
    }
    uh.x = pk2h(v[0], v[1]); uh.y = pk2h(v[2], v[3]);
    uh.z = pk2h(v[4], v[5]); uh.w = pk2h(v[6], v[7]);
    ul.x = pk2h(l[0], l[1]); ul.y = pk2h(l[2], l[3]);
    ul.z = pk2h(l[4], l[5]); ul.w = pk2h(l[6], l[7]);
    *(uint4*)&g_xhi[(size_t)n * CC + myc] = uh;
    *(uint4*)&g_xlo[(size_t)n * CC + myc] = ul;

    // fused batch max-pool: thread tid owns channel tid across block's 8 nodes
    __syncthreads();
    int c = tid;
    int nbase = blockIdx.x * 8;
    int curb = batch[nbase];
    float mx = sv[0][c];
#pragma unroll
    for (int w = 1; w < 8; w++) {
        int b = batch[nbase + w];
        if (b != curb) {
            atomicMax((int*)&g_g[curb * GCOLS + goff + c], __float_as_int(mx));
            curb = b; mx = 0.0f;
        }
        mx = fmaxf(mx, sv[w][c]);
    }
    atomicMax((int*)&g_g[curb * GCOLS + goff + c], __float_as_int(mx));
}

__global__ void k_final(const float* __restrict__ agg_w,
                        const float* __restrict__ agg_b,
                        float* __restrict__ out) {
    __shared__ float sg[GCOLS];
    int b = blockIdx.x;
    int tid = threadIdx.x;
    for (int k = tid; k < GCOLS; k += 256) sg[k] = g_g[b * GCOLS + k];
    __syncthreads();
    float acc = agg_b[tid];
    for (int k = 0; k < GCOLS; k++) acc += sg[k] * agg_w[(size_t)k * BOTN + tid];
    out[b * BOTN + tid] = acc;
}

// ---------------- host ----------------
extern "C" void kernel_launch(void* const* d_in, const int* in_sizes, int n_in,
                              void* d_out, int out_size) {
    const float* sf    = (const float*)d_in[0];
    const int*   ei    = (const int*)d_in[1];
    const int*   batch = (const int*)d_in[2];
    const float* bw    = (const float*)d_in[3];
    const float* bb    = (const float*)d_in[4];
    const float* lin_w[3]   = {(const float*)d_in[5],  (const float*)d_in[9],  (const float*)d_in[13]};
    const float* att_src[3] = {(const float*)d_in[6],  (const float*)d_in[10], (const float*)d_in[14]};
    const float* att_dst[3] = {(const float*)d_in[7],  (const float*)d_in[11], (const float*)d_in[15]};
    const float* bias[3]    = {(const float*)d_in[8],  (const float*)d_in[12], (const float*)d_in[16]};
    const float* agg_w = (const float*)d_in[17];
    const float* agg_b = (const float*)d_in[18];
    float* out = (float*)d_out;

    cudaFuncSetAttribute(k_gemm_mma, cudaFuncAttributeMaxDynamicSharedMemorySize, GEMM_SMEM);

    // CSR build (graph is layer-invariant)
    k_zero_counts<<<(BB * GCOLS + 255) / 256, 256>>>();
    k_hist<<<(E2 + 255) / 256, 256>>>(ei);
    k_scan<<<1, 1024>>>();
    k_scatter<<<(E2 + 255) / 256, 256>>>(ei);

    k_wconv_all<<<(3 * CC * CC + 255) / 256, 256>>>(lin_w[0], lin_w[1], lin_w[2]);
    k_input<<<NN / 8, 64>>>(sf, bw, bb, batch);

    for (int L = 0; L < 3; L++) {
        int K = (L == 0) ? FF : CC;
        dim3 gg(2, (NN + 127) / 128);
        k_gemm_mma<<<gg, 256, GEMM_SMEM>>>(L, K, att_src[L], att_dst[L]);
        k_gat<<<NN / 8, 256>>>(bias[L], batch, FF + L * CC);
    }

    k_final<<<BB, BOTN>>>(agg_w, agg_b, out);
}

// round 15
// speedup vs baseline: 4.0519x; 1.2314x over previous
#include <cuda_runtime.h>
#include <cuda_fp16.h>
#include <math.h>
#include <stdint.h>

// Problem constants (fixed shapes)
#define NN   30000
#define EE   240000
#define E2   (EE + NN)      // 270000 edges incl self-loops
#define BB   64
#define FF   64
#define HH   4
#define CC   256            // H*F
#define GCOLS 832           // F*(1+H*T)
#define BOTN 256

// ---------------- device scratch (no allocations allowed) ----------------
__device__ __align__(16) __half g_xs[NN * CC];   // xs = x @ W (fp16, read by gat)
__device__ float g_asrc[NN * HH];
__device__ float g_adst[NN * HH];
__device__ float g_g[BB * GCOLS];
// fp16 hi/lo activation buffers + fp16 weights (GEMM operands)
__device__ __align__(16) __half g_x0hi[NN * FF];
__device__ __align__(16) __half g_x0lo[NN * FF];
__device__ __align__(16) __half g_xhi[NN * CC];
__device__ __align__(16) __half g_xlo[NN * CC];
__device__ __align__(16) __half g_wt[3 * CC * CC];   // transposed [n][k], per layer
// CSR (built once per launch)
__device__ int g_deg[NN];
__device__ int g_cursor[NN];
__device__ int g_off[NN + 1];
__device__ int g_csr_src[E2];

// ---------------- helpers ----------------
__device__ __forceinline__ void edge_endpoints(const int* __restrict__ ei,
                                               int e, int& src, int& dst) {
    if (e < EE) { src = ei[e]; dst = ei[EE + e]; }
    else        { src = dst = e - EE; }
}

__device__ __forceinline__ uint32_t pk2h(float a, float b) {
    __half2 h = __floats2half2_rn(a, b);
    return *(uint32_t*)&h;
}

// m16n8k16 fp16 MMA, fp32 accumulate
__device__ __forceinline__ void mma16816(float* c, const uint32_t* a,
                                         uint32_t b0, uint32_t b1) {
    asm volatile(
        "mma.sync.aligned.m16n8k16.row.col.f32.f16.f16.f32 "
        "{%0,%1,%2,%3}, {%4,%5,%6,%7}, {%8,%9}, {%0,%1,%2,%3};"
        : "+f"(c[0]), "+f"(c[1]), "+f"(c[2]), "+f"(c[3])
        : "r"(a[0]), "r"(a[1]), "r"(a[2]), "r"(a[3]), "r"(b0), "r"(b1));
}

__device__ __forceinline__ void cpa16(uint32_t dst, const void* src, bool pred) {
    asm volatile("cp.async.cg.shared.global [%0], [%1], 16, %2;"
                 :: "r"(dst), "l"(src), "r"(pred ? 16 : 0));
}
#define CPA_COMMIT() asm volatile("cp.async.commit_group;" ::: "memory")
#define CPA_WAIT2()  asm volatile("cp.async.wait_group 2;" ::: "memory")
#define CPA_WAIT1()  asm volatile("cp.async.wait_group 1;" ::: "memory")
#define CPA_WAIT0()  asm volatile("cp.async.wait_group 0;" ::: "memory")

// ---------------- CSR build (once per launch) ----------------
__global__ void k_zero_counts() {
    int i = blockIdx.x * blockDim.x + threadIdx.x;
    if (i < NN) { g_deg[i] = 0; g_cursor[i] = 0; }
    if (i < BB * GCOLS) g_g[i] = 0.0f;
}

__global__ void k_hist(const int* __restrict__ ei) {
    int e = blockIdx.x * blockDim.x + threadIdx.x;
    if (e >= E2) return;
    int dst = (e < EE) ? ei[EE + e] : e - EE;
    atomicAdd(&g_deg[dst], 1);
}

__global__ void k_scan() {
    __shared__ int sp[1024];
    int tid = threadIdx.x;
    const int CHK = (NN + 1023) / 1024;
    int base = tid * CHK;
    int s = 0;
    for (int i = 0; i < CHK; i++) {
        int idx = base + i;
        if (idx < NN) s += g_deg[idx];
    }
    sp[tid] = s;
    __syncthreads();
    for (int o = 1; o < 1024; o <<= 1) {
        int u = (tid >= o) ? sp[tid - o] : 0;
        __syncthreads();
        sp[tid] += u;
        __syncthreads();
    }
    int run = sp[tid] - s;
    for (int i = 0; i < CHK; i++) {
        int idx = base + i;
        if (idx < NN) { g_off[idx] = run; run += g_deg[idx]; }
    }
    if (tid == 1023) g_off[NN] = sp[1023];
}

__global__ void k_scatter(const int* __restrict__ ei) {
    int e = blockIdx.x * blockDim.x + threadIdx.x;
    if (e >= E2) return;
    int src, dst;
    edge_endpoints(ei, e, src, dst);
    int pos = atomicAdd(&g_cursor[dst], 1);
    g_csr_src[g_off[dst] + pos] = src;
}

// ---------------- weight transpose + fp16 (all layers, once) ----------------
__global__ void k_wconv_all(const float* __restrict__ W0,
                            const float* __restrict__ W1,
                            const float* __restrict__ W2) {
    int idx = blockIdx.x * blockDim.x + threadIdx.x;
    if (idx >= 3 * CC * CC) return;
    int L = idx >> 16;
    int r = idx & 65535;
    int k = r >> 8, n = r & 255;
    int K = (L == 0) ? FF : CC;
    if (k >= K) return;
    const float* W = (L == 0) ? W0 : ((L == 1) ? W1 : W2);
    g_wt[L * CC * CC + n * K + k] = __float2half_rn(W[(size_t)k * CC + n]);
}

// ---------------- input layer: 8 nodes per 64-thread block ----------------
__global__ void k_input(const float* __restrict__ sf,
                        const float* __restrict__ bw,
                        const float* __restrict__ bb,
                        const int* __restrict__ batch) {
    int c = threadIdx.x;            // 0..63
    int base = blockIdx.x * 8;
    float w0 = bw[0 * FF + c], w1 = bw[1 * FF + c], w2 = bw[2 * FF + c],
          w3 = bw[3 * FF + c], w4 = bw[4 * FF + c];
    float bias = bb[c];
    int curb = batch[base];
    float mx = 0.0f;
#pragma unroll
    for (int i = 0; i < 8; i++) {
        int n = base + i;
        int b = batch[n];
        if (b != curb) {
            atomicMax((int*)&g_g[curb * GCOLS + c], __float_as_int(mx));
            curb = b; mx = 0.0f;
        }
        const float* s = &sf[n * 5];
        float v = bias + s[0]*w0 + s[1]*w1 + s[2]*w2 + s[3]*w3 + s[4]*w4;
        v = fmaxf(v, 0.0f);
        __half h = __float2half_rn(v);
        g_x0hi[n * FF + c] = h;
        g_x0lo[n * FF + c] = __float2half_rn(v - __half2float(h));
        mx = fmaxf(mx, v);
    }
    atomicMax((int*)&g_g[curb * GCOLS + c], __float_as_int(mx));
}

// ---- fp16 2-product tensor-core GEMM + fused attention coefficients.
// 3-stage cp.async pipeline. g_xs[m,:] = A[m,:K] @ W[:K,:256] (fp16 out)
#define APAD 40
#define ARR_B (128 * APAD * 2)      // bytes per operand array (10240)
#define STG_B (3 * ARR_B)           // bytes per stage (30720)
#define NSTG  3
#define GEMM_SMEM (NSTG * STG_B)    // 92160

__global__ void __launch_bounds__(256, 2)
k_gemm_mma(int layer, int K,
           const float* __restrict__ att_src, const float* __restrict__ att_dst) {
    const __half* Ahg = (layer == 0) ? g_x0hi : g_xhi;
    const __half* Alg = (layer == 0) ? g_x0lo : g_xlo;
    const __half* Whg = g_wt + layer * CC * CC;
    extern __shared__ char smem[];

    int tid = threadIdx.x;
    int warp = tid >> 5, lane = tid & 31;
    int wm = warp & 3;
    int wn = warp >> 2;
    int g = lane >> 2, t = lane & 3;
    int bm = blockIdx.y * 128;
    int bn = blockIdx.x * 128;

    uint32_t sbase = (uint32_t)__cvta_generic_to_shared(smem);

    auto fill = [&](int s, int k0) {
        uint32_t st = sbase + s * STG_B;
#pragma unroll
        for (int i = tid; i < 512; i += 256) {
            int r = i >> 2;
            int kq = (i & 3) << 3;
            int gr = bm + r;
            bool p = gr < NN;
            size_t oa = (size_t)(p ? gr : 0) * K + k0 + kq;
            uint32_t d = (r * APAD + kq) * 2;
            cpa16(st + 0 * ARR_B + d, &Ahg[oa], p);
            cpa16(st + 1 * ARR_B + d, &Alg[oa], p);
            size_t ob = (size_t)(bn + r) * K + k0 + kq;
            cpa16(st + 2 * ARR_B + d, &Whg[ob], true);
        }
        CPA_COMMIT();
    };

    float acc[2][8][4];
#pragma unroll
    for (int i = 0; i < 2; i++)
#pragma unroll
        for (int j = 0; j < 8; j++)
#pragma unroll
            for (int q = 0; q < 4; q++) acc[i][j][q] = 0.0f;

    int nch = K >> 5;
    fill(0, 0);
    if (nch > 1) fill(1, 32);
    for (int ch = 0; ch < nch; ch++) {
        if (ch + 2 < nch) { fill((ch + 2) % NSTG, (ch + 2) << 5); CPA_WAIT2(); }
        else if (ch + 1 < nch) { CPA_WAIT1(); }
        else { CPA_WAIT0(); }
        __syncthreads();

        int st = ch % NSTG;
        const __half* Ah = (const __half*)(smem + st * STG_B);
        const __half* Al = (const __half*)(smem + st * STG_B + ARR_B);
        const __half* Bh = (const __half*)(smem + st * STG_B + 2 * ARR_B);

#pragma unroll
        for (int ks = 0; ks < 32; ks += 16) {
            uint32_t ah[2][4], al[2][4];
#pragma unroll
            for (int mt = 0; mt < 2; mt++) {
                int r = wm * 32 + mt * 16;
                ah[mt][0] = *(uint32_t*)&Ah[(r + g) * APAD + ks + 2 * t];
                ah[mt][1] = *(uint32_t*)&Ah[(r + g + 8) * APAD + ks + 2 * t];
                ah[mt][2] = *(uint32_t*)&Ah[(r + g) * APAD + ks + 8 + 2 * t];
                ah[mt][3] = *(uint32_t*)&Ah[(r + g + 8) * APAD + ks + 8 + 2 * t];
                al[mt][0] = *(uint32_t*)&Al[(r + g) * APAD + ks + 2 * t];
                al[mt][1] = *(uint32_t*)&Al[(r + g + 8) * APAD + ks + 2 * t];
                al[mt][2] = *(uint32_t*)&Al[(r + g) * APAD + ks + 8 + 2 * t];
                al[mt][3] = *(uint32_t*)&Al[(r + g + 8) * APAD + ks + 8 + 2 * t];
            }
#pragma unroll
            for (int nt = 0; nt < 8; nt++) {
                int c = wn * 64 + nt * 8 + g;
                uint32_t b0 = *(uint32_t*)&Bh[c * APAD + ks + 2 * t];
                uint32_t b1 = *(uint32_t*)&Bh[c * APAD + ks + 8 + 2 * t];
#pragma unroll
                for (int mt = 0; mt < 2; mt++) {
                    mma16816(acc[mt][nt], ah[mt], b0, b1);
                    mma16816(acc[mt][nt], al[mt], b0, b1);
                }
            }
        }
        __syncthreads();
    }

    // store C (fp16) + fused attention dots (fp32 accumulators)
    int h = (bn >> 6) + wn;
#pragma unroll
    for (int mt = 0; mt < 2; mt++) {
        int r0 = bm + wm * 32 + mt * 16 + g;
        float sA = 0.f, dA = 0.f, sB = 0.f, dB = 0.f;
#pragma unroll
        for (int nt = 0; nt < 8; nt++) {
            int c = bn + wn * 64 + nt * 8 + 2 * t;
            float w0s = att_src[c], w1s = att_src[c + 1];
            float w0d = att_dst[c], w1d = att_dst[c + 1];
            sA += acc[mt][nt][0] * w0s + acc[mt][nt][1] * w1s;
            dA += acc[mt][nt][0] * w0d + acc[mt][nt][1] * w1d;
            sB += acc[mt][nt][2] * w0s + acc[mt][nt][3] * w1s;
            dB += acc[mt][nt][2] * w0d + acc[mt][nt][3] * w1d;
            if (r0 < NN) {
                __half2 hv = __floats2half2_rn(acc[mt][nt][0], acc[mt][nt][1]);
                *(__half2*)&g_xs[(size_t)r0 * CC + c] = hv;
            }
            if (r0 + 8 < NN) {
                __half2 hv = __floats2half2_rn(acc[mt][nt][2], acc[mt][nt][3]);
                *(__half2*)&g_xs[(size_t)(r0 + 8) * CC + c] = hv;
            }
        }
#pragma unroll
        for (int o = 1; o < 4; o <<= 1) {
            sA += __shfl_xor_sync(0xffffffff, sA, o);
            dA += __shfl_xor_sync(0xffffffff, dA, o);
            sB += __shfl_xor_sync(0xffffffff, sB, o);
            dB += __shfl_xor_sync(0xffffffff, dB, o);
        }
        if (t == 0) {
            if (r0 < NN)     { g_asrc[r0 * HH + h] = sA; g_adst[r0 * HH + h] = dA; }
            if (r0 + 8 < NN) { g_asrc[(r0 + 8) * HH + h] = sB; g_adst[(r0 + 8) * HH + h] = dB; }
        }
    }
}

// ---- fused GAT aggregation + relu + fp16 split + batch max-pool.
// Block = 8 consecutive nodes (one warp each); 3750 blocks exactly cover NN.
__global__ void __launch_bounds__(256)
k_gat(const float* __restrict__ bias, const int* __restrict__ batch, int goff) {
    __shared__ int   ssrc[8][32];
    __shared__ float sex[8][32][4];
    __shared__ float sv[8][CC];
    int tid = threadIdx.x;
    int warp = tid >> 5, lane = tid & 31;
    int n = blockIdx.x * 8 + warp;          // always < NN (3750*8 == NN)
    int beg = g_off[n], end = g_off[n + 1];
    float4 ad = *(const float4*)&g_adst[n * HH];

    float acc[8];
#pragma unroll
    for (int q = 0; q < 8; q++) acc[q] = 0.0f;
    float4 den = make_float4(0.f, 0.f, 0.f, 0.f);
    int myc = lane * 8;
    int hme = lane >> 3;
    for (int cb = beg; cb < end; cb += 32) {
        int i = cb + lane;
        int s = 0;
        float4 ex = make_float4(0.f, 0.f, 0.f, 0.f);
        if (i < end) {
            s = g_csr_src[i];
            float4 as = *(const float4*)&g_asrc[s * HH];
            float lx = as.x + ad.x, ly = as.y + ad.y, lz = as.z + ad.z, lw = as.w + ad.w;
            lx = (lx >= 0.f) ? lx : 0.2f * lx;
            ly = (ly >= 0.f) ? ly : 0.2f * ly;
            lz = (lz >= 0.f) ? lz : 0.2f * lz;
            lw = (lw >= 0.f) ? lw : 0.2f * lw;
            ex = make_float4(__expf(lx), __expf(ly), __expf(lz), __expf(lw));
            den.x += ex.x; den.y += ex.y; den.z += ex.z; den.w += ex.w;
        }
        ssrc[warp][lane] = s;
        *(float4*)&sex[warp][lane][0] = ex;
        __syncwarp();
        int cnt = min(32, end - cb);
        // depth-2 ping-pong prefetch; one uint4 = 8 fp16 channels per edge
        uint4 pld[2];
        float pe[2];
#define LOADJ(slot, j) do {                                            \
            int _s = ssrc[warp][j];                                    \
            pe[slot] = sex[warp][j][hme];                              \
            pld[slot] = *(const uint4*)&g_xs[(size_t)_s * CC + myc];   \
        } while (0)
        LOADJ(0, 0);
        if (cnt > 1) LOADJ(1, 1);
        for (int j = 0; j < cnt; j++) {
            uint4 u = pld[j & 1];
            float ev = pe[j & 1];
            if (j + 2 < cnt) LOADJ(j & 1, j + 2);
            __half2* hp = (__half2*)&u;
            float2 f0 = __half22float2(hp[0]);
            float2 f1 = __half22float2(hp[1]);
            float2 f2 = __half22float2(hp[2]);
            float2 f3 = __half22float2(hp[3]);
            acc[0] += ev * f0.x; acc[1] += ev * f0.y;
            acc[2] += ev * f1.x; acc[3] += ev * f1.y;
            acc[4] += ev * f2.x; acc[5] += ev * f2.y;
            acc[6] += ev * f3.x; acc[7] += ev * f3.y;
        }
#undef LOADJ
        __syncwarp();
    }

#pragma unroll
    for (int o = 16; o > 0; o >>= 1) {
        den.x += __shfl_xor_sync(0xffffffff, den.x, o);
        den.y += __shfl_xor_sync(0xffffffff, den.y, o);
        den.z += __shfl_xor_sync(0xffffffff, den.z, o);
        den.w += __shfl_xor_sync(0xffffffff, den.w, o);
    }
    float dh[4] = {den.x, den.y, den.z, den.w};
    float rinv = 1.0f / (dh[hme] + 1e-16f);

    const float4* bp = (const float4*)&bias[myc];
    float4 b1 = bp[0], b2 = bp[1];
    float v[8];
    v[0] = fmaxf(acc[0] * rinv + b1.x, 0.f);
    v[1] = fmaxf(acc[1] * rinv + b1.y, 0.f);
    v[2] = fmaxf(acc[2] * rinv + b1.z, 0.f);
    v[3] = fmaxf(acc[3] * rinv + b1.w, 0.f);
    v[4] = fmaxf(acc[4] * rinv + b2.x, 0.f);
    v[5] = fmaxf(acc[5] * rinv + b2.y, 0.f);
    v[6] = fmaxf(acc[6] * rinv + b2.z, 0.f);
    v[7] = fmaxf(acc[7] * rinv + b2.w, 0.f);
    // stash for pooling
    *(float4*)&sv[warp][myc] = make_float4(v[0], v[1], v[2], v[3]);
    *(float4*)&sv[warp][myc + 4] = make_float4(v[4], v[5], v[6], v[7]);
    // fp16 hi/lo split for next GEMM
    uint4 uh, ul;
    float l[8];
#pragma unroll
    for (int q = 0; q < 8; q++) {
        __half hbits = __float2half_rn(v[q]);
        l[q] = v[q] - __half2float(hbits);
    }
    uh.x = pk2h(v[0], v[1]); uh.y = pk2h(v[2], v[3]);
    uh.z = pk2h(v[4], v[5]); uh.w = pk2h(v[6], v[7]);
    ul.x = pk2h(l[0], l[1]); ul.y = pk2h(l[2], l[3]);
    ul.z = pk2h(l[4], l[5]); ul.w = pk2h(l[6], l[7]);
    *(uint4*)&g_xhi[(size_t)n * CC + myc] = uh;
    *(uint4*)&g_xlo[(size_t)n * CC + myc] = ul;

    // fused batch max-pool: thread tid owns channel tid across block's 8 nodes
    __syncthreads();
    int c = tid;
    int nbase = blockIdx.x * 8;
    int curb = batch[nbase];
    float mx = sv[0][c];
#pragma unroll
    for (int w = 1; w < 8; w++) {
        int b = batch[nbase + w];
        if (b != curb) {
            atomicMax((int*)&g_g[curb * GCOLS + goff + c], __float_as_int(mx));
            curb = b; mx = 0.0f;
        }
        mx = fmaxf(mx, sv[w][c]);
    }
    atomicMax((int*)&g_g[curb * GCOLS + goff + c], __float_as_int(mx));
}

__global__ void k_final(const float* __restrict__ agg_w,
                        const float* __restrict__ agg_b,
                        float* __restrict__ out) {
    __shared__ float sg[GCOLS];
    int b = blockIdx.x;
    int tid = threadIdx.x;
    for (int k = tid; k < GCOLS; k += 256) sg[k] = g_g[b * GCOLS + k];
    __syncthreads();
    float acc = agg_b[tid];
    for (int k = 0; k < GCOLS; k++) acc += sg[k] * agg_w[(size_t)k * BOTN + tid];
    out[b * BOTN + tid] = acc;
}

// ---------------- host ----------------
extern "C" void kernel_launch(void* const* d_in, const int* in_sizes, int n_in,
                              void* d_out, int out_size) {
    const float* sf    = (const float*)d_in[0];
    const int*   ei    = (const int*)d_in[1];
    const int*   batch = (const int*)d_in[2];
    const float* bw    = (const float*)d_in[3];
    const float* bb    = (const float*)d_in[4];
    const float* lin_w[3]   = {(const float*)d_in[5],  (const float*)d_in[9],  (const float*)d_in[13]};
    const float* att_src[3] = {(const float*)d_in[6],  (const float*)d_in[10], (const float*)d_in[14]};
    const float* att_dst[3] = {(const float*)d_in[7],  (const float*)d_in[11], (const float*)d_in[15]};
    const float* bias[3]    = {(const float*)d_in[8],  (const float*)d_in[12], (const float*)d_in[16]};
    const float* agg_w = (const float*)d_in[17];
    const float* agg_b = (const float*)d_in[18];
    float* out = (float*)d_out;

    cudaFuncSetAttribute(k_gemm_mma, cudaFuncAttributeMaxDynamicSharedMemorySize, GEMM_SMEM);

    // CSR build (graph is layer-invariant)
    k_zero_counts<<<(BB * GCOLS + 255) / 256, 256>>>();
    k_hist<<<(E2 + 255) / 256, 256>>>(ei);
    k_scan<<<1, 1024>>>();
    k_scatter<<<(E2 + 255) / 256, 256>>>(ei);

    k_wconv_all<<<(3 * CC * CC + 255) / 256, 256>>>(lin_w[0], lin_w[1], lin_w[2]);
    k_input<<<NN / 8, 64>>>(sf, bw, bb, batch);

    for (int L = 0; L < 3; L++) {
        int K = (L == 0) ? FF : CC;
        dim3 gg(2, (NN + 127) / 128);
        k_gemm_mma<<<gg, 256, GEMM_SMEM>>>(L, K, att_src[L], att_dst[L]);
        k_gat<<<NN / 8, 256>>>(bias[L], batch, FF + L * CC);
    }

    k_final<<<BB, BOTN>>>(agg_w, agg_b, out);
}

// round 16
// speedup vs baseline: 4.6229x; 1.1409x over previous
#include <cuda_runtime.h>
#include <cuda_fp16.h>
#include <math.h>
#include <stdint.h>

// Problem constants (fixed shapes)
#define NN   30000
#define EE   240000
#define E2   (EE + NN)      // 270000 edges incl self-loops
#define BB   64
#define FF   64
#define HH   4
#define CC   256            // H*F
#define GCOLS 832           // F*(1+H*T)
#define BOTN 256

// ---------------- device scratch (no allocations allowed) ----------------
__device__ __align__(16) __half g_xs[NN * CC];   // xs = x @ W (fp16, read by gat)
__device__ float g_asrc[NN * HH];
__device__ float g_adst[NN * HH];
__device__ float g_g[BB * GCOLS];
// fp16 activations + fp16 weights (GEMM operands)
__device__ __align__(16) __half g_x0[NN * FF];
__device__ __align__(16) __half g_xc[NN * CC];
__device__ __align__(16) __half g_wt[3 * CC * CC];   // transposed [n][k], per layer
// CSR (built once per launch)
__device__ int g_deg[NN];
__device__ int g_cursor[NN];
__device__ int g_off[NN + 1];
__device__ int g_csr_src[E2];

// ---------------- helpers ----------------
__device__ __forceinline__ void edge_endpoints(const int* __restrict__ ei,
                                               int e, int& src, int& dst) {
    if (e < EE) { src = ei[e]; dst = ei[EE + e]; }
    else        { src = dst = e - EE; }
}

__device__ __forceinline__ uint32_t pk2h(float a, float b) {
    __half2 h = __floats2half2_rn(a, b);
    return *(uint32_t*)&h;
}

// m16n8k16 fp16 MMA, fp32 accumulate
__device__ __forceinline__ void mma16816(float* c, const uint32_t* a,
                                         uint32_t b0, uint32_t b1) {
    asm volatile(
        "mma.sync.aligned.m16n8k16.row.col.f32.f16.f16.f32 "
        "{%0,%1,%2,%3}, {%4,%5,%6,%7}, {%8,%9}, {%0,%1,%2,%3};"
        : "+f"(c[0]), "+f"(c[1]), "+f"(c[2]), "+f"(c[3])
        : "r"(a[0]), "r"(a[1]), "r"(a[2]), "r"(a[3]), "r"(b0), "r"(b1));
}

__device__ __forceinline__ void cpa16(uint32_t dst, const void* src, bool pred) {
    asm volatile("cp.async.cg.shared.global [%0], [%1], 16, %2;"
                 :: "r"(dst), "l"(src), "r"(pred ? 16 : 0));
}
#define CPA_COMMIT() asm volatile("cp.async.commit_group;" ::: "memory")
#define CPA_WAIT2()  asm volatile("cp.async.wait_group 2;" ::: "memory")
#define CPA_WAIT1()  asm volatile("cp.async.wait_group 1;" ::: "memory")
#define CPA_WAIT0()  asm volatile("cp.async.wait_group 0;" ::: "memory")

// ---------------- CSR build (once per launch) ----------------
__global__ void k_zero_counts() {
    int i = blockIdx.x * blockDim.x + threadIdx.x;
    if (i < NN) { g_deg[i] = 0; g_cursor[i] = 0; }
    if (i < BB * GCOLS) g_g[i] = 0.0f;
}

__global__ void k_hist(const int* __restrict__ ei) {
    int e = blockIdx.x * blockDim.x + threadIdx.x;
    if (e >= E2) return;
    int dst = (e < EE) ? ei[EE + e] : e - EE;
    atomicAdd(&g_deg[dst], 1);
}

__global__ void k_scan() {
    __shared__ int sp[1024];
    int tid = threadIdx.x;
    const int CHK = (NN + 1023) / 1024;
    int base = tid * CHK;
    int s = 0;
    for (int i = 0; i < CHK; i++) {
        int idx = base + i;
        if (idx < NN) s += g_deg[idx];
    }
    sp[tid] = s;
    __syncthreads();
    for (int o = 1; o < 1024; o <<= 1) {
        int u = (tid >= o) ? sp[tid - o] : 0;
        __syncthreads();
        sp[tid] += u;
        __syncthreads();
    }
    int run = sp[tid] - s;
    for (int i = 0; i < CHK; i++) {
        int idx = base + i;
        if (idx < NN) { g_off[idx] = run; run += g_deg[idx]; }
    }
    if (tid == 1023) g_off[NN] = sp[1023];
}

__global__ void k_scatter(const int* __restrict__ ei) {
    int e = blockIdx.x * blockDim.x + threadIdx.x;
    if (e >= E2) return;
    int src, dst;
    edge_endpoints(ei, e, src, dst);
    int pos = atomicAdd(&g_cursor[dst], 1);
    g_csr_src[g_off[dst] + pos] = src;
}

// ---------------- weight transpose + fp16 (all layers, once) ----------------
__global__ void k_wconv_all(const float* __restrict__ W0,
                            const float* __restrict__ W1,
                            const float* __restrict__ W2) {
    int idx = blockIdx.x * blockDim.x + threadIdx.x;
    if (idx >= 3 * CC * CC) return;
    int L = idx >> 16;
    int r = idx & 65535;
    int k = r >> 8, n = r & 255;
    int K = (L == 0) ? FF : CC;
    if (k >= K) return;
    const float* W = (L == 0) ? W0 : ((L == 1) ? W1 : W2);
    g_wt[L * CC * CC + n * K + k] = __float2half_rn(W[(size_t)k * CC + n]);
}

// ---------------- input layer: 8 nodes per 64-thread block ----------------
__global__ void k_input(const float* __restrict__ sf,
                        const float* __restrict__ bw,
                        const float* __restrict__ bb,
                        const int* __restrict__ batch) {
    int c = threadIdx.x;            // 0..63
    int base = blockIdx.x * 8;
    float w0 = bw[0 * FF + c], w1 = bw[1 * FF + c], w2 = bw[2 * FF + c],
          w3 = bw[3 * FF + c], w4 = bw[4 * FF + c];
    float bias = bb[c];
    int curb = batch[base];
    float mx = 0.0f;
#pragma unroll
    for (int i = 0; i < 8; i++) {
        int n = base + i;
        int b = batch[n];
        if (b != curb) {
            atomicMax((int*)&g_g[curb * GCOLS + c], __float_as_int(mx));
            curb = b; mx = 0.0f;
        }
        const float* s = &sf[n * 5];
        float v = bias + s[0]*w0 + s[1]*w1 + s[2]*w2 + s[3]*w3 + s[4]*w4;
        v = fmaxf(v, 0.0f);
        g_x0[n * FF + c] = __float2half_rn(v);
        mx = fmaxf(mx, v);
    }
    atomicMax((int*)&g_g[curb * GCOLS + c], __float_as_int(mx));
}

// ---- fp16 single-product tensor-core GEMM + fused attention coefficients.
// 3-stage cp.async pipeline. g_xs[m,:] = A[m,:K] @ W[:K,:256] (fp16 out)
#define APAD 40
#define ARR_B (128 * APAD * 2)      // bytes per operand array (10240)
#define STG_B (2 * ARR_B)           // bytes per stage (20480)
#define NSTG  3
#define GEMM_SMEM (NSTG * STG_B)    // 61440

__global__ void __launch_bounds__(256, 2)
k_gemm_mma(int layer, int K,
           const float* __restrict__ att_src, const float* __restrict__ att_dst) {
    const __half* Ag = (layer == 0) ? g_x0 : g_xc;
    const __half* Whg = g_wt + layer * CC * CC;
    extern __shared__ char smem[];

    int tid = threadIdx.x;
    int warp = tid >> 5, lane = tid & 31;
    int wm = warp & 3;
    int wn = warp >> 2;
    int g = lane >> 2, t = lane & 3;
    int bm = blockIdx.y * 128;
    int bn = blockIdx.x * 128;

    uint32_t sbase = (uint32_t)__cvta_generic_to_shared(smem);

    auto fill = [&](int s, int k0) {
        uint32_t st = sbase + s * STG_B;
#pragma unroll
        for (int i = tid; i < 512; i += 256) {
            int r = i >> 2;
            int kq = (i & 3) << 3;
            int gr = bm + r;
            bool p = gr < NN;
            size_t oa = (size_t)(p ? gr : 0) * K + k0 + kq;
            uint32_t d = (r * APAD + kq) * 2;
            cpa16(st + 0 * ARR_B + d, &Ag[oa], p);
            size_t ob = (size_t)(bn + r) * K + k0 + kq;
            cpa16(st + 1 * ARR_B + d, &Whg[ob], true);
        }
        CPA_COMMIT();
    };

    float acc[2][8][4];
#pragma unroll
    for (int i = 0; i < 2; i++)
#pragma unroll
        for (int j = 0; j < 8; j++)
#pragma unroll
            for (int q = 0; q < 4; q++) acc[i][j][q] = 0.0f;

    int nch = K >> 5;
    fill(0, 0);
    if (nch > 1) fill(1, 32);
    for (int ch = 0; ch < nch; ch++) {
        if (ch + 2 < nch) { fill((ch + 2) % NSTG, (ch + 2) << 5); CPA_WAIT2(); }
        else if (ch + 1 < nch) { CPA_WAIT1(); }
        else { CPA_WAIT0(); }
        __syncthreads();

        int st = ch % NSTG;
        const __half* Ah = (const __half*)(smem + st * STG_B);
        const __half* Bh = (const __half*)(smem + st * STG_B + ARR_B);

#pragma unroll
        for (int ks = 0; ks < 32; ks += 16) {
            uint32_t ah[2][4];
#pragma unroll
            for (int mt = 0; mt < 2; mt++) {
                int r = wm * 32 + mt * 16;
                ah[mt][0] = *(uint32_t*)&Ah[(r + g) * APAD + ks + 2 * t];
                ah[mt][1] = *(uint32_t*)&Ah[(r + g + 8) * APAD + ks + 2 * t];
                ah[mt][2] = *(uint32_t*)&Ah[(r + g) * APAD + ks + 8 + 2 * t];
                ah[mt][3] = *(uint32_t*)&Ah[(r + g + 8) * APAD + ks + 8 + 2 * t];
            }
#pragma unroll
            for (int nt = 0; nt < 8; nt++) {
                int c = wn * 64 + nt * 8 + g;
                uint32_t b0 = *(uint32_t*)&Bh[c * APAD + ks + 2 * t];
                uint32_t b1 = *(uint32_t*)&Bh[c * APAD + ks + 8 + 2 * t];
#pragma unroll
                for (int mt = 0; mt < 2; mt++) {
                    mma16816(acc[mt][nt], ah[mt], b0, b1);
                }
            }
        }
        __syncthreads();
    }

    // store C (fp16) + fused attention dots (fp32 accumulators)
    int h = (bn >> 6) + wn;
#pragma unroll
    for (int mt = 0; mt < 2; mt++) {
        int r0 = bm + wm * 32 + mt * 16 + g;
        float sA = 0.f, dA = 0.f, sB = 0.f, dB = 0.f;
#pragma unroll
        for (int nt = 0; nt < 8; nt++) {
            int c = bn + wn * 64 + nt * 8 + 2 * t;
            float w0s = att_src[c], w1s = att_src[c + 1];
            float w0d = att_dst[c], w1d = att_dst[c + 1];
            sA += acc[mt][nt][0] * w0s + acc[mt][nt][1] * w1s;
            dA += acc[mt][nt][0] * w0d + acc[mt][nt][1] * w1d;
            sB += acc[mt][nt][2] * w0s + acc[mt][nt][3] * w1s;
            dB += acc[mt][nt][2] * w0d + acc[mt][nt][3] * w1d;
            if (r0 < NN) {
                __half2 hv = __floats2half2_rn(acc[mt][nt][0], acc[mt][nt][1]);
                *(__half2*)&g_xs[(size_t)r0 * CC + c] = hv;
            }
            if (r0 + 8 < NN) {
                __half2 hv = __floats2half2_rn(acc[mt][nt][2], acc[mt][nt][3]);
                *(__half2*)&g_xs[(size_t)(r0 + 8) * CC + c] = hv;
            }
        }
#pragma unroll
        for (int o = 1; o < 4; o <<= 1) {
            sA += __shfl_xor_sync(0xffffffff, sA, o);
            dA += __shfl_xor_sync(0xffffffff, dA, o);
            sB += __shfl_xor_sync(0xffffffff, sB, o);
            dB += __shfl_xor_sync(0xffffffff, dB, o);
        }
        if (t == 0) {
            if (r0 < NN)     { g_asrc[r0 * HH + h] = sA; g_adst[r0 * HH + h] = dA; }
            if (r0 + 8 < NN) { g_asrc[(r0 + 8) * HH + h] = sB; g_adst[(r0 + 8) * HH + h] = dB; }
        }
    }
}

// ---- fused GAT aggregation + relu + fp16 + batch max-pool.
// Block = 8 consecutive nodes (one warp each); 3750 blocks exactly cover NN.
__global__ void __launch_bounds__(256)
k_gat(const float* __restrict__ bias, const int* __restrict__ batch, int goff) {
    __shared__ int   ssrc[8][32];
    __shared__ float sex[8][32][4];
    __shared__ float sv[8][CC];
    int tid = threadIdx.x;
    int warp = tid >> 5, lane = tid & 31;
    int n = blockIdx.x * 8 + warp;          // always < NN (3750*8 == NN)
    int beg = g_off[n], end = g_off[n + 1];
    float4 ad = *(const float4*)&g_adst[n * HH];

    float acc[8];
#pragma unroll
    for (int q = 0; q < 8; q++) acc[q] = 0.0f;
    float4 den = make_float4(0.f, 0.f, 0.f, 0.f);
    int myc = lane * 8;
    int hme = lane >> 3;
    for (int cb = beg; cb < end; cb += 32) {
        int i = cb + lane;
        int s = 0;
        float4 ex = make_float4(0.f, 0.f, 0.f, 0.f);
        if (i < end) {
            s = g_csr_src[i];
            float4 as = *(const float4*)&g_asrc[s * HH];
            float lx = as.x + ad.x, ly = as.y + ad.y, lz = as.z + ad.z, lw = as.w + ad.w;
            lx = (lx >= 0.f) ? lx : 0.2f * lx;
            ly = (ly >= 0.f) ? ly : 0.2f * ly;
            lz = (lz >= 0.f) ? lz : 0.2f * lz;
            lw = (lw >= 0.f) ? lw : 0.2f * lw;
            ex = make_float4(__expf(lx), __expf(ly), __expf(lz), __expf(lw));
            den.x += ex.x; den.y += ex.y; den.z += ex.z; den.w += ex.w;
        }
        ssrc[warp][lane] = s;
        *(float4*)&sex[warp][lane][0] = ex;
        __syncwarp();
        int cnt = min(32, end - cb);
        // depth-2 ping-pong prefetch; one uint4 = 8 fp16 channels per edge
        uint4 pld[2];
        float pe[2];
#define LOADJ(slot, j) do {                                            \
            int _s = ssrc[warp][j];                                    \
            pe[slot] = sex[warp][j][hme];                              \
            pld[slot] = *(const uint4*)&g_xs[(size_t)_s * CC + myc];   \
        } while (0)
        LOADJ(0, 0);
        if (cnt > 1) LOADJ(1, 1);
        for (int j = 0; j < cnt; j++) {
            uint4 u = pld[j & 1];
            float ev = pe[j & 1];
            if (j + 2 < cnt) LOADJ(j & 1, j + 2);
            __half2* hp = (__half2*)&u;
            float2 f0 = __half22float2(hp[0]);
            float2 f1 = __half22float2(hp[1]);
            float2 f2 = __half22float2(hp[2]);
            float2 f3 = __half22float2(hp[3]);
            acc[0] += ev * f0.x; acc[1] += ev * f0.y;
            acc[2] += ev * f1.x; acc[3] += ev * f1.y;
            acc[4] += ev * f2.x; acc[5] += ev * f2.y;
            acc[6] += ev * f3.x; acc[7] += ev * f3.y;
        }
#undef LOADJ
        __syncwarp();
    }

#pragma unroll
    for (int o = 16; o > 0; o >>= 1) {
        den.x += __shfl_xor_sync(0xffffffff, den.x, o);
        den.y += __shfl_xor_sync(0xffffffff, den.y, o);
        den.z += __shfl_xor_sync(0xffffffff, den.z, o);
        den.w += __shfl_xor_sync(0xffffffff, den.w, o);
    }
    float dh[4] = {den.x, den.y, den.z, den.w};
    float rinv = 1.0f / (dh[hme] + 1e-16f);

    const float4* bp = (const float4*)&bias[myc];
    float4 b1 = bp[0], b2 = bp[1];
    float v[8];
    v[0] = fmaxf(acc[0] * rinv + b1.x, 0.f);
    v[1] = fmaxf(acc[1] * rinv + b1.y, 0.f);
    v[2] = fmaxf(acc[2] * rinv + b1.z, 0.f);
    v[3] = fmaxf(acc[3] * rinv + b1.w, 0.f);
    v[4] = fmaxf(acc[4] * rinv + b2.x, 0.f);
    v[5] = fmaxf(acc[5] * rinv + b2.y, 0.f);
    v[6] = fmaxf(acc[6] * rinv + b2.z, 0.f);
    v[7] = fmaxf(acc[7] * rinv + b2.w, 0.f);
    // stash for pooling
    *(float4*)&sv[warp][myc] = make_float4(v[0], v[1], v[2], v[3]);
    *(float4*)&sv[warp][myc + 4] = make_float4(v[4], v[5], v[6], v[7]);
    // fp16 for next GEMM
    uint4 uh;
    uh.x = pk2h(v[0], v[1]); uh.y = pk2h(v[2], v[3]);
    uh.z = pk2h(v[4], v[5]); uh.w = pk2h(v[6], v[7]);
    *(uint4*)&g_xc[(size_t)n * CC + myc] = uh;

    // fused batch max-pool: thread tid owns channel tid across block's 8 nodes
    __syncthreads();
    int c = tid;
    int nbase = blockIdx.x * 8;
    int curb = batch[nbase];
    float mx = sv[0][c];
#pragma unroll
    for (int w = 1; w < 8; w++) {
        int b = batch[nbase + w];
        if (b != curb) {
            atomicMax((int*)&g_g[curb * GCOLS + goff + c], __float_as_int(mx));
            curb = b; mx = 0.0f;
        }
        mx = fmaxf(mx, sv[w][c]);
    }
    atomicMax((int*)&g_g[curb * GCOLS + goff + c], __float_as_int(mx));
}

__global__ void k_final(const float* __restrict__ agg_w,
                        const float* __restrict__ agg_b,
                        float* __restrict__ out) {
    __shared__ float sg[GCOLS];
    int b = blockIdx.x;
    int tid = threadIdx.x;
    for (int k = tid; k < GCOLS; k += 256) sg[k] = g_g[b * GCOLS + k];
    __syncthreads();
    float acc = agg_b[tid];
    for (int k = 0; k < GCOLS; k++) acc += sg[k] * agg_w[(size_t)k * BOTN + tid];
    out[b * BOTN + tid] = acc;
}

// ---------------- host ----------------
extern "C" void kernel_launch(void* const* d_in, const int* in_sizes, int n_in,
                              void* d_out, int out_size) {
    const float* sf    = (const float*)d_in[0];
    const int*   ei    = (const int*)d_in[1];
    const int*   batch = (const int*)d_in[2];
    const float* bw    = (const float*)d_in[3];
    const float* bb    = (const float*)d_in[4];
    const float* lin_w[3]   = {(const float*)d_in[5],  (const float*)d_in[9],  (const float*)d_in[13]};
    const float* att_src[3] = {(const float*)d_in[6],  (const float*)d_in[10], (const float*)d_in[14]};
    const float* att_dst[3] = {(const float*)d_in[7],  (const float*)d_in[11], (const float*)d_in[15]};
    const float* bias[3]    = {(const float*)d_in[8],  (const float*)d_in[12], (const float*)d_in[16]};
    const float* agg_w = (const float*)d_in[17];
    const float* agg_b = (const float*)d_in[18];
    float* out = (float*)d_out;

    cudaFuncSetAttribute(k_gemm_mma, cudaFuncAttributeMaxDynamicSharedMemorySize, GEMM_SMEM);

    // CSR build (graph is layer-invariant)
    k_zero_counts<<<(BB * GCOLS + 255) / 256, 256>>>();
    k_hist<<<(E2 + 255) / 256, 256>>>(ei);
    k_scan<<<1, 1024>>>();
    k_scatter<<<(E2 + 255) / 256, 256>>>(ei);

    k_wconv_all<<<(3 * CC * CC + 255) / 256, 256>>>(lin_w[0], lin_w[1], lin_w[2]);
    k_input<<<NN / 8, 64>>>(sf, bw, bb, batch);

    for (int L = 0; L < 3; L++) {
        int K = (L == 0) ? FF : CC;
        dim3 gg(2, (NN + 127) / 128);
        k_gemm_mma<<<gg, 256, GEMM_SMEM>>>(L, K, att_src[L], att_dst[L]);
        k_gat<<<NN / 8, 256>>>(bias[L], batch, FF + L * CC);
    }

    k_final<<<BB, BOTN>>>(agg_w, agg_b, out);
}

// round 17
// speedup vs baseline: 4.7350x; 1.0243x over previous
#include <cuda_runtime.h>
#include <cuda_fp16.h>
#include <math.h>
#include <stdint.h>

// Problem constants (fixed shapes)
#define NN   30000
#define EE   240000
#define E2   (EE + NN)      // 270000 edges incl self-loops
#define BB   64
#define FF   64
#define HH   4
#define CC   256            // H*F
#define GCOLS 832           // F*(1+H*T)
#define BOTN 256
#define SCB  118            // ceil(NN/256) scan blocks

// ---------------- device scratch (no allocations allowed) ----------------
__device__ __align__(16) __half g_xs[NN * CC];   // xs = x @ W (fp16, read by gat)
__device__ float g_asrc[NN * HH];
__device__ float g_adst[NN * HH];
__device__ float g_g[BB * GCOLS];
// fp16 activations + fp16 weights (GEMM operands)
__device__ __align__(16) __half g_x0[NN * FF];
__device__ __align__(16) __half g_xc[NN * CC];
__device__ __align__(16) __half g_wt[3 * CC * CC];   // transposed [n][k], per layer
// CSR (built once per launch)
__device__ int g_deg[NN];
__device__ int g_cursor[NN];
__device__ int g_off[NN + 1];
__device__ int g_csr_src[E2];
__device__ int g_part[SCB];
__device__ int g_poff[SCB];

// ---------------- helpers ----------------
__device__ __forceinline__ void edge_endpoints(const int* __restrict__ ei,
                                               int e, int& src, int& dst) {
    if (e < EE) { src = ei[e]; dst = ei[EE + e]; }
    else        { src = dst = e - EE; }
}

__device__ __forceinline__ uint32_t pk2h(float a, float b) {
    __half2 h = __floats2half2_rn(a, b);
    return *(uint32_t*)&h;
}

// m16n8k16 fp16 MMA, fp32 accumulate
__device__ __forceinline__ void mma16816(float* c, const uint32_t* a,
                                         uint32_t b0, uint32_t b1) {
    asm volatile(
        "mma.sync.aligned.m16n8k16.row.col.f32.f16.f16.f32 "
        "{%0,%1,%2,%3}, {%4,%5,%6,%7}, {%8,%9}, {%0,%1,%2,%3};"
        : "+f"(c[0]), "+f"(c[1]), "+f"(c[2]), "+f"(c[3])
        : "r"(a[0]), "r"(a[1]), "r"(a[2]), "r"(a[3]), "r"(b0), "r"(b1));
}

__device__ __forceinline__ void cpa16(uint32_t dst, const void* src, bool pred) {
    asm volatile("cp.async.cg.shared.global [%0], [%1], 16, %2;"
                 :: "r"(dst), "l"(src), "r"(pred ? 16 : 0));
}
#define CPA_COMMIT() asm volatile("cp.async.commit_group;" ::: "memory")
#define CPA_WAIT2()  asm volatile("cp.async.wait_group 2;" ::: "memory")
#define CPA_WAIT1()  asm volatile("cp.async.wait_group 1;" ::: "memory")
#define CPA_WAIT0()  asm volatile("cp.async.wait_group 0;" ::: "memory")

// ---------------- CSR build (once per launch) ----------------
__global__ void k_zero_counts() {
    int i = blockIdx.x * blockDim.x + threadIdx.x;
    if (i < NN) g_deg[i] = 0;
    if (i < BB * GCOLS) g_g[i] = 0.0f;
}

__global__ void k_hist(const int* __restrict__ ei) {
    int e = blockIdx.x * blockDim.x + threadIdx.x;
    if (e >= E2) return;
    int dst = (e < EE) ? ei[EE + e] : e - EE;
    atomicAdd(&g_deg[dst], 1);
}

// phase 1: per-block sums of g_deg (coalesced)
__global__ void k_scan1() {
    __shared__ int sp[256];
    int tid = threadIdx.x;
    int i = blockIdx.x * 256 + tid;
    int v = (i < NN) ? g_deg[i] : 0;
    sp[tid] = v;
    __syncthreads();
    for (int o = 128; o > 0; o >>= 1) {
        if (tid < o) sp[tid] += sp[tid + o];
        __syncthreads();
    }
    if (tid == 0) g_part[blockIdx.x] = sp[0];
}

// phase 2: single block scans the SCB partials (exclusive)
__global__ void k_scan2() {
    __shared__ int sp[128];
    int tid = threadIdx.x;   // 128 threads
    int v = (tid < SCB) ? g_part[tid] : 0;
    sp[tid] = v;
    __syncthreads();
    for (int o = 1; o < 128; o <<= 1) {
        int u = (tid >= o) ? sp[tid - o] : 0;
        __syncthreads();
        sp[tid] += u;
        __syncthreads();
    }
    if (tid < SCB) g_poff[tid] = sp[tid] - v;   // exclusive
}

// phase 3: per-block local exclusive scan + base; writes g_off and seeds cursor
__global__ void k_scan3() {
    __shared__ int sp[256];
    int tid = threadIdx.x;
    int i = blockIdx.x * 256 + tid;
    int v = (i < NN) ? g_deg[i] : 0;
    sp[tid] = v;
    __syncthreads();
    for (int o = 1; o < 256; o <<= 1) {
        int u = (tid >= o) ? sp[tid - o] : 0;
        __syncthreads();
        sp[tid] += u;
        __syncthreads();
    }
    int base = g_poff[blockIdx.x];
    if (i < NN) {
        int excl = base + sp[tid] - v;
        g_off[i] = excl;
        g_cursor[i] = excl;          // scatter uses absolute positions
        if (i == NN - 1) g_off[NN] = base + sp[tid];
    }
}

__global__ void k_scatter(const int* __restrict__ ei) {
    int e = blockIdx.x * blockDim.x + threadIdx.x;
    if (e >= E2) return;
    int src, dst;
    edge_endpoints(ei, e, src, dst);
    int pos = atomicAdd(&g_cursor[dst], 1);
    g_csr_src[pos] = src;
}

// ---------------- weight transpose + fp16 (all layers, once) ----------------
__global__ void k_wconv_all(const float* __restrict__ W0,
                            const float* __restrict__ W1,
                            const float* __restrict__ W2) {
    int idx = blockIdx.x * blockDim.x + threadIdx.x;
    if (idx >= 3 * CC * CC) return;
    int L = idx >> 16;
    int r = idx & 65535;
    int k = r >> 8, n = r & 255;
    int K = (L == 0) ? FF : CC;
    if (k >= K) return;
    const float* W = (L == 0) ? W0 : ((L == 1) ? W1 : W2);
    g_wt[L * CC * CC + n * K + k] = __float2half_rn(W[(size_t)k * CC + n]);
}

// ---------------- input layer: 8 nodes per 64-thread block ----------------
__global__ void k_input(const float* __restrict__ sf,
                        const float* __restrict__ bw,
                        const float* __restrict__ bb,
                        const int* __restrict__ batch) {
    int c = threadIdx.x;            // 0..63
    int base = blockIdx.x * 8;
    float w0 = bw[0 * FF + c], w1 = bw[1 * FF + c], w2 = bw[2 * FF + c],
          w3 = bw[3 * FF + c], w4 = bw[4 * FF + c];
    float bias = bb[c];
    int curb = batch[base];
    float mx = 0.0f;
#pragma unroll
    for (int i = 0; i < 8; i++) {
        int n = base + i;
        int b = batch[n];
        if (b != curb) {
            atomicMax((int*)&g_g[curb * GCOLS + c], __float_as_int(mx));
            curb = b; mx = 0.0f;
        }
        const float* s = &sf[n * 5];
        float v = bias + s[0]*w0 + s[1]*w1 + s[2]*w2 + s[3]*w3 + s[4]*w4;
        v = fmaxf(v, 0.0f);
        g_x0[n * FF + c] = __float2half_rn(v);
        mx = fmaxf(mx, v);
    }
    atomicMax((int*)&g_g[curb * GCOLS + c], __float_as_int(mx));
}

// ---- fp16 single-product tensor-core GEMM + fused attention coefficients.
// 3-stage cp.async pipeline. g_xs[m,:] = A[m,:K] @ W[:K,:256] (fp16 out)
#define APAD 40
#define ARR_B (128 * APAD * 2)      // bytes per operand array (10240)
#define STG_B (2 * ARR_B)           // bytes per stage (20480)
#define NSTG  3
#define GEMM_SMEM (NSTG * STG_B)    // 61440

__global__ void __launch_bounds__(256, 2)
k_gemm_mma(int layer, int K,
           const float* __restrict__ att_src, const float* __restrict__ att_dst) {
    const __half* Ag = (layer == 0) ? g_x0 : g_xc;
    const __half* Whg = g_wt + layer * CC * CC;
    extern __shared__ char smem[];

    int tid = threadIdx.x;
    int warp = tid >> 5, lane = tid & 31;
    int wm = warp & 3;
    int wn = warp >> 2;
    int g = lane >> 2, t = lane & 3;
    int bm = blockIdx.y * 128;
    int bn = blockIdx.x * 128;

    uint32_t sbase = (uint32_t)__cvta_generic_to_shared(smem);

    auto fill = [&](int s, int k0) {
        uint32_t st = sbase + s * STG_B;
#pragma unroll
        for (int i = tid; i < 512; i += 256) {
            int r = i >> 2;
            int kq = (i & 3) << 3;
            int gr = bm + r;
            bool p = gr < NN;
            size_t oa = (size_t)(p ? gr : 0) * K + k0 + kq;
            uint32_t d = (r * APAD + kq) * 2;
            cpa16(st + 0 * ARR_B + d, &Ag[oa], p);
            size_t ob = (size_t)(bn + r) * K + k0 + kq;
            cpa16(st + 1 * ARR_B + d, &Whg[ob], true);
        }
        CPA_COMMIT();
    };

    float acc[2][8][4];
#pragma unroll
    for (int i = 0; i < 2; i++)
#pragma unroll
        for (int j = 0; j < 8; j++)
#pragma unroll
            for (int q = 0; q < 4; q++) acc[i][j][q] = 0.0f;

    int nch = K >> 5;
    fill(0, 0);
    if (nch > 1) fill(1, 32);
    for (int ch = 0; ch < nch; ch++) {
        if (ch + 2 < nch) { fill((ch + 2) % NSTG, (ch + 2) << 5); CPA_WAIT2(); }
        else if (ch + 1 < nch) { CPA_WAIT1(); }
        else { CPA_WAIT0(); }
        __syncthreads();

        int st = ch % NSTG;
        const __half* Ah = (const __half*)(smem + st * STG_B);
        const __half* Bh = (const __half*)(smem + st * STG_B + ARR_B);

#pragma unroll
        for (int ks = 0; ks < 32; ks += 16) {
            uint32_t ah[2][4];
#pragma unroll
            for (int mt = 0; mt < 2; mt++) {
                int r = wm * 32 + mt * 16;
                ah[mt][0] = *(uint32_t*)&Ah[(r + g) * APAD + ks + 2 * t];
                ah[mt][1] = *(uint32_t*)&Ah[(r + g + 8) * APAD + ks + 2 * t];
                ah[mt][2] = *(uint32_t*)&Ah[(r + g) * APAD + ks + 8 + 2 * t];
                ah[mt][3] = *(uint32_t*)&Ah[(r + g + 8) * APAD + ks + 8 + 2 * t];
            }
#pragma unroll
            for (int nt = 0; nt < 8; nt++) {
                int c = wn * 64 + nt * 8 + g;
                uint32_t b0 = *(uint32_t*)&Bh[c * APAD + ks + 2 * t];
                uint32_t b1 = *(uint32_t*)&Bh[c * APAD + ks + 8 + 2 * t];
#pragma unroll
                for (int mt = 0; mt < 2; mt++) {
                    mma16816(acc[mt][nt], ah[mt], b0, b1);
                }
            }
        }
        __syncthreads();
    }

    // store C (fp16) + fused attention dots (fp32 accumulators)
    int h = (bn >> 6) + wn;
#pragma unroll
    for (int mt = 0; mt < 2; mt++) {
        int r0 = bm + wm * 32 + mt * 16 + g;
        float sA = 0.f, dA = 0.f, sB = 0.f, dB = 0.f;
#pragma unroll
        for (int nt = 0; nt < 8; nt++) {
            int c = bn + wn * 64 + nt * 8 + 2 * t;
            float w0s = att_src[c], w1s = att_src[c + 1];
            float w0d = att_dst[c], w1d = att_dst[c + 1];
            sA += acc[mt][nt][0] * w0s + acc[mt][nt][1] * w1s;
            dA += acc[mt][nt][0] * w0d + acc[mt][nt][1] * w1d;
            sB += acc[mt][nt][2] * w0s + acc[mt][nt][3] * w1s;
            dB += acc[mt][nt][2] * w0d + acc[mt][nt][3] * w1d;
            if (r0 < NN) {
                __half2 hv = __floats2half2_rn(acc[mt][nt][0], acc[mt][nt][1]);
                *(__half2*)&g_xs[(size_t)r0 * CC + c] = hv;
            }
            if (r0 + 8 < NN) {
                __half2 hv = __floats2half2_rn(acc[mt][nt][2], acc[mt][nt][3]);
                *(__half2*)&g_xs[(size_t)(r0 + 8) * CC + c] = hv;
            }
        }
#pragma unroll
        for (int o = 1; o < 4; o <<= 1) {
            sA += __shfl_xor_sync(0xffffffff, sA, o);
            dA += __shfl_xor_sync(0xffffffff, dA, o);
            sB += __shfl_xor_sync(0xffffffff, sB, o);
            dB += __shfl_xor_sync(0xffffffff, dB, o);
        }
        if (t == 0) {
            if (r0 < NN)     { g_asrc[r0 * HH + h] = sA; g_adst[r0 * HH + h] = dA; }
            if (r0 + 8 < NN) { g_asrc[(r0 + 8) * HH + h] = sB; g_adst[(r0 + 8) * HH + h] = dB; }
        }
    }
}

// ---- fused GAT aggregation + relu + fp16 + batch max-pool.
// Block = 8 consecutive nodes (one warp each); 3750 blocks exactly cover NN.
__global__ void __launch_bounds__(256)
k_gat(const float* __restrict__ bias, const int* __restrict__ batch, int goff) {
    __shared__ int   ssrc[8][32];
    __shared__ float sex[8][32][4];
    __shared__ float sv[8][CC];
    int tid = threadIdx.x;
    int warp = tid >> 5, lane = tid & 31;
    int n = blockIdx.x * 8 + warp;          // always < NN (3750*8 == NN)
    int beg = g_off[n], end = g_off[n + 1];
    float4 ad = *(const float4*)&g_adst[n * HH];

    float acc[8];
#pragma unroll
    for (int q = 0; q < 8; q++) acc[q] = 0.0f;
    float4 den = make_float4(0.f, 0.f, 0.f, 0.f);
    int myc = lane * 8;
    int hme = lane >> 3;
    for (int cb = beg; cb < end; cb += 32) {
        int i = cb + lane;
        int s = 0;
        float4 ex = make_float4(0.f, 0.f, 0.f, 0.f);
        if (i < end) {
            s = g_csr_src[i];
            float4 as = *(const float4*)&g_asrc[s * HH];
            float lx = as.x + ad.x, ly = as.y + ad.y, lz = as.z + ad.z, lw = as.w + ad.w;
            lx = (lx >= 0.f) ? lx : 0.2f * lx;
            ly = (ly >= 0.f) ? ly : 0.2f * ly;
            lz = (lz >= 0.f) ? lz : 0.2f * lz;
            lw = (lw >= 0.f) ? lw : 0.2f * lw;
            ex = make_float4(__expf(lx), __expf(ly), __expf(lz), __expf(lw));
            den.x += ex.x; den.y += ex.y; den.z += ex.z; den.w += ex.w;
        }
        ssrc[warp][lane] = s;
        *(float4*)&sex[warp][lane][0] = ex;
        __syncwarp();
        int cnt = min(32, end - cb);
        // depth-4 prefetch ring; one uint4 = 8 fp16 channels per edge
        uint4 pld[4];
        float pe[4];
#define LOADJ(slot, j) do {                                            \
            int _s = ssrc[warp][j];                                    \
            pe[slot] = sex[warp][j][hme];                              \
            pld[slot] = *(const uint4*)&g_xs[(size_t)_s * CC + myc];   \
        } while (0)
        LOADJ(0, 0);
        if (cnt > 1) LOADJ(1, 1);
        if (cnt > 2) LOADJ(2, 2);
        if (cnt > 3) LOADJ(3, 3);
        for (int j = 0; j < cnt; j++) {
            uint4 u = pld[j & 3];
            float ev = pe[j & 3];
            if (j + 4 < cnt) LOADJ(j & 3, j + 4);
            __half2* hp = (__half2*)&u;
            float2 f0 = __half22float2(hp[0]);
            float2 f1 = __half22float2(hp[1]);
            float2 f2 = __half22float2(hp[2]);
            float2 f3 = __half22float2(hp[3]);
            acc[0] += ev * f0.x; acc[1] += ev * f0.y;
            acc[2] += ev * f1.x; acc[3] += ev * f1.y;
            acc[4] += ev * f2.x; acc[5] += ev * f2.y;
            acc[6] += ev * f3.x; acc[7] += ev * f3.y;
        }
#undef LOADJ
        __syncwarp();
    }

#pragma unroll
    for (int o = 16; o > 0; o >>= 1) {
        den.x += __shfl_xor_sync(0xffffffff, den.x, o);
        den.y += __shfl_xor_sync(0xffffffff, den.y, o);
        den.z += __shfl_xor_sync(0xffffffff, den.z, o);
        den.w += __shfl_xor_sync(0xffffffff, den.w, o);
    }
    float dh[4] = {den.x, den.y, den.z, den.w};
    float rinv = 1.0f / (dh[hme] + 1e-16f);

    const float4* bp = (const float4*)&bias[myc];
    float4 b1 = bp[0], b2 = bp[1];
    float v[8];
    v[0] = fmaxf(acc[0] * rinv + b1.x, 0.f);
    v[1] = fmaxf(acc[1] * rinv + b1.y, 0.f);
    v[2] = fmaxf(acc[2] * rinv + b1.z, 0.f);
    v[3] = fmaxf(acc[3] * rinv + b1.w, 0.f);
    v[4] = fmaxf(acc[4] * rinv + b2.x, 0.f);
    v[5] = fmaxf(acc[5] * rinv + b2.y, 0.f);
    v[6] = fmaxf(acc[6] * rinv + b2.z, 0.f);
    v[7] = fmaxf(acc[7] * rinv + b2.w, 0.f);
    // stash for pooling
    *(float4*)&sv[warp][myc] = make_float4(v[0], v[1], v[2], v[3]);
    *(float4*)&sv[warp][myc + 4] = make_float4(v[4], v[5], v[6], v[7]);
    // fp16 for next GEMM
    uint4 uh;
    uh.x = pk2h(v[0], v[1]); uh.y = pk2h(v[2], v[3]);
    uh.z = pk2h(v[4], v[5]); uh.w = pk2h(v[6], v[7]);
    *(uint4*)&g_xc[(size_t)n * CC + myc] = uh;

    // fused batch max-pool: thread tid owns channel tid across block's 8 nodes
    __syncthreads();
    int c = tid;
    int nbase = blockIdx.x * 8;
    int curb = batch[nbase];
    float mx = sv[0][c];
#pragma unroll
    for (int w = 1; w < 8; w++) {
        int b = batch[nbase + w];
        if (b != curb) {
            atomicMax((int*)&g_g[curb * GCOLS + goff + c], __float_as_int(mx));
            curb = b; mx = 0.0f;
        }
        mx = fmaxf(mx, sv[w][c]);
    }
    atomicMax((int*)&g_g[curb * GCOLS + goff + c], __float_as_int(mx));
}

__global__ void k_final(const float* __restrict__ agg_w,
                        const float* __restrict__ agg_b,
                        float* __restrict__ out) {
    __shared__ float sg[GCOLS];
    int b = blockIdx.x;
    int tid = threadIdx.x;
    for (int k = tid; k < GCOLS; k += 256) sg[k] = g_g[b * GCOLS + k];
    __syncthreads();
    float acc = agg_b[tid];
    for (int k = 0; k < GCOLS; k++) acc += sg[k] * agg_w[(size_t)k * BOTN + tid];
    out[b * BOTN + tid] = acc;
}

// ---------------- host ----------------
extern "C" void kernel_launch(void* const* d_in, const int* in_sizes, int n_in,
                              void* d_out, int out_size) {
    const float* sf    = (const float*)d_in[0];
    const int*   ei    = (const int*)d_in[1];
    const int*   batch = (const int*)d_in[2];
    const float* bw    = (const float*)d_in[3];
    const float* bb    = (const float*)d_in[4];
    const float* lin_w[3]   = {(const float*)d_in[5],  (const float*)d_in[9],  (const float*)d_in[13]};
    const float* att_src[3] = {(const float*)d_in[6],  (const float*)d_in[10], (const float*)d_in[14]};
    const float* att_dst[3] = {(const float*)d_in[7],  (const float*)d_in[11], (const float*)d_in[15]};
    const float* bias[3]    = {(const float*)d_in[8],  (const float*)d_in[12], (const float*)d_in[16]};
    const float* agg_w = (const float*)d_in[17];
    const float* agg_b = (const float*)d_in[18];
    float* out = (float*)d_out;

    cudaFuncSetAttribute(k_gemm_mma, cudaFuncAttributeMaxDynamicSharedMemorySize, GEMM_SMEM);

    // CSR build (graph is layer-invariant)
    k_zero_counts<<<(BB * GCOLS + 255) / 256, 256>>>();
    k_hist<<<(E2 + 255) / 256, 256>>>(ei);
    k_scan1<<<SCB, 256>>>();
    k_scan2<<<1, 128>>>();
    k_scan3<<<SCB, 256>>>();
    k_scatter<<<(E2 + 255) / 256, 256>>>(ei);

    k_wconv_all<<<(3 * CC * CC + 255) / 256, 256>>>(lin_w[0], lin_w[1], lin_w[2]);
    k_input<<<NN / 8, 64>>>(sf, bw, bb, batch);

    for (int L = 0; L < 3; L++) {
        int K = (L == 0) ? FF : CC;
        dim3 gg(2, (NN + 127) / 128);
        k_gemm_mma<<<gg, 256, GEMM_SMEM>>>(L, K, att_src[L], att_dst[L]);
        k_gat<<<NN / 8, 256>>>(bias[L], batch, FF + L * CC);
    }

    k_final<<<BB, BOTN>>>(agg_w, agg_b, out);
}